// round 3
// baseline (speedup 1.0000x reference)
#include <cuda_runtime.h>
#include <math.h>

#define BB   8
#define LL   2016
#define HH   4
#define DKK  32
#define DD   256
#define FCC  64
#define NLL  3
#define BL   (BB*LL)      // 16128
#define HD   (HH*DKK)     // 128
#define SCALE 0.0625f     // 1/sqrt(256)
#define EPSV  1e-5f

// ---------------- scratch (device globals: no allocation allowed) ----------
__device__ float g_h [BL*DD];
__device__ float g_q [BL*HD];
__device__ float g_k [BL*HD];
__device__ float g_v [BL*HD];
__device__ float g_o [BL*HD];
__device__ float g_t1[BL*DD];
__device__ float g_ff[BL*FCC];

// ---------------- tf32 helpers --------------------------------------------
__device__ __forceinline__ unsigned f2tf(float f) {
    unsigned u;
    asm("cvt.rna.tf32.f32 %0, %1;" : "=r"(u) : "f"(f));
    return u;
}

__device__ __forceinline__ void mma_tf32(float* d, const unsigned* a, const unsigned* b) {
    asm("mma.sync.aligned.m16n8k8.row.col.f32.tf32.tf32.f32 "
        "{%0,%1,%2,%3},{%4,%5,%6,%7},{%8,%9},{%0,%1,%2,%3};"
        : "+f"(d[0]), "+f"(d[1]), "+f"(d[2]), "+f"(d[3])
        : "r"(a[0]), "r"(a[1]), "r"(a[2]), "r"(a[3]),
          "r"(b[0]), "r"(b[1]));
}

// ---------------- input projection: h = x @ in_w + in_b (K=2) -------------
__global__ void k_input(const float* __restrict__ x, const float* __restrict__ w,
                        const float* __restrict__ b, float* __restrict__ h) {
    int idx = blockIdx.x * 256 + threadIdx.x;       // over BL*DD
    int d = idx & (DD - 1);
    int r = idx >> 8;
    h[idx] = fmaf(x[2*r], w[d], fmaf(x[2*r+1], w[DD + d], b[d]));
}

// ------- split-tf32 MMA GEMM (near-fp32): C = A@W + bias [, relu] ----------
// C = a_hi*b_hi + a_lo*b_hi + a_hi*b_lo  (residual ~2^-22)
// M%64==0, N%64==0, K%32==0. 256 threads, 8 warps in 4x2, warp tile 16x32.
template<bool RELU>
__global__ void k_gemm_mma(const float* __restrict__ A, const float* __restrict__ W,
                           const float* __restrict__ bias, float* __restrict__ C,
                           int M, int N, int K) {
    __shared__ unsigned AsH[64*40], AsL[64*40];
    __shared__ unsigned WsH[32*72], WsL[32*72];
    int tid = threadIdx.x;
    int w = tid >> 5, lane = tid & 31, g = lane >> 2, t = lane & 3;
    int wm = w >> 1, wn = w & 1;
    int m0 = blockIdx.y * 64, n0 = blockIdx.x * 64;
    float acc[4][4] = {};
    for (int k0 = 0; k0 < K; k0 += 32) {
        for (int i = tid; i < 2048; i += 256) {
            int r = i >> 5, c = i & 31;
            float a = A[(size_t)(m0 + r) * K + k0 + c];
            unsigned hi = f2tf(a);
            AsH[r*40 + c] = hi;
            AsL[r*40 + c] = f2tf(a - __uint_as_float(hi));
        }
        for (int i = tid; i < 2048; i += 256) {
            int kk = i >> 6, n = i & 63;
            float wv = W[(size_t)(k0 + kk) * N + n0 + n];
            unsigned hi = f2tf(wv);
            WsH[kk*72 + n] = hi;
            WsL[kk*72 + n] = f2tf(wv - __uint_as_float(hi));
        }
        __syncthreads();
        #pragma unroll
        for (int kk = 0; kk < 4; kk++) {
            unsigned aH[4], aL[4];
            int ar = wm*16;
            aH[0] = AsH[(ar + g    )*40 + kk*8 + t];
            aH[1] = AsH[(ar + g + 8)*40 + kk*8 + t];
            aH[2] = AsH[(ar + g    )*40 + kk*8 + t + 4];
            aH[3] = AsH[(ar + g + 8)*40 + kk*8 + t + 4];
            aL[0] = AsL[(ar + g    )*40 + kk*8 + t];
            aL[1] = AsL[(ar + g + 8)*40 + kk*8 + t];
            aL[2] = AsL[(ar + g    )*40 + kk*8 + t + 4];
            aL[3] = AsL[(ar + g + 8)*40 + kk*8 + t + 4];
            #pragma unroll
            for (int nt = 0; nt < 4; nt++) {
                unsigned bH[2], bL[2];
                int nc = wn*32 + nt*8 + g;
                bH[0] = WsH[(kk*8 + t    )*72 + nc];
                bH[1] = WsH[(kk*8 + t + 4)*72 + nc];
                bL[0] = WsL[(kk*8 + t    )*72 + nc];
                bL[1] = WsL[(kk*8 + t + 4)*72 + nc];
                mma_tf32(acc[nt], aL, bH);
                mma_tf32(acc[nt], aH, bL);
                mma_tf32(acc[nt], aH, bH);
            }
        }
        __syncthreads();
    }
    #pragma unroll
    for (int nt = 0; nt < 4; nt++) {
        int col = n0 + wn*32 + nt*8 + t*2;
        int r0  = m0 + wm*16 + g;
        float b0v = bias[col], b1v = bias[col + 1];
        float c00 = acc[nt][0] + b0v, c01 = acc[nt][1] + b1v;
        float c10 = acc[nt][2] + b0v, c11 = acc[nt][3] + b1v;
        if (RELU) {
            c00 = fmaxf(c00, 0.f); c01 = fmaxf(c01, 0.f);
            c10 = fmaxf(c10, 0.f); c11 = fmaxf(c11, 0.f);
        }
        C[(size_t)r0*N + col]     = c00; C[(size_t)r0*N + col + 1]     = c01;
        C[(size_t)(r0+8)*N + col] = c10; C[(size_t)(r0+8)*N + col + 1] = c11;
    }
}

// ---------------- fused attention: scores + softmax + P.V ------------------
// Block: 16 query rows of one (b,h). S stripe 16x2016 lives in smem.
// grid = (126, 32), 256 threads (8 warps).
#define S_STRIDE 2048
__global__ void k_attn(const float* __restrict__ Q, const float* __restrict__ Kv,
                       const float* __restrict__ V, float* __restrict__ P,
                       float* __restrict__ O) {
    extern __shared__ char sm[];
    float*    S   = (float*)sm;                                 // 16*2048 f
    unsigned* KVs = (unsigned*)(sm + 16*S_STRIDE*4);            // 128*40 u
    unsigned* Qs  = (unsigned*)(sm + 16*S_STRIDE*4 + 128*40*4); // 16*40 u
    float*    part= (float*)(sm + 16*S_STRIDE*4 + 128*40*4 + 16*40*4); // 8*16*32

    int tid = threadIdx.x;
    int w = tid >> 5, lane = tid & 31, g = lane >> 2, t = lane & 3;
    int l0 = blockIdx.x * 16;
    int bh = blockIdx.y, b = bh >> 2, hh = bh & 3;
    const float* qb = Q  + (size_t)b * LL * HD + hh * DKK;
    const float* kb = Kv + (size_t)b * LL * HD + hh * DKK;
    const float* vb = V  + (size_t)b * LL * HD + hh * DKK;

    // load Q tile 16x32 (tf32)
    for (int i = tid; i < 512; i += 256) {
        int r = i >> 5, c = i & 31;
        Qs[r*40 + c] = f2tf(qb[(size_t)(l0 + r) * HD + c]);
    }
    __syncthreads();

    // ---- phase 1: S = scale * Q @ K^T, streamed over 128-wide s-tiles ----
    for (int s0 = 0; s0 < LL; s0 += 128) {
        for (int i = tid; i < 4096; i += 256) {
            int r = i >> 5, c = i & 31;
            int s = s0 + r;
            float v = (s < LL) ? kb[(size_t)s * HD + c] : 0.f;
            KVs[r*40 + c] = f2tf(v);
        }
        __syncthreads();
        float acc[2][4] = {};
        #pragma unroll
        for (int kk = 0; kk < 4; kk++) {
            unsigned a[4];
            a[0] = Qs[g*40       + kk*8 + t];
            a[1] = Qs[(g+8)*40   + kk*8 + t];
            a[2] = Qs[g*40       + kk*8 + t + 4];
            a[3] = Qs[(g+8)*40   + kk*8 + t + 4];
            #pragma unroll
            for (int nt = 0; nt < 2; nt++) {
                unsigned b2[2];
                int nr = w*16 + nt*8 + g;
                b2[0] = KVs[nr*40 + kk*8 + t];
                b2[1] = KVs[nr*40 + kk*8 + t + 4];
                mma_tf32(acc[nt], a, b2);
            }
        }
        #pragma unroll
        for (int nt = 0; nt < 2; nt++) {
            int cb = s0 + w*16 + nt*8 + t*2;
            S[g*S_STRIDE     + cb]     = acc[nt][0] * SCALE;
            S[g*S_STRIDE     + cb + 1] = acc[nt][1] * SCALE;
            S[(g+8)*S_STRIDE + cb]     = acc[nt][2] * SCALE;
            S[(g+8)*S_STRIDE + cb + 1] = acc[nt][3] * SCALE;
        }
        __syncthreads();
    }

    // ---- phase 2: row softmax in smem, write P to gmem -------------------
    float* Pbh = P + (size_t)bh * LL * LL;
    #pragma unroll
    for (int rr = 0; rr < 2; rr++) {
        int r = w*2 + rr;
        float* Sr = S + r*S_STRIDE;
        float m = -1e30f;
        for (int idx = lane; idx < LL; idx += 32) m = fmaxf(m, Sr[idx]);
        #pragma unroll
        for (int o = 16; o > 0; o >>= 1) m = fmaxf(m, __shfl_xor_sync(0xffffffffu, m, o));
        float sum = 0.f;
        for (int idx = lane; idx < LL; idx += 32) {
            float e = __expf(Sr[idx] - m);
            Sr[idx] = e;
            sum += e;
        }
        #pragma unroll
        for (int o = 16; o > 0; o >>= 1) sum += __shfl_xor_sync(0xffffffffu, sum, o);
        float inv = 1.f / sum;
        float* Pg = Pbh + (size_t)(l0 + r) * LL;
        for (int idx = lane; idx < LL; idx += 32) {
            float v = Sr[idx] * inv;
            Sr[idx] = v;
            Pg[idx] = v;
        }
    }
    __syncthreads();

    // ---- phase 3: O = P @ V, k split across warps ------------------------
    float acc2[4][4] = {};
    for (int s0 = 0; s0 < LL; s0 += 128) {
        for (int i = tid; i < 4096; i += 256) {
            int r = i >> 5, c = i & 31;
            int s = s0 + r;
            float v = (s < LL) ? vb[(size_t)s * HD + c] : 0.f;
            KVs[r*40 + c] = f2tf(v);
        }
        __syncthreads();
        #pragma unroll
        for (int k2 = 0; k2 < 2; k2++) {
            int klocal = w*2 + k2;
            int scol = s0 + klocal*8;
            unsigned a[4];
            a[0] = f2tf(S[g*S_STRIDE     + scol + t]);
            a[1] = f2tf(S[(g+8)*S_STRIDE + scol + t]);
            a[2] = f2tf(S[g*S_STRIDE     + scol + t + 4]);
            a[3] = f2tf(S[(g+8)*S_STRIDE + scol + t + 4]);
            #pragma unroll
            for (int nt = 0; nt < 4; nt++) {
                unsigned b2[2];
                b2[0] = KVs[(klocal*8 + t    )*40 + nt*8 + g];
                b2[1] = KVs[(klocal*8 + t + 4)*40 + nt*8 + g];
                mma_tf32(acc2[nt], a, b2);
            }
        }
        __syncthreads();
    }
    // reduce 8 warp partials
    #pragma unroll
    for (int nt = 0; nt < 4; nt++) {
        part[w*512 + g*32     + nt*8 + t*2]     = acc2[nt][0];
        part[w*512 + g*32     + nt*8 + t*2 + 1] = acc2[nt][1];
        part[w*512 + (g+8)*32 + nt*8 + t*2]     = acc2[nt][2];
        part[w*512 + (g+8)*32 + nt*8 + t*2 + 1] = acc2[nt][3];
    }
    __syncthreads();
    float* ob = O + (size_t)b * LL * HD + hh * DKK;
    for (int i = tid; i < 512; i += 256) {
        int r = i >> 5, dv = i & 31;
        float s = 0.f;
        #pragma unroll
        for (int ww = 0; ww < 8; ww++) s += part[ww*512 + i];
        ob[(size_t)(l0 + r) * HD + dv] = s;
    }
}

// ---------------- h = LayerNorm(h + add) * g + b (row of 256) --------------
__global__ void k_ln(float* __restrict__ h, const float* __restrict__ add,
                     const float* __restrict__ g, const float* __restrict__ bta) {
    int row  = blockIdx.x * 8 + (threadIdx.x >> 5);
    int lane = threadIdx.x & 31;
    float* hp = h + (size_t)row * DD;
    const float* ap = add + (size_t)row * DD;
    float v[8]; float s = 0.f;
    #pragma unroll
    for (int i = 0; i < 8; i++) {
        v[i] = hp[lane + 32*i] + ap[lane + 32*i];
        s += v[i];
    }
    #pragma unroll
    for (int o = 16; o > 0; o >>= 1) s += __shfl_xor_sync(0xffffffffu, s, o);
    float mean = s * (1.f / DD);
    float var = 0.f;
    #pragma unroll
    for (int i = 0; i < 8; i++) { float d = v[i] - mean; var = fmaf(d, d, var); }
    #pragma unroll
    for (int o = 16; o > 0; o >>= 1) var += __shfl_xor_sync(0xffffffffu, var, o);
    var *= (1.f / DD);
    float r = rsqrtf(var + EPSV);
    #pragma unroll
    for (int i = 0; i < 8; i++) {
        int d = lane + 32*i;
        hp[d] = (v[i] - mean) * r * g[d] + bta[d];
    }
}

// ---------------- final head: out = A(relu'd) @ o2w(256x2) + o2b -----------
__global__ void k_out2(const float* __restrict__ A, const float* __restrict__ w,
                       const float* __restrict__ b, float* __restrict__ out) {
    int row  = blockIdx.x * 8 + (threadIdx.x >> 5);
    int lane = threadIdx.x & 31;
    const float* ap = A + (size_t)row * DD;
    float s0 = 0.f, s1 = 0.f;
    #pragma unroll
    for (int i = 0; i < 8; i++) {
        int d = lane + 32*i;
        float a = ap[d];
        s0 = fmaf(a, w[d*2],     s0);
        s1 = fmaf(a, w[d*2 + 1], s1);
    }
    #pragma unroll
    for (int o = 16; o > 0; o >>= 1) {
        s0 += __shfl_xor_sync(0xffffffffu, s0, o);
        s1 += __shfl_xor_sync(0xffffffffu, s1, o);
    }
    if (lane == 0) {
        out[(size_t)row*2]     = s0 + b[0];
        out[(size_t)row*2 + 1] = s1 + b[1];
    }
}

// ---------------------------------------------------------------------------
extern "C" void kernel_launch(void* const* d_in, const int* in_sizes, int n_in,
                              void* d_out, int out_size) {
    const float* x    = (const float*)d_in[0];
    const float* in_w = (const float*)d_in[1];
    const float* in_b = (const float*)d_in[2];
    const float* qw   = (const float*)d_in[3];
    const float* qb   = (const float*)d_in[4];
    const float* kw   = (const float*)d_in[5];
    const float* kb   = (const float*)d_in[6];
    const float* vw   = (const float*)d_in[7];
    const float* vb   = (const float*)d_in[8];
    const float* ow   = (const float*)d_in[9];
    const float* ob   = (const float*)d_in[10];
    const float* f1w  = (const float*)d_in[11];
    const float* f1b  = (const float*)d_in[12];
    const float* f2w  = (const float*)d_in[13];
    const float* f2b  = (const float*)d_in[14];
    const float* n1g  = (const float*)d_in[15];
    const float* n1b  = (const float*)d_in[16];
    const float* n2g  = (const float*)d_in[17];
    const float* n2b  = (const float*)d_in[18];
    const float* o1w  = (const float*)d_in[19];
    const float* o1b  = (const float*)d_in[20];
    const float* o2w  = (const float*)d_in[21];
    const float* o2b  = (const float*)d_in[22];

    float* out  = (float*)d_out;
    float* attn = out + (size_t)BB * LL * 2;   // attns region: (NL,B,H,L,L)

    float *h, *q, *k, *v, *o, *t1, *ff;
    cudaGetSymbolAddress((void**)&h,  g_h);
    cudaGetSymbolAddress((void**)&q,  g_q);
    cudaGetSymbolAddress((void**)&k,  g_k);
    cudaGetSymbolAddress((void**)&v,  g_v);
    cudaGetSymbolAddress((void**)&o,  g_o);
    cudaGetSymbolAddress((void**)&t1, g_t1);
    cudaGetSymbolAddress((void**)&ff, g_ff);

    const int SMEM_ATTN = 16*S_STRIDE*4 + 128*40*4 + 16*40*4 + 8*16*32*4; // 170496
    cudaFuncSetAttribute(k_attn, cudaFuncAttributeMaxDynamicSharedMemorySize, SMEM_ATTN);

    // input projection
    k_input<<<(BL*DD)/256, 256>>>(x, in_w, in_b, h);

    for (int i = 0; i < NLL; i++) {
        const float* qwi = qw + (size_t)i * DD * HD;
        const float* qbi = qb + (size_t)i * HD;
        const float* kwi = kw + (size_t)i * DD * HD;
        const float* kbi = kb + (size_t)i * HD;
        const float* vwi = vw + (size_t)i * DD * HD;
        const float* vbi = vb + (size_t)i * HD;
        const float* owi = ow + (size_t)i * HD * DD;
        const float* obi = ob + (size_t)i * DD;
        const float* f1wi = f1w + (size_t)i * DD * FCC;
        const float* f1bi = f1b + (size_t)i * FCC;
        const float* f2wi = f2w + (size_t)i * FCC * DD;
        const float* f2bi = f2b + (size_t)i * DD;

        // Q,K,V projections (split-tf32 mma, near-fp32 accuracy)
        k_gemm_mma<false><<<dim3(HD/64, BL/64), 256>>>(h, qwi, qbi, q, BL, HD, DD);
        k_gemm_mma<false><<<dim3(HD/64, BL/64), 256>>>(h, kwi, kbi, k, BL, HD, DD);
        k_gemm_mma<false><<<dim3(HD/64, BL/64), 256>>>(h, vwi, vbi, v, BL, HD, DD);

        // fused scores + softmax + P.V
        float* Si = attn + (size_t)i * BB * HH * LL * LL;
        k_attn<<<dim3(LL/16, BB*HH), 256, SMEM_ATTN>>>(q, k, v, Si, o);

        // output projection + residual LN
        k_gemm_mma<false><<<dim3(DD/64, BL/64), 256>>>(o, owi, obi, t1, BL, DD, HD);
        k_ln<<<BL/8, 256>>>(h, t1, n1g + (size_t)i*DD, n1b + (size_t)i*DD);

        // FFN + residual LN
        k_gemm_mma<true ><<<dim3(FCC/64, BL/64), 256>>>(h, f1wi, f1bi, ff, BL, FCC, DD);
        k_gemm_mma<false><<<dim3(DD/64, BL/64), 256>>>(ff, f2wi, f2bi, t1, BL, DD, FCC);
        k_ln<<<BL/8, 256>>>(h, t1, n2g + (size_t)i*DD, n2b + (size_t)i*DD);
    }

    // final MLP head
    k_gemm_mma<true><<<dim3(DD/64, BL/64), 256>>>(h, o1w, o1b, t1, BL, DD, DD);
    k_out2<<<BL/8, 256>>>(t1, o2w, o2b, out);
}

// round 4
// speedup vs baseline: 1.5207x; 1.5207x over previous
#include <cuda_runtime.h>
#include <math.h>

#define BB   8
#define LL   2016
#define HH   4
#define DKK  32
#define DD   256
#define FCC  64
#define NLL  3
#define BL   (BB*LL)      // 16128
#define HD   (HH*DKK)     // 128
#define BHH  (BB*HH)      // 32
#define SCALE 0.0625f     // 1/sqrt(256)
#define EPSV  1e-5f

// ---------------- scratch (device globals: no allocation allowed) ----------
__device__ float g_h [BL*DD];
__device__ float g_q [BL*HD];
__device__ float g_k [BL*HD];
__device__ float g_v [BL*HD];
__device__ float g_o [BL*HD];
__device__ float g_t1[BL*DD];
__device__ float g_ff[BL*FCC];
__device__ float g_stat[BHH*LL*2];   // per-row (max, 1/sum)

// ---------------- tf32 helpers --------------------------------------------
__device__ __forceinline__ unsigned f2tf(float f) {
    unsigned u;
    asm("cvt.rna.tf32.f32 %0, %1;" : "=r"(u) : "f"(f));
    return u;
}

__device__ __forceinline__ void mma_tf32(float* d, const unsigned* a, const unsigned* b) {
    asm("mma.sync.aligned.m16n8k8.row.col.f32.tf32.tf32.f32 "
        "{%0,%1,%2,%3},{%4,%5,%6,%7},{%8,%9},{%0,%1,%2,%3};"
        : "+f"(d[0]), "+f"(d[1]), "+f"(d[2]), "+f"(d[3])
        : "r"(a[0]), "r"(a[1]), "r"(a[2]), "r"(a[3]),
          "r"(b[0]), "r"(b[1]));
}

// ---------------- input projection: h = x @ in_w + in_b (K=2) -------------
__global__ void k_input(const float* __restrict__ x, const float* __restrict__ w,
                        const float* __restrict__ b, float* __restrict__ h) {
    int idx = blockIdx.x * 256 + threadIdx.x;
    int d = idx & (DD - 1);
    int r = idx >> 8;
    h[idx] = fmaf(x[2*r], w[d], fmaf(x[2*r+1], w[DD + d], b[d]));
}

// ------- split-tf32 MMA GEMM (near-fp32): C = A@W + bias [, relu] ----------
template<bool RELU>
__global__ void k_gemm_mma(const float* __restrict__ A, const float* __restrict__ W,
                           const float* __restrict__ bias, float* __restrict__ C,
                           int M, int N, int K) {
    __shared__ unsigned AsH[64*40], AsL[64*40];
    __shared__ unsigned WsH[32*72], WsL[32*72];
    int tid = threadIdx.x;
    int w = tid >> 5, lane = tid & 31, g = lane >> 2, t = lane & 3;
    int wm = w >> 1, wn = w & 1;
    int m0 = blockIdx.y * 64, n0 = blockIdx.x * 64;
    float acc[4][4] = {};
    for (int k0 = 0; k0 < K; k0 += 32) {
        for (int i = tid; i < 2048; i += 256) {
            int r = i >> 5, c = i & 31;
            float a = A[(size_t)(m0 + r) * K + k0 + c];
            unsigned hi = f2tf(a);
            AsH[r*40 + c] = hi;
            AsL[r*40 + c] = f2tf(a - __uint_as_float(hi));
        }
        for (int i = tid; i < 2048; i += 256) {
            int kk = i >> 6, n = i & 63;
            float wv = W[(size_t)(k0 + kk) * N + n0 + n];
            unsigned hi = f2tf(wv);
            WsH[kk*72 + n] = hi;
            WsL[kk*72 + n] = f2tf(wv - __uint_as_float(hi));
        }
        __syncthreads();
        #pragma unroll
        for (int kk = 0; kk < 4; kk++) {
            unsigned aH[4], aL[4];
            int ar = wm*16;
            aH[0] = AsH[(ar + g    )*40 + kk*8 + t];
            aH[1] = AsH[(ar + g + 8)*40 + kk*8 + t];
            aH[2] = AsH[(ar + g    )*40 + kk*8 + t + 4];
            aH[3] = AsH[(ar + g + 8)*40 + kk*8 + t + 4];
            aL[0] = AsL[(ar + g    )*40 + kk*8 + t];
            aL[1] = AsL[(ar + g + 8)*40 + kk*8 + t];
            aL[2] = AsL[(ar + g    )*40 + kk*8 + t + 4];
            aL[3] = AsL[(ar + g + 8)*40 + kk*8 + t + 4];
            #pragma unroll
            for (int nt = 0; nt < 4; nt++) {
                unsigned bH[2], bL[2];
                int nc = wn*32 + nt*8 + g;
                bH[0] = WsH[(kk*8 + t    )*72 + nc];
                bH[1] = WsH[(kk*8 + t + 4)*72 + nc];
                bL[0] = WsL[(kk*8 + t    )*72 + nc];
                bL[1] = WsL[(kk*8 + t + 4)*72 + nc];
                mma_tf32(acc[nt], aL, bH);
                mma_tf32(acc[nt], aH, bL);
                mma_tf32(acc[nt], aH, bH);
            }
        }
        __syncthreads();
    }
    #pragma unroll
    for (int nt = 0; nt < 4; nt++) {
        int col = n0 + wn*32 + nt*8 + t*2;
        int r0  = m0 + wm*16 + g;
        float b0v = bias[col], b1v = bias[col + 1];
        float c00 = acc[nt][0] + b0v, c01 = acc[nt][1] + b1v;
        float c10 = acc[nt][2] + b0v, c11 = acc[nt][3] + b1v;
        if (RELU) {
            c00 = fmaxf(c00, 0.f); c01 = fmaxf(c01, 0.f);
            c10 = fmaxf(c10, 0.f); c11 = fmaxf(c11, 0.f);
        }
        C[(size_t)r0*N + col]     = c00; C[(size_t)r0*N + col + 1]     = c01;
        C[(size_t)(r0+8)*N + col] = c10; C[(size_t)(r0+8)*N + col + 1] = c11;
    }
}

// ---------------- scores: S[bh,l,s] = scale * <Q[l], K[s]>, raw, tf32 ------
// block 256 thr (8 warps 2x4), tile 128x128, grid (16 col, 16 row, 32 bh)
__global__ void __launch_bounds__(256) k_scores(
        const float* __restrict__ Q, const float* __restrict__ Kv,
        float* __restrict__ S) {
    __shared__ unsigned Qs[128*36];
    __shared__ unsigned Ks[128*36];
    int tid = threadIdx.x;
    int w = tid >> 5, lane = tid & 31, g = lane >> 2, t = lane & 3;
    int wm = w >> 2, wn = w & 3;            // 2 x 4 warps, warp tile 64x32
    int l0 = blockIdx.y * 128, s0 = blockIdx.x * 128;
    int bh = blockIdx.z, b = bh >> 2, hh = bh & 3;
    const float* qb = Q  + (size_t)b * LL * HD + hh * DKK;
    const float* kb = Kv + (size_t)b * LL * HD + hh * DKK;

    for (int i = tid; i < 4096; i += 256) {
        int r = i >> 5, c = i & 31;
        Qs[r*36 + c] = f2tf((l0 + r < LL) ? qb[(size_t)(l0 + r) * HD + c] : 0.f);
        Ks[r*36 + c] = f2tf((s0 + r < LL) ? kb[(size_t)(s0 + r) * HD + c] : 0.f);
    }
    __syncthreads();

    float acc[4][4][4] = {};   // [mi][ni][4]
    #pragma unroll
    for (int kk = 0; kk < 4; kk++) {
        unsigned bfr[4][2];
        #pragma unroll
        for (int ni = 0; ni < 4; ni++) {
            int nr = wn*32 + ni*8 + g;
            bfr[ni][0] = Ks[nr*36 + kk*8 + t];
            bfr[ni][1] = Ks[nr*36 + kk*8 + t + 4];
        }
        #pragma unroll
        for (int mi = 0; mi < 4; mi++) {
            unsigned a[4];
            int ar = wm*64 + mi*16;
            a[0] = Qs[(ar + g    )*36 + kk*8 + t];
            a[1] = Qs[(ar + g + 8)*36 + kk*8 + t];
            a[2] = Qs[(ar + g    )*36 + kk*8 + t + 4];
            a[3] = Qs[(ar + g + 8)*36 + kk*8 + t + 4];
            #pragma unroll
            for (int ni = 0; ni < 4; ni++)
                mma_tf32(acc[mi][ni], a, bfr[ni]);
        }
    }

    float* Sb = S + (size_t)bh * LL * LL;
    #pragma unroll
    for (int mi = 0; mi < 4; mi++) {
        int r0 = l0 + wm*64 + mi*16 + g;
        #pragma unroll
        for (int ni = 0; ni < 4; ni++) {
            int c0 = s0 + wn*32 + ni*8 + t*2;
            if (c0 + 1 < LL) {
                if (r0 < LL) {
                    Sb[(size_t)r0*LL + c0]     = acc[mi][ni][0] * SCALE;
                    Sb[(size_t)r0*LL + c0 + 1] = acc[mi][ni][1] * SCALE;
                }
                if (r0 + 8 < LL) {
                    Sb[(size_t)(r0+8)*LL + c0]     = acc[mi][ni][2] * SCALE;
                    Sb[(size_t)(r0+8)*LL + c0 + 1] = acc[mi][ni][3] * SCALE;
                }
            }
        }
    }
}

// ---------------- row stats: per row of S compute (max, 1/sumexp) ----------
__global__ void k_rowstat(const float* __restrict__ S, float* __restrict__ st) {
    __shared__ float rm[256], rs[256];
    const float* p = S + (size_t)blockIdx.x * LL;
    int tid = threadIdx.x;
    float v[8]; float m = -1e30f;
    #pragma unroll
    for (int i = 0; i < 8; i++) {
        int idx = tid + i*256;
        v[i] = (idx < LL) ? p[idx] : -1e30f;
        m = fmaxf(m, v[i]);
    }
    float s = 0.f;
    #pragma unroll
    for (int i = 0; i < 8; i++) s += __expf(v[i] - m);
    rm[tid] = m; rs[tid] = s; __syncthreads();
    for (int off = 128; off > 0; off >>= 1) {
        if (tid < off) {
            float m2 = rm[tid + off], s2 = rs[tid + off];
            float M = fmaxf(rm[tid], m2);
            rs[tid] = rs[tid] * __expf(rm[tid] - M) + s2 * __expf(m2 - M);
            rm[tid] = M;
        }
        __syncthreads();
    }
    if (tid == 0) {
        st[(size_t)blockIdx.x*2]     = rm[0];
        st[(size_t)blockIdx.x*2 + 1] = 1.f / rs[0];
    }
}

// ---------------- pv: normalize S in place -> P, and O = P @ V -------------
// block 256 thr (8 warps, 16 rows each), row tile 128, grid (16, 32 bh)
__global__ void __launch_bounds__(256) k_pv(
        float* __restrict__ S, const float* __restrict__ st,
        const float* __restrict__ V, float* __restrict__ O) {
    __shared__ unsigned Ps[128*68];
    __shared__ unsigned Vs[64*36];
    __shared__ float ms[128], inv[128];
    int tid = threadIdx.x;
    int w = tid >> 5, lane = tid & 31, g = lane >> 2, t = lane & 3;
    int l0 = blockIdx.x * 128;
    int bh = blockIdx.y, b = bh >> 2, hh = bh & 3;
    float* Sb = S + (size_t)bh * LL * LL;
    const float* stb = st + (size_t)bh * LL * 2;
    const float* vb = V + (size_t)b * LL * HD + hh * DKK;

    if (tid < 128) {
        int row = l0 + tid;
        ms[tid]  = (row < LL) ? stb[(size_t)row*2]     : 0.f;
        inv[tid] = (row < LL) ? stb[(size_t)row*2 + 1] : 0.f;
    }
    __syncthreads();

    float acc[4][4] = {};   // [ni][4], warp rows w*16..w*16+15, cols 32
    for (int s0 = 0; s0 < LL; s0 += 64) {
        // load + normalize P chunk 128x64, write P back to gmem
        for (int i = tid; i < 8192; i += 256) {
            int r = i >> 6, c = i & 63;
            int row = l0 + r, col = s0 + c;
            float pv = 0.f;
            if (row < LL && col < LL) {
                float sv = Sb[(size_t)row * LL + col];
                pv = __expf(sv - ms[r]) * inv[r];
                Sb[(size_t)row * LL + col] = pv;
            }
            Ps[r*68 + c] = f2tf(pv);
        }
        // load V chunk 64x32
        for (int i = tid; i < 2048; i += 256) {
            int r = i >> 5, c = i & 31;
            int srow = s0 + r;
            Vs[r*36 + c] = f2tf((srow < LL) ? vb[(size_t)srow * HD + c] : 0.f);
        }
        __syncthreads();
        #pragma unroll
        for (int kk = 0; kk < 8; kk++) {
            unsigned a[4];
            int ar = w*16;
            a[0] = Ps[(ar + g    )*68 + kk*8 + t];
            a[1] = Ps[(ar + g + 8)*68 + kk*8 + t];
            a[2] = Ps[(ar + g    )*68 + kk*8 + t + 4];
            a[3] = Ps[(ar + g + 8)*68 + kk*8 + t + 4];
            #pragma unroll
            for (int ni = 0; ni < 4; ni++) {
                unsigned b2[2];
                b2[0] = Vs[(kk*8 + t    )*36 + ni*8 + g];
                b2[1] = Vs[(kk*8 + t + 4)*36 + ni*8 + g];
                mma_tf32(acc[ni], a, b2);
            }
        }
        __syncthreads();
    }
    float* ob = O + (size_t)b * LL * HD + hh * DKK;
    #pragma unroll
    for (int ni = 0; ni < 4; ni++) {
        int r0 = l0 + w*16 + g;
        int c0 = ni*8 + t*2;
        if (r0 < LL) {
            ob[(size_t)r0*HD + c0]     = acc[ni][0];
            ob[(size_t)r0*HD + c0 + 1] = acc[ni][1];
        }
        if (r0 + 8 < LL) {
            ob[(size_t)(r0+8)*HD + c0]     = acc[ni][2];
            ob[(size_t)(r0+8)*HD + c0 + 1] = acc[ni][3];
        }
    }
}

// ---------------- h = LayerNorm(h + add) * g + b (row of 256) --------------
__global__ void k_ln(float* __restrict__ h, const float* __restrict__ add,
                     const float* __restrict__ g, const float* __restrict__ bta) {
    int row  = blockIdx.x * 8 + (threadIdx.x >> 5);
    int lane = threadIdx.x & 31;
    float* hp = h + (size_t)row * DD;
    const float* ap = add + (size_t)row * DD;
    float v[8]; float s = 0.f;
    #pragma unroll
    for (int i = 0; i < 8; i++) {
        v[i] = hp[lane + 32*i] + ap[lane + 32*i];
        s += v[i];
    }
    #pragma unroll
    for (int o = 16; o > 0; o >>= 1) s += __shfl_xor_sync(0xffffffffu, s, o);
    float mean = s * (1.f / DD);
    float var = 0.f;
    #pragma unroll
    for (int i = 0; i < 8; i++) { float d = v[i] - mean; var = fmaf(d, d, var); }
    #pragma unroll
    for (int o = 16; o > 0; o >>= 1) var += __shfl_xor_sync(0xffffffffu, var, o);
    var *= (1.f / DD);
    float r = rsqrtf(var + EPSV);
    #pragma unroll
    for (int i = 0; i < 8; i++) {
        int d = lane + 32*i;
        hp[d] = (v[i] - mean) * r * g[d] + bta[d];
    }
}

// ---------------- final head: out = A(relu'd) @ o2w(256x2) + o2b -----------
__global__ void k_out2(const float* __restrict__ A, const float* __restrict__ w,
                       const float* __restrict__ b, float* __restrict__ out) {
    int row  = blockIdx.x * 8 + (threadIdx.x >> 5);
    int lane = threadIdx.x & 31;
    const float* ap = A + (size_t)row * DD;
    float s0 = 0.f, s1 = 0.f;
    #pragma unroll
    for (int i = 0; i < 8; i++) {
        int d = lane + 32*i;
        float a = ap[d];
        s0 = fmaf(a, w[d*2],     s0);
        s1 = fmaf(a, w[d*2 + 1], s1);
    }
    #pragma unroll
    for (int o = 16; o > 0; o >>= 1) {
        s0 += __shfl_xor_sync(0xffffffffu, s0, o);
        s1 += __shfl_xor_sync(0xffffffffu, s1, o);
    }
    if (lane == 0) {
        out[(size_t)row*2]     = s0 + b[0];
        out[(size_t)row*2 + 1] = s1 + b[1];
    }
}

// ---------------------------------------------------------------------------
extern "C" void kernel_launch(void* const* d_in, const int* in_sizes, int n_in,
                              void* d_out, int out_size) {
    const float* x    = (const float*)d_in[0];
    const float* in_w = (const float*)d_in[1];
    const float* in_b = (const float*)d_in[2];
    const float* qw   = (const float*)d_in[3];
    const float* qb   = (const float*)d_in[4];
    const float* kw   = (const float*)d_in[5];
    const float* kb   = (const float*)d_in[6];
    const float* vw   = (const float*)d_in[7];
    const float* vb   = (const float*)d_in[8];
    const float* ow   = (const float*)d_in[9];
    const float* ob   = (const float*)d_in[10];
    const float* f1w  = (const float*)d_in[11];
    const float* f1b  = (const float*)d_in[12];
    const float* f2w  = (const float*)d_in[13];
    const float* f2b  = (const float*)d_in[14];
    const float* n1g  = (const float*)d_in[15];
    const float* n1b  = (const float*)d_in[16];
    const float* n2g  = (const float*)d_in[17];
    const float* n2b  = (const float*)d_in[18];
    const float* o1w  = (const float*)d_in[19];
    const float* o1b  = (const float*)d_in[20];
    const float* o2w  = (const float*)d_in[21];
    const float* o2b  = (const float*)d_in[22];

    float* out  = (float*)d_out;
    float* attn = out + (size_t)BB * LL * 2;   // attns region: (NL,B,H,L,L)

    float *h, *q, *k, *v, *o, *t1, *ff, *st;
    cudaGetSymbolAddress((void**)&h,  g_h);
    cudaGetSymbolAddress((void**)&q,  g_q);
    cudaGetSymbolAddress((void**)&k,  g_k);
    cudaGetSymbolAddress((void**)&v,  g_v);
    cudaGetSymbolAddress((void**)&o,  g_o);
    cudaGetSymbolAddress((void**)&t1, g_t1);
    cudaGetSymbolAddress((void**)&ff, g_ff);
    cudaGetSymbolAddress((void**)&st, g_stat);

    // input projection
    k_input<<<(BL*DD)/256, 256>>>(x, in_w, in_b, h);

    const int LT = (LL + 127) / 128;   // 16

    for (int i = 0; i < NLL; i++) {
        const float* qwi = qw + (size_t)i * DD * HD;
        const float* qbi = qb + (size_t)i * HD;
        const float* kwi = kw + (size_t)i * DD * HD;
        const float* kbi = kb + (size_t)i * HD;
        const float* vwi = vw + (size_t)i * DD * HD;
        const float* vbi = vb + (size_t)i * HD;
        const float* owi = ow + (size_t)i * HD * DD;
        const float* obi = ob + (size_t)i * DD;
        const float* f1wi = f1w + (size_t)i * DD * FCC;
        const float* f1bi = f1b + (size_t)i * FCC;
        const float* f2wi = f2w + (size_t)i * FCC * DD;
        const float* f2bi = f2b + (size_t)i * DD;

        // Q,K,V projections (split-tf32 mma, near-fp32 accuracy)
        k_gemm_mma<false><<<dim3(HD/64, BL/64), 256>>>(h, qwi, qbi, q, BL, HD, DD);
        k_gemm_mma<false><<<dim3(HD/64, BL/64), 256>>>(h, kwi, kbi, k, BL, HD, DD);
        k_gemm_mma<false><<<dim3(HD/64, BL/64), 256>>>(h, vwi, vbi, v, BL, HD, DD);

        float* Si = attn + (size_t)i * BHH * LL * LL;
        k_scores<<<dim3(LT, LT, BHH), 256>>>(q, k, Si);
        k_rowstat<<<BHH*LL, 256>>>(Si, st);
        k_pv<<<dim3(LT, BHH), 256>>>(Si, st, v, o);

        // output projection + residual LN
        k_gemm_mma<false><<<dim3(DD/64, BL/64), 256>>>(o, owi, obi, t1, BL, DD, HD);
        k_ln<<<BL/8, 256>>>(h, t1, n1g + (size_t)i*DD, n1b + (size_t)i*DD);

        // FFN + residual LN
        k_gemm_mma<true ><<<dim3(FCC/64, BL/64), 256>>>(h, f1wi, f1bi, ff, BL, FCC, DD);
        k_gemm_mma<false><<<dim3(DD/64, BL/64), 256>>>(ff, f2wi, f2bi, t1, BL, DD, FCC);
        k_ln<<<BL/8, 256>>>(h, t1, n2g + (size_t)i*DD, n2b + (size_t)i*DD);
    }

    // final MLP head
    k_gemm_mma<true><<<dim3(DD/64, BL/64), 256>>>(h, o1w, o1b, t1, BL, DD, DD);
    k_out2<<<BL/8, 256>>>(t1, o2w, o2b, out);
}

// round 5
// speedup vs baseline: 2.6381x; 1.7348x over previous
#include <cuda_runtime.h>
#include <math.h>

#define BB   8
#define LL   2016
#define HH   4
#define DKK  32
#define DD   256
#define FCC  64
#define NLL  3
#define BL   (BB*LL)      // 16128
#define HD   (HH*DKK)     // 128
#define BHH  (BB*HH)      // 32
#define SCALE 0.0625f     // 1/sqrt(256)
#define EPSV  1e-5f

// ---------------- scratch (device globals: no allocation allowed) ----------
__device__ float g_h [BL*DD];
__device__ float g_q [BL*HD];
__device__ float g_k [BL*HD];
__device__ float g_v [BL*HD];
__device__ float g_o [BL*HD];
__device__ float g_t1[BL*DD];
__device__ float g_ff[BL*FCC];
__device__ float g_stat[BHH*LL*2];   // per-row (max, 1/sum)

// ---------------- tf32 helpers --------------------------------------------
__device__ __forceinline__ unsigned f2tf(float f) {
    unsigned u;
    asm("cvt.rna.tf32.f32 %0, %1;" : "=r"(u) : "f"(f));
    return u;
}

__device__ __forceinline__ void mma_tf32(float* d, const unsigned* a, const unsigned* b) {
    asm("mma.sync.aligned.m16n8k8.row.col.f32.tf32.tf32.f32 "
        "{%0,%1,%2,%3},{%4,%5,%6,%7},{%8,%9},{%0,%1,%2,%3};"
        : "+f"(d[0]), "+f"(d[1]), "+f"(d[2]), "+f"(d[3])
        : "r"(a[0]), "r"(a[1]), "r"(a[2]), "r"(a[3]),
          "r"(b[0]), "r"(b[1]));
}

// ---------------- input projection: h = x @ in_w + in_b (K=2) -------------
__global__ void k_input(const float* __restrict__ x, const float* __restrict__ w,
                        const float* __restrict__ b, float* __restrict__ h) {
    int idx = blockIdx.x * 256 + threadIdx.x;
    int d = idx & (DD - 1);
    int r = idx >> 8;
    h[idx] = fmaf(x[2*r], w[d], fmaf(x[2*r+1], w[DD + d], b[d]));
}

// ------- split-tf32 MMA GEMM (near-fp32): C = A@W + bias [, relu] ----------
template<bool RELU>
__global__ void __launch_bounds__(256) k_gemm_mma(
        const float* __restrict__ A, const float* __restrict__ W,
        const float* __restrict__ bias, float* __restrict__ C,
        int M, int N, int K) {
    __shared__ unsigned AsH[64*40], AsL[64*40];
    __shared__ unsigned WsH[32*72], WsL[32*72];
    int tid = threadIdx.x;
    int w = tid >> 5, lane = tid & 31, g = lane >> 2, t = lane & 3;
    int wm = w >> 1, wn = w & 1;
    int m0 = blockIdx.y * 64, n0 = blockIdx.x * 64;
    float acc[4][4] = {};
    for (int k0 = 0; k0 < K; k0 += 32) {
        for (int i = tid; i < 512; i += 256) {
            int r = i >> 3, c4 = i & 7;
            float4 av = *(const float4*)&A[(size_t)(m0 + r) * K + k0 + c4*4];
            int base = r*40 + c4*4;
            unsigned h0 = f2tf(av.x), h1 = f2tf(av.y), h2 = f2tf(av.z), h3 = f2tf(av.w);
            AsH[base]   = h0; AsL[base]   = f2tf(av.x - __uint_as_float(h0));
            AsH[base+1] = h1; AsL[base+1] = f2tf(av.y - __uint_as_float(h1));
            AsH[base+2] = h2; AsL[base+2] = f2tf(av.z - __uint_as_float(h2));
            AsH[base+3] = h3; AsL[base+3] = f2tf(av.w - __uint_as_float(h3));
        }
        for (int i = tid; i < 512; i += 256) {
            int kk = i >> 4, c4 = i & 15;
            float4 wv = *(const float4*)&W[(size_t)(k0 + kk) * N + n0 + c4*4];
            int base = kk*72 + c4*4;
            unsigned h0 = f2tf(wv.x), h1 = f2tf(wv.y), h2 = f2tf(wv.z), h3 = f2tf(wv.w);
            WsH[base]   = h0; WsL[base]   = f2tf(wv.x - __uint_as_float(h0));
            WsH[base+1] = h1; WsL[base+1] = f2tf(wv.y - __uint_as_float(h1));
            WsH[base+2] = h2; WsL[base+2] = f2tf(wv.z - __uint_as_float(h2));
            WsH[base+3] = h3; WsL[base+3] = f2tf(wv.w - __uint_as_float(h3));
        }
        __syncthreads();
        #pragma unroll
        for (int kk = 0; kk < 4; kk++) {
            unsigned aH[4], aL[4];
            int ar = wm*16;
            aH[0] = AsH[(ar + g    )*40 + kk*8 + t];
            aH[1] = AsH[(ar + g + 8)*40 + kk*8 + t];
            aH[2] = AsH[(ar + g    )*40 + kk*8 + t + 4];
            aH[3] = AsH[(ar + g + 8)*40 + kk*8 + t + 4];
            aL[0] = AsL[(ar + g    )*40 + kk*8 + t];
            aL[1] = AsL[(ar + g + 8)*40 + kk*8 + t];
            aL[2] = AsL[(ar + g    )*40 + kk*8 + t + 4];
            aL[3] = AsL[(ar + g + 8)*40 + kk*8 + t + 4];
            #pragma unroll
            for (int nt = 0; nt < 4; nt++) {
                unsigned bH[2], bL[2];
                int nc = wn*32 + nt*8 + g;
                bH[0] = WsH[(kk*8 + t    )*72 + nc];
                bH[1] = WsH[(kk*8 + t + 4)*72 + nc];
                bL[0] = WsL[(kk*8 + t    )*72 + nc];
                bL[1] = WsL[(kk*8 + t + 4)*72 + nc];
                mma_tf32(acc[nt], aL, bH);
                mma_tf32(acc[nt], aH, bL);
                mma_tf32(acc[nt], aH, bH);
            }
        }
        __syncthreads();
    }
    #pragma unroll
    for (int nt = 0; nt < 4; nt++) {
        int col = n0 + wn*32 + nt*8 + t*2;
        int r0  = m0 + wm*16 + g;
        float b0v = bias[col], b1v = bias[col + 1];
        float c00 = acc[nt][0] + b0v, c01 = acc[nt][1] + b1v;
        float c10 = acc[nt][2] + b0v, c11 = acc[nt][3] + b1v;
        if (RELU) {
            c00 = fmaxf(c00, 0.f); c01 = fmaxf(c01, 0.f);
            c10 = fmaxf(c10, 0.f); c11 = fmaxf(c11, 0.f);
        }
        C[(size_t)r0*N + col]     = c00; C[(size_t)r0*N + col + 1]     = c01;
        C[(size_t)(r0+8)*N + col] = c10; C[(size_t)(r0+8)*N + col + 1] = c11;
    }
}

// ------- fused QKV: load h tile once, apply 3 weight banks (split-tf32) ----
// grid (HD/64=2, BL/64), 256 thr
__global__ void __launch_bounds__(256) k_qkv(
        const float* __restrict__ A,
        const float* __restrict__ qw, const float* __restrict__ qb2,
        const float* __restrict__ kw, const float* __restrict__ kb2,
        const float* __restrict__ vw, const float* __restrict__ vb2,
        float* __restrict__ q, float* __restrict__ k, float* __restrict__ v) {
    extern __shared__ unsigned qsm[];
    unsigned* AsH = qsm;                 // 64*40
    unsigned* AsL = AsH + 64*40;
    unsigned* WsH = AsL + 64*40;         // 3*32*72
    unsigned* WsL = WsH + 3*32*72;
    int tid = threadIdx.x;
    int w = tid >> 5, lane = tid & 31, g = lane >> 2, t = lane & 3;
    int wm = w >> 1, wn = w & 1;
    int m0 = blockIdx.y * 64, n0 = blockIdx.x * 64;
    const float* Wp[3] = {qw, kw, vw};
    float acc[3][4][4] = {};
    for (int k0 = 0; k0 < DD; k0 += 32) {
        for (int i = tid; i < 512; i += 256) {
            int r = i >> 3, c4 = i & 7;
            float4 av = *(const float4*)&A[(size_t)(m0 + r) * DD + k0 + c4*4];
            int base = r*40 + c4*4;
            unsigned h0 = f2tf(av.x), h1 = f2tf(av.y), h2 = f2tf(av.z), h3 = f2tf(av.w);
            AsH[base]   = h0; AsL[base]   = f2tf(av.x - __uint_as_float(h0));
            AsH[base+1] = h1; AsL[base+1] = f2tf(av.y - __uint_as_float(h1));
            AsH[base+2] = h2; AsL[base+2] = f2tf(av.z - __uint_as_float(h2));
            AsH[base+3] = h3; AsL[base+3] = f2tf(av.w - __uint_as_float(h3));
        }
        for (int i = tid; i < 1536; i += 256) {
            int o = i >> 9, j = i & 511;
            int kk = j >> 4, c4 = j & 15;
            float4 wv = *(const float4*)&Wp[o][(size_t)(k0 + kk) * HD + n0 + c4*4];
            int base = o*2304 + kk*72 + c4*4;
            unsigned h0 = f2tf(wv.x), h1 = f2tf(wv.y), h2 = f2tf(wv.z), h3 = f2tf(wv.w);
            WsH[base]   = h0; WsL[base]   = f2tf(wv.x - __uint_as_float(h0));
            WsH[base+1] = h1; WsL[base+1] = f2tf(wv.y - __uint_as_float(h1));
            WsH[base+2] = h2; WsL[base+2] = f2tf(wv.z - __uint_as_float(h2));
            WsH[base+3] = h3; WsL[base+3] = f2tf(wv.w - __uint_as_float(h3));
        }
        __syncthreads();
        #pragma unroll
        for (int kk = 0; kk < 4; kk++) {
            unsigned aH[4], aL[4];
            int ar = wm*16;
            aH[0] = AsH[(ar + g    )*40 + kk*8 + t];
            aH[1] = AsH[(ar + g + 8)*40 + kk*8 + t];
            aH[2] = AsH[(ar + g    )*40 + kk*8 + t + 4];
            aH[3] = AsH[(ar + g + 8)*40 + kk*8 + t + 4];
            aL[0] = AsL[(ar + g    )*40 + kk*8 + t];
            aL[1] = AsL[(ar + g + 8)*40 + kk*8 + t];
            aL[2] = AsL[(ar + g    )*40 + kk*8 + t + 4];
            aL[3] = AsL[(ar + g + 8)*40 + kk*8 + t + 4];
            #pragma unroll
            for (int o = 0; o < 3; o++) {
                #pragma unroll
                for (int nt = 0; nt < 4; nt++) {
                    unsigned bH[2], bL[2];
                    int nc = o*2304 + wn*32 + nt*8 + g;
                    bH[0] = WsH[(kk*8 + t    )*72 + nc];
                    bH[1] = WsH[(kk*8 + t + 4)*72 + nc];
                    bL[0] = WsL[(kk*8 + t    )*72 + nc];
                    bL[1] = WsL[(kk*8 + t + 4)*72 + nc];
                    mma_tf32(acc[o][nt], aL, bH);
                    mma_tf32(acc[o][nt], aH, bL);
                    mma_tf32(acc[o][nt], aH, bH);
                }
            }
        }
        __syncthreads();
    }
    float* Co[3] = {q, k, v};
    const float* Bo[3] = {qb2, kb2, vb2};
    #pragma unroll
    for (int o = 0; o < 3; o++) {
        #pragma unroll
        for (int nt = 0; nt < 4; nt++) {
            int col = n0 + wn*32 + nt*8 + t*2;
            int r0  = m0 + wm*16 + g;
            float b0v = Bo[o][col], b1v = Bo[o][col + 1];
            Co[o][(size_t)r0*HD + col]       = acc[o][nt][0] + b0v;
            Co[o][(size_t)r0*HD + col + 1]   = acc[o][nt][1] + b1v;
            Co[o][(size_t)(r0+8)*HD + col]   = acc[o][nt][2] + b0v;
            Co[o][(size_t)(r0+8)*HD + col+1] = acc[o][nt][3] + b1v;
        }
    }
}

// ------- k_stats: per-row (max, 1/sumexp) of scale*Q@K^T, no S write -------
// grid (16 row-tiles, 32 bh), 256 thr (warps 2x4, warp tile 64x32)
__global__ void __launch_bounds__(256) k_stats(
        const float* __restrict__ Q, const float* __restrict__ Kv,
        float* __restrict__ st) {
    __shared__ unsigned Qs[128*36];
    __shared__ unsigned Ks[128*36];
    __shared__ float pM[4*128], pS[4*128];
    int tid = threadIdx.x;
    int w = tid >> 5, lane = tid & 31, g = lane >> 2, t = lane & 3;
    int wm = w >> 2, wn = w & 3;
    int l0 = blockIdx.x * 128;
    int bh = blockIdx.y, b = bh >> 2, hh = bh & 3;
    const float* qb = Q  + (size_t)b * LL * HD + hh * DKK;
    const float* kb = Kv + (size_t)b * LL * HD + hh * DKK;

    for (int i = tid; i < 4096; i += 256) {
        int r = i >> 5, c = i & 31;
        Qs[r*36 + c] = f2tf((l0 + r < LL) ? qb[(size_t)(l0 + r) * HD + c] : 0.f);
    }
    float rm_r = -1e30f, rs_r = 0.f;   // running stats for row `tid` (tid<128)
    for (int s0 = 0; s0 < LL; s0 += 128) {
        __syncthreads();
        for (int i = tid; i < 4096; i += 256) {
            int r = i >> 5, c = i & 31;
            Ks[r*36 + c] = f2tf((s0 + r < LL) ? kb[(size_t)(s0 + r) * HD + c] : 0.f);
        }
        __syncthreads();
        float acc[4][4][4] = {};
        #pragma unroll
        for (int kk = 0; kk < 4; kk++) {
            unsigned bfr[4][2];
            #pragma unroll
            for (int ni = 0; ni < 4; ni++) {
                int nr = wn*32 + ni*8 + g;
                bfr[ni][0] = Ks[nr*36 + kk*8 + t];
                bfr[ni][1] = Ks[nr*36 + kk*8 + t + 4];
            }
            #pragma unroll
            for (int mi = 0; mi < 4; mi++) {
                unsigned a[4];
                int ar = wm*64 + mi*16;
                a[0] = Qs[(ar + g    )*36 + kk*8 + t];
                a[1] = Qs[(ar + g + 8)*36 + kk*8 + t];
                a[2] = Qs[(ar + g    )*36 + kk*8 + t + 4];
                a[3] = Qs[(ar + g + 8)*36 + kk*8 + t + 4];
                #pragma unroll
                for (int ni = 0; ni < 4; ni++)
                    mma_tf32(acc[mi][ni], a, bfr[ni]);
            }
        }
        // per-thread local stats per owned row, merged over t lanes then warps
        #pragma unroll
        for (int mi = 0; mi < 4; mi++) {
            #pragma unroll
            for (int hf = 0; hf < 2; hf++) {
                float vals[8];
                float m = -1e30f;
                #pragma unroll
                for (int ni = 0; ni < 4; ni++) {
                    int c = s0 + wn*32 + ni*8 + t*2;
                    float v0 = (c     < LL) ? acc[mi][ni][hf*2]   * SCALE : -1e30f;
                    float v1 = (c + 1 < LL) ? acc[mi][ni][hf*2+1] * SCALE : -1e30f;
                    vals[ni*2] = v0; vals[ni*2+1] = v1;
                    m = fmaxf(m, fmaxf(v0, v1));
                }
                float s = 0.f;
                if (m > -1e29f) {
                    #pragma unroll
                    for (int j = 0; j < 8; j++) s += __expf(vals[j] - m);
                }
                #pragma unroll
                for (int off = 1; off <= 2; off <<= 1) {
                    float om = __shfl_xor_sync(0xffffffffu, m, off);
                    float os = __shfl_xor_sync(0xffffffffu, s, off);
                    float M = fmaxf(m, om);
                    s = s * __expf(m - M) + os * __expf(om - M);
                    m = M;
                }
                if (t == 0) {
                    int row = wm*64 + mi*16 + g + hf*8;
                    pM[wn*128 + row] = m;
                    pS[wn*128 + row] = s;
                }
            }
        }
        __syncthreads();
        if (tid < 128) {
            #pragma unroll
            for (int j = 0; j < 4; j++) {
                float om = pM[j*128 + tid], os = pS[j*128 + tid];
                float M = fmaxf(rm_r, om);
                rs_r = rs_r * __expf(rm_r - M) + os * __expf(om - M);
                rm_r = M;
            }
        }
    }
    if (tid < 128 && l0 + tid < LL) {
        float* sp = st + ((size_t)bh * LL + l0 + tid) * 2;
        sp[0] = rm_r;
        sp[1] = 1.f / rs_r;
    }
}

// ------- k_pv: recompute S tile, P=exp(s-m)*inv -> gmem P, O += P@V --------
// grid (16 row-tiles, 32 bh), 256 thr. S warps 4x2 (32x32), PV warps 8x16rows
__global__ void __launch_bounds__(256) k_pv(
        const float* __restrict__ Q, const float* __restrict__ Kv,
        const float* __restrict__ V, const float* __restrict__ st,
        float* __restrict__ P, float* __restrict__ O) {
    extern __shared__ unsigned psm[];
    unsigned* Qs = psm;                  // 128*36
    unsigned* Ks = Qs + 128*36;          // 64*36
    unsigned* Vs = Ks + 64*36;           // 64*36
    unsigned* Ps = Vs + 64*36;           // 128*68
    float* ms  = (float*)(Ps + 128*68);  // 128
    float* inv = ms + 128;               // 128
    int tid = threadIdx.x;
    int w = tid >> 5, lane = tid & 31, g = lane >> 2, t = lane & 3;
    int wm = w >> 1, wn = w & 1;
    int l0 = blockIdx.x * 128;
    int bh = blockIdx.y, b = bh >> 2, hh = bh & 3;
    const float* qb = Q  + (size_t)b * LL * HD + hh * DKK;
    const float* kb = Kv + (size_t)b * LL * HD + hh * DKK;
    const float* vb = V  + (size_t)b * LL * HD + hh * DKK;
    float* Pb = P + (size_t)bh * LL * LL;

    for (int i = tid; i < 4096; i += 256) {
        int r = i >> 5, c = i & 31;
        Qs[r*36 + c] = f2tf((l0 + r < LL) ? qb[(size_t)(l0 + r) * HD + c] : 0.f);
    }
    if (tid < 128) {
        int row = l0 + tid;
        ms[tid]  = (row < LL) ? st[((size_t)bh*LL + row)*2]     : 0.f;
        inv[tid] = (row < LL) ? st[((size_t)bh*LL + row)*2 + 1] : 0.f;
    }
    float acc2[4][4] = {};   // PV accum: warp w rows w*16..+15, 32 cols
    for (int s0 = 0; s0 < LL; s0 += 64) {
        __syncthreads();
        for (int i = tid; i < 2048; i += 256) {
            int r = i >> 5, c = i & 31;
            int sr = s0 + r;
            Ks[r*36 + c] = f2tf((sr < LL) ? kb[(size_t)sr * HD + c] : 0.f);
            Vs[r*36 + c] = f2tf((sr < LL) ? vb[(size_t)sr * HD + c] : 0.f);
        }
        __syncthreads();
        float acc[2][4][4] = {};
        #pragma unroll
        for (int kk = 0; kk < 4; kk++) {
            unsigned bfr[4][2];
            #pragma unroll
            for (int ni = 0; ni < 4; ni++) {
                int nr = wn*32 + ni*8 + g;
                bfr[ni][0] = Ks[nr*36 + kk*8 + t];
                bfr[ni][1] = Ks[nr*36 + kk*8 + t + 4];
            }
            #pragma unroll
            for (int mi = 0; mi < 2; mi++) {
                unsigned a[4];
                int ar = wm*32 + mi*16;
                a[0] = Qs[(ar + g    )*36 + kk*8 + t];
                a[1] = Qs[(ar + g + 8)*36 + kk*8 + t];
                a[2] = Qs[(ar + g    )*36 + kk*8 + t + 4];
                a[3] = Qs[(ar + g + 8)*36 + kk*8 + t + 4];
                #pragma unroll
                for (int ni = 0; ni < 4; ni++)
                    mma_tf32(acc[mi][ni], a, bfr[ni]);
            }
        }
        // exp + write P (gmem) + Ps (smem)
        #pragma unroll
        for (int mi = 0; mi < 2; mi++) {
            #pragma unroll
            for (int ni = 0; ni < 4; ni++) {
                int rl = wm*32 + mi*16 + g;
                int cl = wn*32 + ni*8 + t*2;
                int col = s0 + cl;
                int rowg = l0 + rl;
                float p0 = 0.f, p1 = 0.f, p2 = 0.f, p3 = 0.f;
                if (col < LL) {
                    p0 = __expf(acc[mi][ni][0]*SCALE - ms[rl])   * inv[rl];
                    p2 = __expf(acc[mi][ni][2]*SCALE - ms[rl+8]) * inv[rl+8];
                }
                if (col + 1 < LL) {
                    p1 = __expf(acc[mi][ni][1]*SCALE - ms[rl])   * inv[rl];
                    p3 = __expf(acc[mi][ni][3]*SCALE - ms[rl+8]) * inv[rl+8];
                }
                if (rowg < LL) {
                    if (col     < LL) Pb[(size_t)rowg*LL + col]     = p0;
                    if (col + 1 < LL) Pb[(size_t)rowg*LL + col + 1] = p1;
                }
                if (rowg + 8 < LL) {
                    if (col     < LL) Pb[(size_t)(rowg+8)*LL + col]     = p2;
                    if (col + 1 < LL) Pb[(size_t)(rowg+8)*LL + col + 1] = p3;
                }
                Ps[rl*68 + cl]       = f2tf(p0);
                Ps[rl*68 + cl + 1]   = f2tf(p1);
                Ps[(rl+8)*68 + cl]   = f2tf(p2);
                Ps[(rl+8)*68 + cl+1] = f2tf(p3);
            }
        }
        __syncthreads();
        // PV MMA: warp w -> rows w*16..w*16+15
        #pragma unroll
        for (int kk = 0; kk < 8; kk++) {
            unsigned a[4];
            int ar = w*16;
            a[0] = Ps[(ar + g    )*68 + kk*8 + t];
            a[1] = Ps[(ar + g + 8)*68 + kk*8 + t];
            a[2] = Ps[(ar + g    )*68 + kk*8 + t + 4];
            a[3] = Ps[(ar + g + 8)*68 + kk*8 + t + 4];
            #pragma unroll
            for (int ni = 0; ni < 4; ni++) {
                unsigned b2[2];
                b2[0] = Vs[(kk*8 + t    )*36 + ni*8 + g];
                b2[1] = Vs[(kk*8 + t + 4)*36 + ni*8 + g];
                mma_tf32(acc2[ni], a, b2);
            }
        }
    }
    float* ob = O + (size_t)b * LL * HD + hh * DKK;
    #pragma unroll
    for (int ni = 0; ni < 4; ni++) {
        int r0 = l0 + w*16 + g;
        int c0 = ni*8 + t*2;
        if (r0 < LL) {
            ob[(size_t)r0*HD + c0]     = acc2[ni][0];
            ob[(size_t)r0*HD + c0 + 1] = acc2[ni][1];
        }
        if (r0 + 8 < LL) {
            ob[(size_t)(r0+8)*HD + c0]     = acc2[ni][2];
            ob[(size_t)(r0+8)*HD + c0 + 1] = acc2[ni][3];
        }
    }
}

// ---------------- h = LayerNorm(h + add) * g + b (row of 256) --------------
__global__ void k_ln(float* __restrict__ h, const float* __restrict__ add,
                     const float* __restrict__ g, const float* __restrict__ bta) {
    int row  = blockIdx.x * 8 + (threadIdx.x >> 5);
    int lane = threadIdx.x & 31;
    float* hp = h + (size_t)row * DD;
    const float* ap = add + (size_t)row * DD;
    float v[8]; float s = 0.f;
    #pragma unroll
    for (int i = 0; i < 8; i++) {
        v[i] = hp[lane + 32*i] + ap[lane + 32*i];
        s += v[i];
    }
    #pragma unroll
    for (int o = 16; o > 0; o >>= 1) s += __shfl_xor_sync(0xffffffffu, s, o);
    float mean = s * (1.f / DD);
    float var = 0.f;
    #pragma unroll
    for (int i = 0; i < 8; i++) { float d = v[i] - mean; var = fmaf(d, d, var); }
    #pragma unroll
    for (int o = 16; o > 0; o >>= 1) var += __shfl_xor_sync(0xffffffffu, var, o);
    var *= (1.f / DD);
    float r = rsqrtf(var + EPSV);
    #pragma unroll
    for (int i = 0; i < 8; i++) {
        int d = lane + 32*i;
        hp[d] = (v[i] - mean) * r * g[d] + bta[d];
    }
}

// ---------------- final head: out = A(relu'd) @ o2w(256x2) + o2b -----------
__global__ void k_out2(const float* __restrict__ A, const float* __restrict__ w,
                       const float* __restrict__ b, float* __restrict__ out) {
    int row  = blockIdx.x * 8 + (threadIdx.x >> 5);
    int lane = threadIdx.x & 31;
    const float* ap = A + (size_t)row * DD;
    float s0 = 0.f, s1 = 0.f;
    #pragma unroll
    for (int i = 0; i < 8; i++) {
        int d = lane + 32*i;
        float a = ap[d];
        s0 = fmaf(a, w[d*2],     s0);
        s1 = fmaf(a, w[d*2 + 1], s1);
    }
    #pragma unroll
    for (int o = 16; o > 0; o >>= 1) {
        s0 += __shfl_xor_sync(0xffffffffu, s0, o);
        s1 += __shfl_xor_sync(0xffffffffu, s1, o);
    }
    if (lane == 0) {
        out[(size_t)row*2]     = s0 + b[0];
        out[(size_t)row*2 + 1] = s1 + b[1];
    }
}

// ---------------------------------------------------------------------------
extern "C" void kernel_launch(void* const* d_in, const int* in_sizes, int n_in,
                              void* d_out, int out_size) {
    const float* x    = (const float*)d_in[0];
    const float* in_w = (const float*)d_in[1];
    const float* in_b = (const float*)d_in[2];
    const float* qw   = (const float*)d_in[3];
    const float* qb   = (const float*)d_in[4];
    const float* kw   = (const float*)d_in[5];
    const float* kb   = (const float*)d_in[6];
    const float* vw   = (const float*)d_in[7];
    const float* vb   = (const float*)d_in[8];
    const float* ow   = (const float*)d_in[9];
    const float* ob   = (const float*)d_in[10];
    const float* f1w  = (const float*)d_in[11];
    const float* f1b  = (const float*)d_in[12];
    const float* f2w  = (const float*)d_in[13];
    const float* f2b  = (const float*)d_in[14];
    const float* n1g  = (const float*)d_in[15];
    const float* n1b  = (const float*)d_in[16];
    const float* n2g  = (const float*)d_in[17];
    const float* n2b  = (const float*)d_in[18];
    const float* o1w  = (const float*)d_in[19];
    const float* o1b  = (const float*)d_in[20];
    const float* o2w  = (const float*)d_in[21];
    const float* o2b  = (const float*)d_in[22];

    float* out  = (float*)d_out;
    float* attn = out + (size_t)BB * LL * 2;   // attns region: (NL,B,H,L,L)

    float *h, *q, *k, *v, *o, *t1, *ff, *st;
    cudaGetSymbolAddress((void**)&h,  g_h);
    cudaGetSymbolAddress((void**)&q,  g_q);
    cudaGetSymbolAddress((void**)&k,  g_k);
    cudaGetSymbolAddress((void**)&v,  g_v);
    cudaGetSymbolAddress((void**)&o,  g_o);
    cudaGetSymbolAddress((void**)&t1, g_t1);
    cudaGetSymbolAddress((void**)&ff, g_ff);
    cudaGetSymbolAddress((void**)&st, g_stat);

    const int SMEM_QKV = (2*64*40 + 2*3*32*72) * 4;                 // 75776
    const int SMEM_PV  = (128*36 + 64*36 + 64*36 + 128*68) * 4 + 1024; // 72704
    cudaFuncSetAttribute(k_qkv, cudaFuncAttributeMaxDynamicSharedMemorySize, SMEM_QKV);
    cudaFuncSetAttribute(k_pv,  cudaFuncAttributeMaxDynamicSharedMemorySize, SMEM_PV);

    // input projection
    k_input<<<(BL*DD)/256, 256>>>(x, in_w, in_b, h);

    const int RT = (LL + 127) / 128;   // 16 row tiles

    for (int i = 0; i < NLL; i++) {
        const float* qwi = qw + (size_t)i * DD * HD;
        const float* qbi = qb + (size_t)i * HD;
        const float* kwi = kw + (size_t)i * DD * HD;
        const float* kbi = kb + (size_t)i * HD;
        const float* vwi = vw + (size_t)i * DD * HD;
        const float* vbi = vb + (size_t)i * HD;
        const float* owi = ow + (size_t)i * HD * DD;
        const float* obi = ob + (size_t)i * DD;
        const float* f1wi = f1w + (size_t)i * DD * FCC;
        const float* f1bi = f1b + (size_t)i * FCC;
        const float* f2wi = f2w + (size_t)i * FCC * DD;
        const float* f2bi = f2b + (size_t)i * DD;

        // fused Q,K,V projection
        k_qkv<<<dim3(HD/64, BL/64), 256, SMEM_QKV>>>(
            h, qwi, qbi, kwi, kbi, vwi, vbi, q, k, v);

        // flash-style attention: stats pass then P+O pass
        float* Si = attn + (size_t)i * BHH * LL * LL;
        k_stats<<<dim3(RT, BHH), 256>>>(q, k, st);
        k_pv<<<dim3(RT, BHH), 256, SMEM_PV>>>(q, k, v, st, Si, o);

        // output projection + residual LN
        k_gemm_mma<false><<<dim3(DD/64, BL/64), 256>>>(o, owi, obi, t1, BL, DD, HD);
        k_ln<<<BL/8, 256>>>(h, t1, n1g + (size_t)i*DD, n1b + (size_t)i*DD);

        // FFN + residual LN
        k_gemm_mma<true ><<<dim3(FCC/64, BL/64), 256>>>(h, f1wi, f1bi, ff, BL, FCC, DD);
        k_gemm_mma<false><<<dim3(DD/64, BL/64), 256>>>(ff, f2wi, f2bi, t1, BL, DD, FCC);
        k_ln<<<BL/8, 256>>>(h, t1, n2g + (size_t)i*DD, n2b + (size_t)i*DD);
    }

    // final MLP head
    k_gemm_mma<true><<<dim3(DD/64, BL/64), 256>>>(h, o1w, o1b, t1, BL, DD, DD);
    k_out2<<<BL/8, 256>>>(t1, o2w, o2b, out);
}

// round 6
// speedup vs baseline: 3.4144x; 1.2943x over previous
#include <cuda_runtime.h>
#include <math.h>

#define BB   8
#define LL   2016
#define HH   4
#define DKK  32
#define DD   256
#define FCC  64
#define NLL  3
#define BL   (BB*LL)      // 16128
#define HD   (HH*DKK)     // 128
#define BHH  (BB*HH)      // 32
#define SCALE 0.0625f     // 1/sqrt(256)
#define EPSV  1e-5f
#define LOG2E 1.4426950408889634f

// ---------------- scratch (device globals: no allocation allowed) ----------
__device__ float g_h [BL*DD];
__device__ float g_q [BL*HD];
__device__ float g_k [BL*HD];
__device__ float g_v [BL*HD];
__device__ float g_o [BL*HD];
__device__ float g_t1[BL*DD];
__device__ float g_ff[BL*FCC];

// ---------------- tf32 helpers --------------------------------------------
__device__ __forceinline__ unsigned f2tf(float f) {
    unsigned u;
    asm("cvt.rna.tf32.f32 %0, %1;" : "=r"(u) : "f"(f));
    return u;
}

__device__ __forceinline__ float ex2(float x) {
    float r;
    asm("ex2.approx.f32 %0, %1;" : "=f"(r) : "f"(x));
    return r;
}

__device__ __forceinline__ void mma_tf32(float* d, const unsigned* a, const unsigned* b) {
    asm("mma.sync.aligned.m16n8k8.row.col.f32.tf32.tf32.f32 "
        "{%0,%1,%2,%3},{%4,%5,%6,%7},{%8,%9},{%0,%1,%2,%3};"
        : "+f"(d[0]), "+f"(d[1]), "+f"(d[2]), "+f"(d[3])
        : "r"(a[0]), "r"(a[1]), "r"(a[2]), "r"(a[3]),
          "r"(b[0]), "r"(b[1]));
}

// ---------------- input projection: h = x @ in_w + in_b (K=2) -------------
__global__ void k_input(const float* __restrict__ x, const float* __restrict__ w,
                        const float* __restrict__ b, float* __restrict__ h) {
    int idx = blockIdx.x * 256 + threadIdx.x;
    int d = idx & (DD - 1);
    int r = idx >> 8;
    h[idx] = fmaf(x[2*r], w[d], fmaf(x[2*r+1], w[DD + d], b[d]));
}

// ------- split-tf32 MMA GEMM (near-fp32): C = A@W + bias [, relu] ----------
template<bool RELU>
__global__ void __launch_bounds__(256) k_gemm_mma(
        const float* __restrict__ A, const float* __restrict__ W,
        const float* __restrict__ bias, float* __restrict__ C,
        int M, int N, int K) {
    __shared__ unsigned AsH[64*40], AsL[64*40];
    __shared__ unsigned WsH[32*72], WsL[32*72];
    int tid = threadIdx.x;
    int w = tid >> 5, lane = tid & 31, g = lane >> 2, t = lane & 3;
    int wm = w >> 1, wn = w & 1;
    int m0 = blockIdx.y * 64, n0 = blockIdx.x * 64;
    float acc[4][4] = {};
    for (int k0 = 0; k0 < K; k0 += 32) {
        for (int i = tid; i < 512; i += 256) {
            int r = i >> 3, c4 = i & 7;
            float4 av = *(const float4*)&A[(size_t)(m0 + r) * K + k0 + c4*4];
            int base = r*40 + c4*4;
            unsigned h0 = f2tf(av.x), h1 = f2tf(av.y), h2 = f2tf(av.z), h3 = f2tf(av.w);
            AsH[base]   = h0; AsL[base]   = f2tf(av.x - __uint_as_float(h0));
            AsH[base+1] = h1; AsL[base+1] = f2tf(av.y - __uint_as_float(h1));
            AsH[base+2] = h2; AsL[base+2] = f2tf(av.z - __uint_as_float(h2));
            AsH[base+3] = h3; AsL[base+3] = f2tf(av.w - __uint_as_float(h3));
        }
        for (int i = tid; i < 512; i += 256) {
            int kk = i >> 4, c4 = i & 15;
            float4 wv = *(const float4*)&W[(size_t)(k0 + kk) * N + n0 + c4*4];
            int base = kk*72 + c4*4;
            unsigned h0 = f2tf(wv.x), h1 = f2tf(wv.y), h2 = f2tf(wv.z), h3 = f2tf(wv.w);
            WsH[base]   = h0; WsL[base]   = f2tf(wv.x - __uint_as_float(h0));
            WsH[base+1] = h1; WsL[base+1] = f2tf(wv.y - __uint_as_float(h1));
            WsH[base+2] = h2; WsL[base+2] = f2tf(wv.z - __uint_as_float(h2));
            WsH[base+3] = h3; WsL[base+3] = f2tf(wv.w - __uint_as_float(h3));
        }
        __syncthreads();
        #pragma unroll
        for (int kk = 0; kk < 4; kk++) {
            unsigned aH[4], aL[4];
            int ar = wm*16;
            aH[0] = AsH[(ar + g    )*40 + kk*8 + t];
            aH[1] = AsH[(ar + g + 8)*40 + kk*8 + t];
            aH[2] = AsH[(ar + g    )*40 + kk*8 + t + 4];
            aH[3] = AsH[(ar + g + 8)*40 + kk*8 + t + 4];
            aL[0] = AsL[(ar + g    )*40 + kk*8 + t];
            aL[1] = AsL[(ar + g + 8)*40 + kk*8 + t];
            aL[2] = AsL[(ar + g    )*40 + kk*8 + t + 4];
            aL[3] = AsL[(ar + g + 8)*40 + kk*8 + t + 4];
            #pragma unroll
            for (int nt = 0; nt < 4; nt++) {
                unsigned bH[2], bL[2];
                int nc = wn*32 + nt*8 + g;
                bH[0] = WsH[(kk*8 + t    )*72 + nc];
                bH[1] = WsH[(kk*8 + t + 4)*72 + nc];
                bL[0] = WsL[(kk*8 + t    )*72 + nc];
                bL[1] = WsL[(kk*8 + t + 4)*72 + nc];
                mma_tf32(acc[nt], aL, bH);
                mma_tf32(acc[nt], aH, bL);
                mma_tf32(acc[nt], aH, bH);
            }
        }
        __syncthreads();
    }
    #pragma unroll
    for (int nt = 0; nt < 4; nt++) {
        int col = n0 + wn*32 + nt*8 + t*2;
        int r0  = m0 + wm*16 + g;
        float b0v = bias[col], b1v = bias[col + 1];
        float c00 = acc[nt][0] + b0v, c01 = acc[nt][1] + b1v;
        float c10 = acc[nt][2] + b0v, c11 = acc[nt][3] + b1v;
        if (RELU) {
            c00 = fmaxf(c00, 0.f); c01 = fmaxf(c01, 0.f);
            c10 = fmaxf(c10, 0.f); c11 = fmaxf(c11, 0.f);
        }
        C[(size_t)r0*N + col]     = c00; C[(size_t)r0*N + col + 1]     = c01;
        C[(size_t)(r0+8)*N + col] = c10; C[(size_t)(r0+8)*N + col + 1] = c11;
    }
}

// ------- fused QKV: load h tile once, apply 3 weight banks (split-tf32) ----
__global__ void __launch_bounds__(256) k_qkv(
        const float* __restrict__ A,
        const float* __restrict__ qw, const float* __restrict__ qb2,
        const float* __restrict__ kw, const float* __restrict__ kb2,
        const float* __restrict__ vw, const float* __restrict__ vb2,
        float* __restrict__ q, float* __restrict__ k, float* __restrict__ v) {
    extern __shared__ unsigned qsm[];
    unsigned* AsH = qsm;                 // 64*40
    unsigned* AsL = AsH + 64*40;
    unsigned* WsH = AsL + 64*40;         // 3*32*72
    unsigned* WsL = WsH + 3*32*72;
    int tid = threadIdx.x;
    int w = tid >> 5, lane = tid & 31, g = lane >> 2, t = lane & 3;
    int wm = w >> 1, wn = w & 1;
    int m0 = blockIdx.y * 64, n0 = blockIdx.x * 64;
    const float* Wp[3] = {qw, kw, vw};
    float acc[3][4][4] = {};
    for (int k0 = 0; k0 < DD; k0 += 32) {
        for (int i = tid; i < 512; i += 256) {
            int r = i >> 3, c4 = i & 7;
            float4 av = *(const float4*)&A[(size_t)(m0 + r) * DD + k0 + c4*4];
            int base = r*40 + c4*4;
            unsigned h0 = f2tf(av.x), h1 = f2tf(av.y), h2 = f2tf(av.z), h3 = f2tf(av.w);
            AsH[base]   = h0; AsL[base]   = f2tf(av.x - __uint_as_float(h0));
            AsH[base+1] = h1; AsL[base+1] = f2tf(av.y - __uint_as_float(h1));
            AsH[base+2] = h2; AsL[base+2] = f2tf(av.z - __uint_as_float(h2));
            AsH[base+3] = h3; AsL[base+3] = f2tf(av.w - __uint_as_float(h3));
        }
        for (int i = tid; i < 1536; i += 256) {
            int o = i >> 9, j = i & 511;
            int kk = j >> 4, c4 = j & 15;
            float4 wv = *(const float4*)&Wp[o][(size_t)(k0 + kk) * HD + n0 + c4*4];
            int base = o*2304 + kk*72 + c4*4;
            unsigned h0 = f2tf(wv.x), h1 = f2tf(wv.y), h2 = f2tf(wv.z), h3 = f2tf(wv.w);
            WsH[base]   = h0; WsL[base]   = f2tf(wv.x - __uint_as_float(h0));
            WsH[base+1] = h1; WsL[base+1] = f2tf(wv.y - __uint_as_float(h1));
            WsH[base+2] = h2; WsL[base+2] = f2tf(wv.z - __uint_as_float(h2));
            WsH[base+3] = h3; WsL[base+3] = f2tf(wv.w - __uint_as_float(h3));
        }
        __syncthreads();
        #pragma unroll
        for (int kk = 0; kk < 4; kk++) {
            unsigned aH[4], aL[4];
            int ar = wm*16;
            aH[0] = AsH[(ar + g    )*40 + kk*8 + t];
            aH[1] = AsH[(ar + g + 8)*40 + kk*8 + t];
            aH[2] = AsH[(ar + g    )*40 + kk*8 + t + 4];
            aH[3] = AsH[(ar + g + 8)*40 + kk*8 + t + 4];
            aL[0] = AsL[(ar + g    )*40 + kk*8 + t];
            aL[1] = AsL[(ar + g + 8)*40 + kk*8 + t];
            aL[2] = AsL[(ar + g    )*40 + kk*8 + t + 4];
            aL[3] = AsL[(ar + g + 8)*40 + kk*8 + t + 4];
            #pragma unroll
            for (int o = 0; o < 3; o++) {
                #pragma unroll
                for (int nt = 0; nt < 4; nt++) {
                    unsigned bH[2], bL[2];
                    int nc = o*2304 + wn*32 + nt*8 + g;
                    bH[0] = WsH[(kk*8 + t    )*72 + nc];
                    bH[1] = WsH[(kk*8 + t + 4)*72 + nc];
                    bL[0] = WsL[(kk*8 + t    )*72 + nc];
                    bL[1] = WsL[(kk*8 + t + 4)*72 + nc];
                    mma_tf32(acc[o][nt], aL, bH);
                    mma_tf32(acc[o][nt], aH, bL);
                    mma_tf32(acc[o][nt], aH, bH);
                }
            }
        }
        __syncthreads();
    }
    float* Co[3] = {q, k, v};
    const float* Bo[3] = {qb2, kb2, vb2};
    #pragma unroll
    for (int o = 0; o < 3; o++) {
        #pragma unroll
        for (int nt = 0; nt < 4; nt++) {
            int col = n0 + wn*32 + nt*8 + t*2;
            int r0  = m0 + wm*16 + g;
            float b0v = Bo[o][col], b1v = Bo[o][col + 1];
            Co[o][(size_t)r0*HD + col]       = acc[o][nt][0] + b0v;
            Co[o][(size_t)r0*HD + col + 1]   = acc[o][nt][1] + b1v;
            Co[o][(size_t)(r0+8)*HD + col]   = acc[o][nt][2] + b0v;
            Co[o][(size_t)(r0+8)*HD + col+1] = acc[o][nt][3] + b1v;
        }
    }
}

// ------- merged flash attention: stats pass + P-write + P@V, one kernel ----
// grid (16 row-tiles of 128, 32 bh), 256 thr. Warp w owns rows w*16..w*16+15.
// Q frags in registers; P relayout via warp shuffles (no smem staging).
__global__ void __launch_bounds__(256) k_attn2(
        const float* __restrict__ Q, const float* __restrict__ Kv,
        const float* __restrict__ V, float* __restrict__ P,
        float* __restrict__ O) {
    __shared__ unsigned Ks[64*36];   // [s-row][dk], stride 36: conflict-free B-frags
    __shared__ unsigned Vs[64*40];   // [s-row][dv], stride 40: conflict-free B-frags
    int tid = threadIdx.x;
    int w = tid >> 5, lane = tid & 31, g = lane >> 2, t = lane & 3;
    int l0 = blockIdx.x * 128;
    int bh = blockIdx.y, b = bh >> 2, hh = bh & 3;
    const float* qb = Q  + (size_t)b * LL * HD + hh * DKK;
    const float* kb = Kv + (size_t)b * LL * HD + hh * DKK;
    const float* vb = V  + (size_t)b * LL * HD + hh * DKK;

    int row0 = l0 + w*16 + g;
    int row1 = row0 + 8;
    bool r0ok = row0 < LL, r1ok = row1 < LL;

    // Q fragments in registers (16 regs)
    unsigned qf[4][4];
    #pragma unroll
    for (int kk = 0; kk < 4; kk++) {
        qf[kk][0] = f2tf(r0ok ? qb[(size_t)row0*HD + kk*8 + t]     : 0.f);
        qf[kk][1] = f2tf(r1ok ? qb[(size_t)row1*HD + kk*8 + t]     : 0.f);
        qf[kk][2] = f2tf(r0ok ? qb[(size_t)row0*HD + kk*8 + t + 4] : 0.f);
        qf[kk][3] = f2tf(r1ok ? qb[(size_t)row1*HD + kk*8 + t + 4] : 0.f);
    }
    const float S2 = SCALE * LOG2E;

    // ---- phase 0: per-row (max, sumexp2) online -------------------------
    float m0 = -1e30f, z0 = 0.f, m1 = -1e30f, z1 = 0.f;
    for (int s0 = 0; s0 < LL; s0 += 64) {
        __syncthreads();
        for (int i = tid; i < 512; i += 256) {
            int r = i >> 3, c4 = (i & 7) * 4;
            int sr = s0 + r;
            uint4 kv;
            if (sr < LL) {
                float4 f = *(const float4*)&kb[(size_t)sr * HD + c4];
                kv.x = f2tf(f.x); kv.y = f2tf(f.y); kv.z = f2tf(f.z); kv.w = f2tf(f.w);
            } else kv.x = kv.y = kv.z = kv.w = 0u;
            *(uint4*)&Ks[r*36 + c4] = kv;
        }
        __syncthreads();
        float acc[8][4] = {};
        #pragma unroll
        for (int kk = 0; kk < 4; kk++) {
            #pragma unroll
            for (int ni = 0; ni < 8; ni++) {
                unsigned b2[2];
                b2[0] = Ks[(ni*8 + g)*36 + kk*8 + t];
                b2[1] = Ks[(ni*8 + g)*36 + kk*8 + t + 4];
                mma_tf32(acc[ni], qf[kk], b2);
            }
        }
        // scale to log2 domain + online stats (cols masked per 8-group)
        float lm0 = -1e30f, lm1 = -1e30f;
        #pragma unroll
        for (int ni = 0; ni < 8; ni++) {
            if (s0 + ni*8 < LL) {
                acc[ni][0] *= S2; acc[ni][1] *= S2;
                acc[ni][2] *= S2; acc[ni][3] *= S2;
                lm0 = fmaxf(lm0, fmaxf(acc[ni][0], acc[ni][1]));
                lm1 = fmaxf(lm1, fmaxf(acc[ni][2], acc[ni][3]));
            }
        }
        float nm0 = fmaxf(m0, lm0), nm1 = fmaxf(m1, lm1);
        z0 *= ex2(m0 - nm0); z1 *= ex2(m1 - nm1);
        m0 = nm0; m1 = nm1;
        #pragma unroll
        for (int ni = 0; ni < 8; ni++) {
            if (s0 + ni*8 < LL) {
                z0 += ex2(acc[ni][0] - m0) + ex2(acc[ni][1] - m0);
                z1 += ex2(acc[ni][2] - m1) + ex2(acc[ni][3] - m1);
            }
        }
    }
    // merge across the 4 t-lanes of each row quad
    #pragma unroll
    for (int off = 1; off <= 2; off <<= 1) {
        float om = __shfl_xor_sync(0xffffffffu, m0, off);
        float oz = __shfl_xor_sync(0xffffffffu, z0, off);
        float nm = fmaxf(m0, om);
        z0 = z0 * ex2(m0 - nm) + oz * ex2(om - nm);
        m0 = nm;
        om = __shfl_xor_sync(0xffffffffu, m1, off);
        oz = __shfl_xor_sync(0xffffffffu, z1, off);
        nm = fmaxf(m1, om);
        z1 = z1 * ex2(m1 - nm) + oz * ex2(om - nm);
        m1 = nm;
    }
    float inv0 = 1.f / z0, inv1 = 1.f / z1;

    // ---- phase 1: recompute S, write P, accumulate O = P@V ---------------
    float* Pb = P + (size_t)bh * LL * LL;
    float acc2[4][4] = {};
    for (int s0 = 0; s0 < LL; s0 += 64) {
        __syncthreads();
        for (int i = tid; i < 512; i += 256) {
            int r = i >> 3, c4 = (i & 7) * 4;
            int sr = s0 + r;
            uint4 kv, vv;
            if (sr < LL) {
                float4 f = *(const float4*)&kb[(size_t)sr * HD + c4];
                kv.x = f2tf(f.x); kv.y = f2tf(f.y); kv.z = f2tf(f.z); kv.w = f2tf(f.w);
                f = *(const float4*)&vb[(size_t)sr * HD + c4];
                vv.x = f2tf(f.x); vv.y = f2tf(f.y); vv.z = f2tf(f.z); vv.w = f2tf(f.w);
            } else {
                kv.x = kv.y = kv.z = kv.w = 0u;
                vv.x = vv.y = vv.z = vv.w = 0u;
            }
            *(uint4*)&Ks[r*36 + c4] = kv;
            *(uint4*)&Vs[r*40 + c4] = vv;
        }
        __syncthreads();
        float acc[8][4] = {};
        #pragma unroll
        for (int kk = 0; kk < 4; kk++) {
            #pragma unroll
            for (int ni = 0; ni < 8; ni++) {
                unsigned b2[2];
                b2[0] = Ks[(ni*8 + g)*36 + kk*8 + t];
                b2[1] = Ks[(ni*8 + g)*36 + kk*8 + t + 4];
                mma_tf32(acc[ni], qf[kk], b2);
            }
        }
        // exp + normalize + write P; stash tf32 bits back in acc
        #pragma unroll
        for (int ni = 0; ni < 8; ni++) {
            bool cok = (s0 + ni*8) < LL;
            float p0 = cok ? ex2(acc[ni][0]*S2 - m0) * inv0 : 0.f;
            float p1 = cok ? ex2(acc[ni][1]*S2 - m0) * inv0 : 0.f;
            float p2 = cok ? ex2(acc[ni][2]*S2 - m1) * inv1 : 0.f;
            float p3 = cok ? ex2(acc[ni][3]*S2 - m1) * inv1 : 0.f;
            if (cok) {
                size_t cidx = (size_t)(s0 + ni*8 + t*2);
                if (r0ok) *(float2*)&Pb[(size_t)row0*LL + cidx] = make_float2(p0, p1);
                if (r1ok) *(float2*)&Pb[(size_t)row1*LL + cidx] = make_float2(p2, p3);
            }
            acc[ni][0] = __uint_as_float(f2tf(p0));
            acc[ni][1] = __uint_as_float(f2tf(p1));
            acc[ni][2] = __uint_as_float(f2tf(p2));
            acc[ni][3] = __uint_as_float(f2tf(p3));
        }
        // PV: shuffle-relayout C-frags -> A-frags, mma with V
        int srcA = (lane & 0x1C) | (t >> 1);
        bool odd = (t & 1);
        #pragma unroll
        for (int kk = 0; kk < 8; kk++) {
            float x0 = __shfl_sync(0xffffffffu, acc[kk][0], srcA);
            float x1 = __shfl_sync(0xffffffffu, acc[kk][1], srcA);
            float y0 = __shfl_sync(0xffffffffu, acc[kk][2], srcA);
            float y1 = __shfl_sync(0xffffffffu, acc[kk][3], srcA);
            float x0b = __shfl_sync(0xffffffffu, acc[kk][0], srcA + 2);
            float x1b = __shfl_sync(0xffffffffu, acc[kk][1], srcA + 2);
            float y0b = __shfl_sync(0xffffffffu, acc[kk][2], srcA + 2);
            float y1b = __shfl_sync(0xffffffffu, acc[kk][3], srcA + 2);
            unsigned a[4];
            a[0] = __float_as_uint(odd ? x1  : x0);
            a[1] = __float_as_uint(odd ? y1  : y0);
            a[2] = __float_as_uint(odd ? x1b : x0b);
            a[3] = __float_as_uint(odd ? y1b : y0b);
            #pragma unroll
            for (int ni = 0; ni < 4; ni++) {
                unsigned b2[2];
                b2[0] = Vs[(kk*8 + t)*40 + ni*8 + g];
                b2[1] = Vs[(kk*8 + t + 4)*40 + ni*8 + g];
                mma_tf32(acc2[ni], a, b2);
            }
        }
    }
    float* ob = O + (size_t)b * LL * HD + hh * DKK;
    #pragma unroll
    for (int ni = 0; ni < 4; ni++) {
        int c0 = ni*8 + t*2;
        if (r0ok) *(float2*)&ob[(size_t)row0*HD + c0] = make_float2(acc2[ni][0], acc2[ni][1]);
        if (r1ok) *(float2*)&ob[(size_t)row1*HD + c0] = make_float2(acc2[ni][2], acc2[ni][3]);
    }
}

// ---------------- h = LayerNorm(h + add) * g + b (row of 256) --------------
__global__ void k_ln(float* __restrict__ h, const float* __restrict__ add,
                     const float* __restrict__ g, const float* __restrict__ bta) {
    int row  = blockIdx.x * 8 + (threadIdx.x >> 5);
    int lane = threadIdx.x & 31;
    float* hp = h + (size_t)row * DD;
    const float* ap = add + (size_t)row * DD;
    float v[8]; float s = 0.f;
    #pragma unroll
    for (int i = 0; i < 8; i++) {
        v[i] = hp[lane + 32*i] + ap[lane + 32*i];
        s += v[i];
    }
    #pragma unroll
    for (int o = 16; o > 0; o >>= 1) s += __shfl_xor_sync(0xffffffffu, s, o);
    float mean = s * (1.f / DD);
    float var = 0.f;
    #pragma unroll
    for (int i = 0; i < 8; i++) { float d = v[i] - mean; var = fmaf(d, d, var); }
    #pragma unroll
    for (int o = 16; o > 0; o >>= 1) var += __shfl_xor_sync(0xffffffffu, var, o);
    var *= (1.f / DD);
    float r = rsqrtf(var + EPSV);
    #pragma unroll
    for (int i = 0; i < 8; i++) {
        int d = lane + 32*i;
        hp[d] = (v[i] - mean) * r * g[d] + bta[d];
    }
}

// ---------------- final head: out = A(relu'd) @ o2w(256x2) + o2b -----------
__global__ void k_out2(const float* __restrict__ A, const float* __restrict__ w,
                       const float* __restrict__ b, float* __restrict__ out) {
    int row  = blockIdx.x * 8 + (threadIdx.x >> 5);
    int lane = threadIdx.x & 31;
    const float* ap = A + (size_t)row * DD;
    float s0 = 0.f, s1 = 0.f;
    #pragma unroll
    for (int i = 0; i < 8; i++) {
        int d = lane + 32*i;
        float a = ap[d];
        s0 = fmaf(a, w[d*2],     s0);
        s1 = fmaf(a, w[d*2 + 1], s1);
    }
    #pragma unroll
    for (int o = 16; o > 0; o >>= 1) {
        s0 += __shfl_xor_sync(0xffffffffu, s0, o);
        s1 += __shfl_xor_sync(0xffffffffu, s1, o);
    }
    if (lane == 0) {
        out[(size_t)row*2]     = s0 + b[0];
        out[(size_t)row*2 + 1] = s1 + b[1];
    }
}

// ---------------------------------------------------------------------------
extern "C" void kernel_launch(void* const* d_in, const int* in_sizes, int n_in,
                              void* d_out, int out_size) {
    const float* x    = (const float*)d_in[0];
    const float* in_w = (const float*)d_in[1];
    const float* in_b = (const float*)d_in[2];
    const float* qw   = (const float*)d_in[3];
    const float* qb   = (const float*)d_in[4];
    const float* kw   = (const float*)d_in[5];
    const float* kb   = (const float*)d_in[6];
    const float* vw   = (const float*)d_in[7];
    const float* vb   = (const float*)d_in[8];
    const float* ow   = (const float*)d_in[9];
    const float* ob   = (const float*)d_in[10];
    const float* f1w  = (const float*)d_in[11];
    const float* f1b  = (const float*)d_in[12];
    const float* f2w  = (const float*)d_in[13];
    const float* f2b  = (const float*)d_in[14];
    const float* n1g  = (const float*)d_in[15];
    const float* n1b  = (const float*)d_in[16];
    const float* n2g  = (const float*)d_in[17];
    const float* n2b  = (const float*)d_in[18];
    const float* o1w  = (const float*)d_in[19];
    const float* o1b  = (const float*)d_in[20];
    const float* o2w  = (const float*)d_in[21];
    const float* o2b  = (const float*)d_in[22];

    float* out  = (float*)d_out;
    float* attn = out + (size_t)BB * LL * 2;   // attns region: (NL,B,H,L,L)

    float *h, *q, *k, *v, *o, *t1, *ff;
    cudaGetSymbolAddress((void**)&h,  g_h);
    cudaGetSymbolAddress((void**)&q,  g_q);
    cudaGetSymbolAddress((void**)&k,  g_k);
    cudaGetSymbolAddress((void**)&v,  g_v);
    cudaGetSymbolAddress((void**)&o,  g_o);
    cudaGetSymbolAddress((void**)&t1, g_t1);
    cudaGetSymbolAddress((void**)&ff, g_ff);

    const int SMEM_QKV = (2*64*40 + 2*3*32*72) * 4;   // 75776
    cudaFuncSetAttribute(k_qkv, cudaFuncAttributeMaxDynamicSharedMemorySize, SMEM_QKV);

    // input projection
    k_input<<<(BL*DD)/256, 256>>>(x, in_w, in_b, h);

    const int RT = (LL + 127) / 128;   // 16 row tiles

    for (int i = 0; i < NLL; i++) {
        const float* qwi = qw + (size_t)i * DD * HD;
        const float* qbi = qb + (size_t)i * HD;
        const float* kwi = kw + (size_t)i * DD * HD;
        const float* kbi = kb + (size_t)i * HD;
        const float* vwi = vw + (size_t)i * DD * HD;
        const float* vbi = vb + (size_t)i * HD;
        const float* owi = ow + (size_t)i * HD * DD;
        const float* obi = ob + (size_t)i * DD;
        const float* f1wi = f1w + (size_t)i * DD * FCC;
        const float* f1bi = f1b + (size_t)i * FCC;
        const float* f2wi = f2w + (size_t)i * FCC * DD;
        const float* f2bi = f2b + (size_t)i * DD;

        // fused Q,K,V projection
        k_qkv<<<dim3(HD/64, BL/64), 256, SMEM_QKV>>>(
            h, qwi, qbi, kwi, kbi, vwi, vbi, q, k, v);

        // merged flash attention (stats + P + O)
        float* Si = attn + (size_t)i * BHH * LL * LL;
        k_attn2<<<dim3(RT, BHH), 256>>>(q, k, v, Si, o);

        // output projection + residual LN
        k_gemm_mma<false><<<dim3(DD/64, BL/64), 256>>>(o, owi, obi, t1, BL, DD, HD);
        k_ln<<<BL/8, 256>>>(h, t1, n1g + (size_t)i*DD, n1b + (size_t)i*DD);

        // FFN + residual LN
        k_gemm_mma<true ><<<dim3(FCC/64, BL/64), 256>>>(h, f1wi, f1bi, ff, BL, FCC, DD);
        k_gemm_mma<false><<<dim3(DD/64, BL/64), 256>>>(ff, f2wi, f2bi, t1, BL, DD, FCC);
        k_ln<<<BL/8, 256>>>(h, t1, n2g + (size_t)i*DD, n2b + (size_t)i*DD);
    }

    // final MLP head
    k_gemm_mma<true><<<dim3(DD/64, BL/64), 256>>>(h, o1w, o1b, t1, BL, DD, DD);
    k_out2<<<BL/8, 256>>>(t1, o2w, o2b, out);
}

// round 7
// speedup vs baseline: 3.7453x; 1.0969x over previous
#include <cuda_runtime.h>
#include <math.h>

#define BB   8
#define LL   2016
#define HH   4
#define DKK  32
#define DD   256
#define FCC  64
#define NLL  3
#define BL   (BB*LL)      // 16128
#define HD   (HH*DKK)     // 128
#define BHH  (BB*HH)      // 32
#define SCALE 0.0625f     // 1/sqrt(256)
#define EPSV  1e-5f
#define LOG2E 1.4426950408889634f

// ---------------- scratch (device globals: no allocation allowed) ----------
__device__ float g_h [BL*DD];
__device__ float g_q [BL*HD];
__device__ float g_k [BL*HD];
__device__ float g_v [BL*HD];
__device__ float g_o [BL*HD];
__device__ float g_t1[BL*DD];
__device__ float g_ff[BL*FCC];

// ---------------- tf32 helpers --------------------------------------------
__device__ __forceinline__ unsigned f2tf(float f) {
    unsigned u;
    asm("cvt.rna.tf32.f32 %0, %1;" : "=r"(u) : "f"(f));
    return u;
}

__device__ __forceinline__ float ex2(float x) {
    float r;
    asm("ex2.approx.f32 %0, %1;" : "=f"(r) : "f"(x));
    return r;
}

__device__ __forceinline__ void mma_tf32(float* d, const unsigned* a, const unsigned* b) {
    asm("mma.sync.aligned.m16n8k8.row.col.f32.tf32.tf32.f32 "
        "{%0,%1,%2,%3},{%4,%5,%6,%7},{%8,%9},{%0,%1,%2,%3};"
        : "+f"(d[0]), "+f"(d[1]), "+f"(d[2]), "+f"(d[3])
        : "r"(a[0]), "r"(a[1]), "r"(a[2]), "r"(a[3]),
          "r"(b[0]), "r"(b[1]));
}

__device__ __forceinline__ void split4(float4 f, uint4& hi, uint4& lo) {
    hi.x = f2tf(f.x); hi.y = f2tf(f.y); hi.z = f2tf(f.z); hi.w = f2tf(f.w);
    lo.x = f2tf(f.x - __uint_as_float(hi.x));
    lo.y = f2tf(f.y - __uint_as_float(hi.y));
    lo.z = f2tf(f.z - __uint_as_float(hi.z));
    lo.w = f2tf(f.w - __uint_as_float(hi.w));
}

__device__ __forceinline__ uint4 tf4(float4 f) {
    uint4 u;
    u.x = f2tf(f.x); u.y = f2tf(f.y); u.z = f2tf(f.z); u.w = f2tf(f.w);
    return u;
}

// ---------------- input projection: h = x @ in_w + in_b (K=2) -------------
__global__ void k_input(const float* __restrict__ x, const float* __restrict__ w,
                        const float* __restrict__ b, float* __restrict__ h) {
    int idx = blockIdx.x * 256 + threadIdx.x;
    int d = idx & (DD - 1);
    int r = idx >> 8;
    h[idx] = fmaf(x[2*r], w[d], fmaf(x[2*r+1], w[DD + d], b[d]));
}

// ------- 2-term split-tf32 GEMM: C = (aH+aL)@bH + bias [, relu] ------------
// block tile 128x64, 8 warps 4x2, warp tile 32x32. M%128==0, N%64==0, K%32==0
template<bool RELU>
__global__ void __launch_bounds__(256) k_gemm_mma(
        const float* __restrict__ A, const float* __restrict__ W,
        const float* __restrict__ bias, float* __restrict__ C,
        int M, int N, int K) {
    __shared__ unsigned AsH[128*36], AsL[128*36];
    __shared__ unsigned WsH[32*72];
    int tid = threadIdx.x;
    int w = tid >> 5, lane = tid & 31, g = lane >> 2, t = lane & 3;
    int wm = w >> 1, wn = w & 1;
    int m0 = blockIdx.y * 128, n0 = blockIdx.x * 64;
    float acc[2][4][4] = {};
    for (int k0 = 0; k0 < K; k0 += 32) {
        for (int i = tid; i < 1024; i += 256) {
            int r = i >> 3, c4 = (i & 7) * 4;
            float4 av = *(const float4*)&A[(size_t)(m0 + r) * K + k0 + c4];
            uint4 hi, lo; split4(av, hi, lo);
            *(uint4*)&AsH[r*36 + c4] = hi;
            *(uint4*)&AsL[r*36 + c4] = lo;
        }
        for (int i = tid; i < 512; i += 256) {
            int kk = i >> 4, c4 = (i & 15) * 4;
            float4 wv = *(const float4*)&W[(size_t)(k0 + kk) * N + n0 + c4];
            *(uint4*)&WsH[kk*72 + c4] = tf4(wv);
        }
        __syncthreads();
        #pragma unroll
        for (int kk = 0; kk < 4; kk++) {
            unsigned aH[2][4], aL[2][4];
            #pragma unroll
            for (int mi = 0; mi < 2; mi++) {
                int ar = wm*32 + mi*16;
                aH[mi][0] = AsH[(ar + g    )*36 + kk*8 + t];
                aH[mi][1] = AsH[(ar + g + 8)*36 + kk*8 + t];
                aH[mi][2] = AsH[(ar + g    )*36 + kk*8 + t + 4];
                aH[mi][3] = AsH[(ar + g + 8)*36 + kk*8 + t + 4];
                aL[mi][0] = AsL[(ar + g    )*36 + kk*8 + t];
                aL[mi][1] = AsL[(ar + g + 8)*36 + kk*8 + t];
                aL[mi][2] = AsL[(ar + g    )*36 + kk*8 + t + 4];
                aL[mi][3] = AsL[(ar + g + 8)*36 + kk*8 + t + 4];
            }
            #pragma unroll
            for (int nt = 0; nt < 4; nt++) {
                unsigned bH[2];
                int nc = wn*32 + nt*8 + g;
                bH[0] = WsH[(kk*8 + t    )*72 + nc];
                bH[1] = WsH[(kk*8 + t + 4)*72 + nc];
                #pragma unroll
                for (int mi = 0; mi < 2; mi++) {
                    mma_tf32(acc[mi][nt], aL[mi], bH);
                    mma_tf32(acc[mi][nt], aH[mi], bH);
                }
            }
        }
        __syncthreads();
    }
    #pragma unroll
    for (int mi = 0; mi < 2; mi++) {
        #pragma unroll
        for (int nt = 0; nt < 4; nt++) {
            int col = n0 + wn*32 + nt*8 + t*2;
            int r0  = m0 + wm*32 + mi*16 + g;
            float b0v = bias[col], b1v = bias[col + 1];
            float c00 = acc[mi][nt][0] + b0v, c01 = acc[mi][nt][1] + b1v;
            float c10 = acc[mi][nt][2] + b0v, c11 = acc[mi][nt][3] + b1v;
            if (RELU) {
                c00 = fmaxf(c00, 0.f); c01 = fmaxf(c01, 0.f);
                c10 = fmaxf(c10, 0.f); c11 = fmaxf(c11, 0.f);
            }
            C[(size_t)r0*N + col]     = c00; C[(size_t)r0*N + col + 1]     = c01;
            C[(size_t)(r0+8)*N + col] = c10; C[(size_t)(r0+8)*N + col + 1] = c11;
        }
    }
}

// ------- fused QKV: 2-term split, load h tile once, 3 weight banks ---------
// block 64x64, 8 warps 4x2 (warp tile 16x32), grid (HD/64=2, BL/64)
__global__ void __launch_bounds__(256) k_qkv(
        const float* __restrict__ A,
        const float* __restrict__ qw, const float* __restrict__ qb2,
        const float* __restrict__ kw, const float* __restrict__ kb2,
        const float* __restrict__ vw, const float* __restrict__ vb2,
        float* __restrict__ q, float* __restrict__ k, float* __restrict__ v) {
    __shared__ unsigned AsH[64*36], AsL[64*36];
    __shared__ unsigned WsH[3*32*72];
    int tid = threadIdx.x;
    int w = tid >> 5, lane = tid & 31, g = lane >> 2, t = lane & 3;
    int wm = w >> 1, wn = w & 1;
    int m0 = blockIdx.y * 64, n0 = blockIdx.x * 64;
    const float* Wp[3] = {qw, kw, vw};
    float acc[3][4][4] = {};
    for (int k0 = 0; k0 < DD; k0 += 32) {
        for (int i = tid; i < 512; i += 256) {
            int r = i >> 3, c4 = (i & 7) * 4;
            float4 av = *(const float4*)&A[(size_t)(m0 + r) * DD + k0 + c4];
            uint4 hi, lo; split4(av, hi, lo);
            *(uint4*)&AsH[r*36 + c4] = hi;
            *(uint4*)&AsL[r*36 + c4] = lo;
        }
        for (int i = tid; i < 1536; i += 256) {
            int o = i >> 9, j = i & 511;
            int kk = j >> 4, c4 = (j & 15) * 4;
            float4 wv = *(const float4*)&Wp[o][(size_t)(k0 + kk) * HD + n0 + c4];
            *(uint4*)&WsH[o*2304 + kk*72 + c4] = tf4(wv);
        }
        __syncthreads();
        #pragma unroll
        for (int kk = 0; kk < 4; kk++) {
            unsigned aH[4], aL[4];
            int ar = wm*16;
            aH[0] = AsH[(ar + g    )*36 + kk*8 + t];
            aH[1] = AsH[(ar + g + 8)*36 + kk*8 + t];
            aH[2] = AsH[(ar + g    )*36 + kk*8 + t + 4];
            aH[3] = AsH[(ar + g + 8)*36 + kk*8 + t + 4];
            aL[0] = AsL[(ar + g    )*36 + kk*8 + t];
            aL[1] = AsL[(ar + g + 8)*36 + kk*8 + t];
            aL[2] = AsL[(ar + g    )*36 + kk*8 + t + 4];
            aL[3] = AsL[(ar + g + 8)*36 + kk*8 + t + 4];
            #pragma unroll
            for (int o = 0; o < 3; o++) {
                #pragma unroll
                for (int nt = 0; nt < 4; nt++) {
                    unsigned bH[2];
                    int nc = o*2304 + wn*32 + nt*8 + g;
                    bH[0] = WsH[(kk*8 + t    )*72 + nc];
                    bH[1] = WsH[(kk*8 + t + 4)*72 + nc];
                    mma_tf32(acc[o][nt], aL, bH);
                    mma_tf32(acc[o][nt], aH, bH);
                }
            }
        }
        __syncthreads();
    }
    float* Co[3] = {q, k, v};
    const float* Bo[3] = {qb2, kb2, vb2};
    #pragma unroll
    for (int o = 0; o < 3; o++) {
        #pragma unroll
        for (int nt = 0; nt < 4; nt++) {
            int col = n0 + wn*32 + nt*8 + t*2;
            int r0  = m0 + wm*16 + g;
            float b0v = Bo[o][col], b1v = Bo[o][col + 1];
            Co[o][(size_t)r0*HD + col]       = acc[o][nt][0] + b0v;
            Co[o][(size_t)r0*HD + col + 1]   = acc[o][nt][1] + b1v;
            Co[o][(size_t)(r0+8)*HD + col]   = acc[o][nt][2] + b0v;
            Co[o][(size_t)(r0+8)*HD + col+1] = acc[o][nt][3] + b1v;
        }
    }
}

// ------- merged flash attention: stats + P-write + P@V, one kernel ---------
// grid (16 row-tiles of 128, 32 bh), 256 thr. Warp w owns rows w*16..w*16+15.
// Q frags in registers; P relayout via warp shuffles. K/V staged 128 rows.
__global__ void __launch_bounds__(256) k_attn2(
        const float* __restrict__ Q, const float* __restrict__ Kv,
        const float* __restrict__ V, float* __restrict__ P,
        float* __restrict__ O) {
    __shared__ unsigned Ks[128*36];
    __shared__ unsigned Vs[128*40];
    int tid = threadIdx.x;
    int w = tid >> 5, lane = tid & 31, g = lane >> 2, t = lane & 3;
    int l0 = blockIdx.x * 128;
    int bh = blockIdx.y, b = bh >> 2, hh = bh & 3;
    const float* qb = Q  + (size_t)b * LL * HD + hh * DKK;
    const float* kb = Kv + (size_t)b * LL * HD + hh * DKK;
    const float* vb = V  + (size_t)b * LL * HD + hh * DKK;

    int row0 = l0 + w*16 + g;
    int row1 = row0 + 8;
    bool r0ok = row0 < LL, r1ok = row1 < LL;

    unsigned qf[4][4];
    #pragma unroll
    for (int kk = 0; kk < 4; kk++) {
        qf[kk][0] = f2tf(r0ok ? qb[(size_t)row0*HD + kk*8 + t]     : 0.f);
        qf[kk][1] = f2tf(r1ok ? qb[(size_t)row1*HD + kk*8 + t]     : 0.f);
        qf[kk][2] = f2tf(r0ok ? qb[(size_t)row0*HD + kk*8 + t + 4] : 0.f);
        qf[kk][3] = f2tf(r1ok ? qb[(size_t)row1*HD + kk*8 + t + 4] : 0.f);
    }
    const float S2 = SCALE * LOG2E;

    // ---- phase 0: per-row (max, sumexp2) online --------------------------
    float m0 = -1e30f, z0 = 0.f, m1 = -1e30f, z1 = 0.f;
    for (int s0 = 0; s0 < LL; s0 += 128) {
        __syncthreads();
        for (int i = tid; i < 1024; i += 256) {
            int r = i >> 3, c4 = (i & 7) * 4;
            int sr = s0 + r;
            uint4 kv = {0u,0u,0u,0u};
            if (sr < LL) kv = tf4(*(const float4*)&kb[(size_t)sr * HD + c4]);
            *(uint4*)&Ks[r*36 + c4] = kv;
        }
        __syncthreads();
        #pragma unroll
        for (int hf2 = 0; hf2 < 2; hf2++) {
            int sb = s0 + hf2*64;
            float acc[8][4] = {};
            #pragma unroll
            for (int kk = 0; kk < 4; kk++) {
                #pragma unroll
                for (int ni = 0; ni < 8; ni++) {
                    unsigned b2[2];
                    b2[0] = Ks[(hf2*64 + ni*8 + g)*36 + kk*8 + t];
                    b2[1] = Ks[(hf2*64 + ni*8 + g)*36 + kk*8 + t + 4];
                    mma_tf32(acc[ni], qf[kk], b2);
                }
            }
            float lm0 = -1e30f, lm1 = -1e30f;
            #pragma unroll
            for (int ni = 0; ni < 8; ni++) {
                if (sb + ni*8 < LL) {
                    acc[ni][0] *= S2; acc[ni][1] *= S2;
                    acc[ni][2] *= S2; acc[ni][3] *= S2;
                    lm0 = fmaxf(lm0, fmaxf(acc[ni][0], acc[ni][1]));
                    lm1 = fmaxf(lm1, fmaxf(acc[ni][2], acc[ni][3]));
                }
            }
            float nm0 = fmaxf(m0, lm0), nm1 = fmaxf(m1, lm1);
            z0 *= ex2(m0 - nm0); z1 *= ex2(m1 - nm1);
            m0 = nm0; m1 = nm1;
            #pragma unroll
            for (int ni = 0; ni < 8; ni++) {
                if (sb + ni*8 < LL) {
                    z0 += ex2(acc[ni][0] - m0) + ex2(acc[ni][1] - m0);
                    z1 += ex2(acc[ni][2] - m1) + ex2(acc[ni][3] - m1);
                }
            }
        }
    }
    #pragma unroll
    for (int off = 1; off <= 2; off <<= 1) {
        float om = __shfl_xor_sync(0xffffffffu, m0, off);
        float oz = __shfl_xor_sync(0xffffffffu, z0, off);
        float nm = fmaxf(m0, om);
        z0 = z0 * ex2(m0 - nm) + oz * ex2(om - nm);
        m0 = nm;
        om = __shfl_xor_sync(0xffffffffu, m1, off);
        oz = __shfl_xor_sync(0xffffffffu, z1, off);
        nm = fmaxf(m1, om);
        z1 = z1 * ex2(m1 - nm) + oz * ex2(om - nm);
        m1 = nm;
    }
    float inv0 = 1.f / z0, inv1 = 1.f / z1;

    // ---- phase 1: recompute S, write P, accumulate O = P@V ---------------
    float* Pb = P + (size_t)bh * LL * LL;
    float acc2[4][4] = {};
    int srcA = (lane & 0x1C) | (t >> 1);
    bool odd = (t & 1);
    for (int s0 = 0; s0 < LL; s0 += 128) {
        __syncthreads();
        for (int i = tid; i < 1024; i += 256) {
            int r = i >> 3, c4 = (i & 7) * 4;
            int sr = s0 + r;
            uint4 kv = {0u,0u,0u,0u}, vv = {0u,0u,0u,0u};
            if (sr < LL) {
                kv = tf4(*(const float4*)&kb[(size_t)sr * HD + c4]);
                vv = tf4(*(const float4*)&vb[(size_t)sr * HD + c4]);
            }
            *(uint4*)&Ks[r*36 + c4] = kv;
            *(uint4*)&Vs[r*40 + c4] = vv;
        }
        __syncthreads();
        #pragma unroll
        for (int hf2 = 0; hf2 < 2; hf2++) {
            int sb = s0 + hf2*64;
            float acc[8][4] = {};
            #pragma unroll
            for (int kk = 0; kk < 4; kk++) {
                #pragma unroll
                for (int ni = 0; ni < 8; ni++) {
                    unsigned b2[2];
                    b2[0] = Ks[(hf2*64 + ni*8 + g)*36 + kk*8 + t];
                    b2[1] = Ks[(hf2*64 + ni*8 + g)*36 + kk*8 + t + 4];
                    mma_tf32(acc[ni], qf[kk], b2);
                }
            }
            #pragma unroll
            for (int ni = 0; ni < 8; ni++) {
                bool cok = (sb + ni*8) < LL;
                float p0 = cok ? ex2(acc[ni][0]*S2 - m0) * inv0 : 0.f;
                float p1 = cok ? ex2(acc[ni][1]*S2 - m0) * inv0 : 0.f;
                float p2 = cok ? ex2(acc[ni][2]*S2 - m1) * inv1 : 0.f;
                float p3 = cok ? ex2(acc[ni][3]*S2 - m1) * inv1 : 0.f;
                if (cok) {
                    size_t cidx = (size_t)(sb + ni*8 + t*2);
                    if (r0ok) *(float2*)&Pb[(size_t)row0*LL + cidx] = make_float2(p0, p1);
                    if (r1ok) *(float2*)&Pb[(size_t)row1*LL + cidx] = make_float2(p2, p3);
                }
                acc[ni][0] = __uint_as_float(f2tf(p0));
                acc[ni][1] = __uint_as_float(f2tf(p1));
                acc[ni][2] = __uint_as_float(f2tf(p2));
                acc[ni][3] = __uint_as_float(f2tf(p3));
            }
            #pragma unroll
            for (int kk = 0; kk < 8; kk++) {
                float x0 = __shfl_sync(0xffffffffu, acc[kk][0], srcA);
                float x1 = __shfl_sync(0xffffffffu, acc[kk][1], srcA);
                float y0 = __shfl_sync(0xffffffffu, acc[kk][2], srcA);
                float y1 = __shfl_sync(0xffffffffu, acc[kk][3], srcA);
                float x0b = __shfl_sync(0xffffffffu, acc[kk][0], srcA + 2);
                float x1b = __shfl_sync(0xffffffffu, acc[kk][1], srcA + 2);
                float y0b = __shfl_sync(0xffffffffu, acc[kk][2], srcA + 2);
                float y1b = __shfl_sync(0xffffffffu, acc[kk][3], srcA + 2);
                unsigned a[4];
                a[0] = __float_as_uint(odd ? x1  : x0);
                a[1] = __float_as_uint(odd ? y1  : y0);
                a[2] = __float_as_uint(odd ? x1b : x0b);
                a[3] = __float_as_uint(odd ? y1b : y0b);
                #pragma unroll
                for (int ni = 0; ni < 4; ni++) {
                    unsigned b2[2];
                    b2[0] = Vs[(hf2*64 + kk*8 + t)*40 + ni*8 + g];
                    b2[1] = Vs[(hf2*64 + kk*8 + t + 4)*40 + ni*8 + g];
                    mma_tf32(acc2[ni], a, b2);
                }
            }
        }
    }
    float* ob = O + (size_t)b * LL * HD + hh * DKK;
    #pragma unroll
    for (int ni = 0; ni < 4; ni++) {
        int c0 = ni*8 + t*2;
        if (r0ok) *(float2*)&ob[(size_t)row0*HD + c0] = make_float2(acc2[ni][0], acc2[ni][1]);
        if (r1ok) *(float2*)&ob[(size_t)row1*HD + c0] = make_float2(acc2[ni][2], acc2[ni][3]);
    }
}

// ---------------- h = LayerNorm(h + add) * g + b (row of 256) --------------
__global__ void k_ln(float* __restrict__ h, const float* __restrict__ add,
                     const float* __restrict__ g, const float* __restrict__ bta) {
    int row  = blockIdx.x * 8 + (threadIdx.x >> 5);
    int lane = threadIdx.x & 31;
    float* hp = h + (size_t)row * DD;
    const float* ap = add + (size_t)row * DD;
    float v[8]; float s = 0.f;
    #pragma unroll
    for (int i = 0; i < 8; i++) {
        v[i] = hp[lane + 32*i] + ap[lane + 32*i];
        s += v[i];
    }
    #pragma unroll
    for (int o = 16; o > 0; o >>= 1) s += __shfl_xor_sync(0xffffffffu, s, o);
    float mean = s * (1.f / DD);
    float var = 0.f;
    #pragma unroll
    for (int i = 0; i < 8; i++) { float d = v[i] - mean; var = fmaf(d, d, var); }
    #pragma unroll
    for (int o = 16; o > 0; o >>= 1) var += __shfl_xor_sync(0xffffffffu, var, o);
    var *= (1.f / DD);
    float r = rsqrtf(var + EPSV);
    #pragma unroll
    for (int i = 0; i < 8; i++) {
        int d = lane + 32*i;
        hp[d] = (v[i] - mean) * r * g[d] + bta[d];
    }
}

// ---------------- final head: out = A(relu'd) @ o2w(256x2) + o2b -----------
__global__ void k_out2(const float* __restrict__ A, const float* __restrict__ w,
                       const float* __restrict__ b, float* __restrict__ out) {
    int row  = blockIdx.x * 8 + (threadIdx.x >> 5);
    int lane = threadIdx.x & 31;
    const float* ap = A + (size_t)row * DD;
    float s0 = 0.f, s1 = 0.f;
    #pragma unroll
    for (int i = 0; i < 8; i++) {
        int d = lane + 32*i;
        float a = ap[d];
        s0 = fmaf(a, w[d*2],     s0);
        s1 = fmaf(a, w[d*2 + 1], s1);
    }
    #pragma unroll
    for (int o = 16; o > 0; o >>= 1) {
        s0 += __shfl_xor_sync(0xffffffffu, s0, o);
        s1 += __shfl_xor_sync(0xffffffffu, s1, o);
    }
    if (lane == 0) {
        out[(size_t)row*2]     = s0 + b[0];
        out[(size_t)row*2 + 1] = s1 + b[1];
    }
}

// ---------------------------------------------------------------------------
extern "C" void kernel_launch(void* const* d_in, const int* in_sizes, int n_in,
                              void* d_out, int out_size) {
    const float* x    = (const float*)d_in[0];
    const float* in_w = (const float*)d_in[1];
    const float* in_b = (const float*)d_in[2];
    const float* qw   = (const float*)d_in[3];
    const float* qb   = (const float*)d_in[4];
    const float* kw   = (const float*)d_in[5];
    const float* kb   = (const float*)d_in[6];
    const float* vw   = (const float*)d_in[7];
    const float* vb   = (const float*)d_in[8];
    const float* ow   = (const float*)d_in[9];
    const float* ob   = (const float*)d_in[10];
    const float* f1w  = (const float*)d_in[11];
    const float* f1b  = (const float*)d_in[12];
    const float* f2w  = (const float*)d_in[13];
    const float* f2b  = (const float*)d_in[14];
    const float* n1g  = (const float*)d_in[15];
    const float* n1b  = (const float*)d_in[16];
    const float* n2g  = (const float*)d_in[17];
    const float* n2b  = (const float*)d_in[18];
    const float* o1w  = (const float*)d_in[19];
    const float* o1b  = (const float*)d_in[20];
    const float* o2w  = (const float*)d_in[21];
    const float* o2b  = (const float*)d_in[22];

    float* out  = (float*)d_out;
    float* attn = out + (size_t)BB * LL * 2;   // attns region: (NL,B,H,L,L)

    float *h, *q, *k, *v, *o, *t1, *ff;
    cudaGetSymbolAddress((void**)&h,  g_h);
    cudaGetSymbolAddress((void**)&q,  g_q);
    cudaGetSymbolAddress((void**)&k,  g_k);
    cudaGetSymbolAddress((void**)&v,  g_v);
    cudaGetSymbolAddress((void**)&o,  g_o);
    cudaGetSymbolAddress((void**)&t1, g_t1);
    cudaGetSymbolAddress((void**)&ff, g_ff);

    // input projection
    k_input<<<(BL*DD)/256, 256>>>(x, in_w, in_b, h);

    const int RT = (LL + 127) / 128;   // 16 row tiles

    for (int i = 0; i < NLL; i++) {
        const float* qwi = qw + (size_t)i * DD * HD;
        const float* qbi = qb + (size_t)i * HD;
        const float* kwi = kw + (size_t)i * DD * HD;
        const float* kbi = kb + (size_t)i * HD;
        const float* vwi = vw + (size_t)i * DD * HD;
        const float* vbi = vb + (size_t)i * HD;
        const float* owi = ow + (size_t)i * HD * DD;
        const float* obi = ob + (size_t)i * DD;
        const float* f1wi = f1w + (size_t)i * DD * FCC;
        const float* f1bi = f1b + (size_t)i * FCC;
        const float* f2wi = f2w + (size_t)i * FCC * DD;
        const float* f2bi = f2b + (size_t)i * DD;

        // fused Q,K,V projection
        k_qkv<<<dim3(HD/64, BL/64), 256>>>(
            h, qwi, qbi, kwi, kbi, vwi, vbi, q, k, v);

        // merged flash attention (stats + P + O)
        float* Si = attn + (size_t)i * BHH * LL * LL;
        k_attn2<<<dim3(RT, BHH), 256>>>(q, k, v, Si, o);

        // output projection + residual LN
        k_gemm_mma<false><<<dim3(DD/64, BL/128), 256>>>(o, owi, obi, t1, BL, DD, HD);
        k_ln<<<BL/8, 256>>>(h, t1, n1g + (size_t)i*DD, n1b + (size_t)i*DD);

        // FFN + residual LN
        k_gemm_mma<true ><<<dim3(FCC/64, BL/128), 256>>>(h, f1wi, f1bi, ff, BL, FCC, DD);
        k_gemm_mma<false><<<dim3(DD/64, BL/128), 256>>>(ff, f2wi, f2bi, t1, BL, DD, FCC);
        k_ln<<<BL/8, 256>>>(h, t1, n2g + (size_t)i*DD, n2b + (size_t)i*DD);
    }

    // final MLP head
    k_gemm_mma<true><<<dim3(DD/64, BL/128), 256>>>(h, o1w, o1b, t1, BL, DD, DD);
    k_out2<<<BL/8, 256>>>(t1, o2w, o2b, out);
}

// round 8
// speedup vs baseline: 4.1831x; 1.1169x over previous
#include <cuda_runtime.h>
#include <math.h>

#define BB   8
#define LL   2016
#define HH   4
#define DKK  32
#define DD   256
#define FCC  64
#define NLL  3
#define BL   (BB*LL)      // 16128
#define HD   (HH*DKK)     // 128
#define BHH  (BB*HH)      // 32
#define SCALE 0.0625f     // 1/sqrt(256)
#define EPSV  1e-5f
#define LOG2E 1.4426950408889634f

// ---------------- scratch (device globals: no allocation allowed) ----------
__device__ float g_h [BL*DD];
__device__ float g_q [BL*HD];
__device__ float g_k [BL*HD];
__device__ float g_v [BL*HD];
__device__ float g_o [BL*HD];
__device__ float g_t1[BL*DD];
__device__ float g_ff[BL*FCC];

// ---------------- tf32 helpers --------------------------------------------
__device__ __forceinline__ unsigned f2tf(float f) {
    unsigned u;
    asm("cvt.rna.tf32.f32 %0, %1;" : "=r"(u) : "f"(f));
    return u;
}

__device__ __forceinline__ float ex2(float x) {
    float r;
    asm("ex2.approx.f32 %0, %1;" : "=f"(r) : "f"(x));
    return r;
}

__device__ __forceinline__ void mma_tf32(float* d, const unsigned* a, const unsigned* b) {
    asm("mma.sync.aligned.m16n8k8.row.col.f32.tf32.tf32.f32 "
        "{%0,%1,%2,%3},{%4,%5,%6,%7},{%8,%9},{%0,%1,%2,%3};"
        : "+f"(d[0]), "+f"(d[1]), "+f"(d[2]), "+f"(d[3])
        : "r"(a[0]), "r"(a[1]), "r"(a[2]), "r"(a[3]),
          "r"(b[0]), "r"(b[1]));
}

__device__ __forceinline__ void split4(float4 f, uint4& hi, uint4& lo) {
    hi.x = f2tf(f.x); hi.y = f2tf(f.y); hi.z = f2tf(f.z); hi.w = f2tf(f.w);
    lo.x = f2tf(f.x - __uint_as_float(hi.x));
    lo.y = f2tf(f.y - __uint_as_float(hi.y));
    lo.z = f2tf(f.z - __uint_as_float(hi.z));
    lo.w = f2tf(f.w - __uint_as_float(hi.w));
}

__device__ __forceinline__ uint4 tf4(float4 f) {
    uint4 u;
    u.x = f2tf(f.x); u.y = f2tf(f.y); u.z = f2tf(f.z); u.w = f2tf(f.w);
    return u;
}

// ---------------- input projection: h = x @ in_w + in_b (K=2) -------------
__global__ void k_input(const float* __restrict__ x, const float* __restrict__ w,
                        const float* __restrict__ b, float* __restrict__ h) {
    int idx = blockIdx.x * 256 + threadIdx.x;
    int d = idx & (DD - 1);
    int r = idx >> 8;
    h[idx] = fmaf(x[2*r], w[d], fmaf(x[2*r+1], w[DD + d], b[d]));
}

// ------- 2-term split-tf32 GEMM, register-prefetch double-buffered ---------
// block tile 128x64, 8 warps 4x2, warp tile 32x32. M%128==0, N%64==0, K%32==0
template<bool RELU>
__global__ void __launch_bounds__(256) k_gemm_mma(
        const float* __restrict__ A, const float* __restrict__ W,
        const float* __restrict__ bias, float* __restrict__ C,
        int M, int N, int K) {
    __shared__ unsigned AsH[128*36], AsL[128*36];
    __shared__ unsigned WsH[32*72];
    int tid = threadIdx.x;
    int w = tid >> 5, lane = tid & 31, g = lane >> 2, t = lane & 3;
    int wm = w >> 1, wn = w & 1;
    int m0 = blockIdx.y * 128, n0 = blockIdx.x * 64;
    float acc[2][4][4] = {};
    float4 pA[4], pW[2];
    // prologue: load k-chunk 0 into registers
    #pragma unroll
    for (int j = 0; j < 4; j++) {
        int i = tid + j*256; int r = i >> 3, c4 = (i & 7)*4;
        pA[j] = *(const float4*)&A[(size_t)(m0 + r) * K + c4];
    }
    #pragma unroll
    for (int j = 0; j < 2; j++) {
        int i = tid + j*256; int kk = i >> 4, c4 = (i & 15)*4;
        pW[j] = *(const float4*)&W[(size_t)kk * N + n0 + c4];
    }
    for (int k0 = 0; k0 < K; k0 += 32) {
        #pragma unroll
        for (int j = 0; j < 4; j++) {
            int i = tid + j*256; int r = i >> 3, c4 = (i & 7)*4;
            uint4 hi, lo; split4(pA[j], hi, lo);
            *(uint4*)&AsH[r*36 + c4] = hi;
            *(uint4*)&AsL[r*36 + c4] = lo;
        }
        #pragma unroll
        for (int j = 0; j < 2; j++) {
            int i = tid + j*256; int kk = i >> 4, c4 = (i & 15)*4;
            *(uint4*)&WsH[kk*72 + c4] = tf4(pW[j]);
        }
        __syncthreads();
        if (k0 + 32 < K) {   // prefetch next chunk (overlaps compute)
            #pragma unroll
            for (int j = 0; j < 4; j++) {
                int i = tid + j*256; int r = i >> 3, c4 = (i & 7)*4;
                pA[j] = *(const float4*)&A[(size_t)(m0 + r) * K + k0 + 32 + c4];
            }
            #pragma unroll
            for (int j = 0; j < 2; j++) {
                int i = tid + j*256; int kk = i >> 4, c4 = (i & 15)*4;
                pW[j] = *(const float4*)&W[(size_t)(k0 + 32 + kk) * N + n0 + c4];
            }
        }
        #pragma unroll
        for (int kk = 0; kk < 4; kk++) {
            unsigned aH[2][4], aL[2][4];
            #pragma unroll
            for (int mi = 0; mi < 2; mi++) {
                int ar = wm*32 + mi*16;
                aH[mi][0] = AsH[(ar + g    )*36 + kk*8 + t];
                aH[mi][1] = AsH[(ar + g + 8)*36 + kk*8 + t];
                aH[mi][2] = AsH[(ar + g    )*36 + kk*8 + t + 4];
                aH[mi][3] = AsH[(ar + g + 8)*36 + kk*8 + t + 4];
                aL[mi][0] = AsL[(ar + g    )*36 + kk*8 + t];
                aL[mi][1] = AsL[(ar + g + 8)*36 + kk*8 + t];
                aL[mi][2] = AsL[(ar + g    )*36 + kk*8 + t + 4];
                aL[mi][3] = AsL[(ar + g + 8)*36 + kk*8 + t + 4];
            }
            #pragma unroll
            for (int nt = 0; nt < 4; nt++) {
                unsigned bH[2];
                int nc = wn*32 + nt*8 + g;
                bH[0] = WsH[(kk*8 + t    )*72 + nc];
                bH[1] = WsH[(kk*8 + t + 4)*72 + nc];
                #pragma unroll
                for (int mi = 0; mi < 2; mi++) {
                    mma_tf32(acc[mi][nt], aL[mi], bH);
                    mma_tf32(acc[mi][nt], aH[mi], bH);
                }
            }
        }
        __syncthreads();
    }
    #pragma unroll
    for (int mi = 0; mi < 2; mi++) {
        #pragma unroll
        for (int nt = 0; nt < 4; nt++) {
            int col = n0 + wn*32 + nt*8 + t*2;
            int r0  = m0 + wm*32 + mi*16 + g;
            float b0v = bias[col], b1v = bias[col + 1];
            float c00 = acc[mi][nt][0] + b0v, c01 = acc[mi][nt][1] + b1v;
            float c10 = acc[mi][nt][2] + b0v, c11 = acc[mi][nt][3] + b1v;
            if (RELU) {
                c00 = fmaxf(c00, 0.f); c01 = fmaxf(c01, 0.f);
                c10 = fmaxf(c10, 0.f); c11 = fmaxf(c11, 0.f);
            }
            C[(size_t)r0*N + col]     = c00; C[(size_t)r0*N + col + 1]     = c01;
            C[(size_t)(r0+8)*N + col] = c10; C[(size_t)(r0+8)*N + col + 1] = c11;
        }
    }
}

// ------- fused QKV: 2-term split, register-prefetch double-buffered --------
// block 64x64, 8 warps 4x2 (warp tile 16x32), grid (HD/64=2, BL/64)
__global__ void __launch_bounds__(256) k_qkv(
        const float* __restrict__ A,
        const float* __restrict__ qw, const float* __restrict__ qb2,
        const float* __restrict__ kw, const float* __restrict__ kb2,
        const float* __restrict__ vw, const float* __restrict__ vb2,
        float* __restrict__ q, float* __restrict__ k, float* __restrict__ v) {
    __shared__ unsigned AsH[64*36], AsL[64*36];
    __shared__ unsigned WsH[3*32*72];
    int tid = threadIdx.x;
    int w = tid >> 5, lane = tid & 31, g = lane >> 2, t = lane & 3;
    int wm = w >> 1, wn = w & 1;
    int m0 = blockIdx.y * 64, n0 = blockIdx.x * 64;
    const float* Wp[3] = {qw, kw, vw};
    float acc[3][4][4] = {};
    float4 pA[2], pW[6];
    #pragma unroll
    for (int j = 0; j < 2; j++) {
        int i = tid + j*256; int r = i >> 3, c4 = (i & 7)*4;
        pA[j] = *(const float4*)&A[(size_t)(m0 + r) * DD + c4];
    }
    #pragma unroll
    for (int j = 0; j < 6; j++) {
        int i = tid + j*256; int o = i >> 9, jj = i & 511;
        int kk = jj >> 4, c4 = (jj & 15)*4;
        pW[j] = *(const float4*)&Wp[o][(size_t)kk * HD + n0 + c4];
    }
    for (int k0 = 0; k0 < DD; k0 += 32) {
        #pragma unroll
        for (int j = 0; j < 2; j++) {
            int i = tid + j*256; int r = i >> 3, c4 = (i & 7)*4;
            uint4 hi, lo; split4(pA[j], hi, lo);
            *(uint4*)&AsH[r*36 + c4] = hi;
            *(uint4*)&AsL[r*36 + c4] = lo;
        }
        #pragma unroll
        for (int j = 0; j < 6; j++) {
            int i = tid + j*256; int o = i >> 9, jj = i & 511;
            int kk = jj >> 4, c4 = (jj & 15)*4;
            *(uint4*)&WsH[o*2304 + kk*72 + c4] = tf4(pW[j]);
        }
        __syncthreads();
        if (k0 + 32 < DD) {
            #pragma unroll
            for (int j = 0; j < 2; j++) {
                int i = tid + j*256; int r = i >> 3, c4 = (i & 7)*4;
                pA[j] = *(const float4*)&A[(size_t)(m0 + r) * DD + k0 + 32 + c4];
            }
            #pragma unroll
            for (int j = 0; j < 6; j++) {
                int i = tid + j*256; int o = i >> 9, jj = i & 511;
                int kk = jj >> 4, c4 = (jj & 15)*4;
                pW[j] = *(const float4*)&Wp[o][(size_t)(k0 + 32 + kk) * HD + n0 + c4];
            }
        }
        #pragma unroll
        for (int kk = 0; kk < 4; kk++) {
            unsigned aH[4], aL[4];
            int ar = wm*16;
            aH[0] = AsH[(ar + g    )*36 + kk*8 + t];
            aH[1] = AsH[(ar + g + 8)*36 + kk*8 + t];
            aH[2] = AsH[(ar + g    )*36 + kk*8 + t + 4];
            aH[3] = AsH[(ar + g + 8)*36 + kk*8 + t + 4];
            aL[0] = AsL[(ar + g    )*36 + kk*8 + t];
            aL[1] = AsL[(ar + g + 8)*36 + kk*8 + t];
            aL[2] = AsL[(ar + g    )*36 + kk*8 + t + 4];
            aL[3] = AsL[(ar + g + 8)*36 + kk*8 + t + 4];
            #pragma unroll
            for (int o = 0; o < 3; o++) {
                #pragma unroll
                for (int nt = 0; nt < 4; nt++) {
                    unsigned bH[2];
                    int nc = o*2304 + wn*32 + nt*8 + g;
                    bH[0] = WsH[(kk*8 + t    )*72 + nc];
                    bH[1] = WsH[(kk*8 + t + 4)*72 + nc];
                    mma_tf32(acc[o][nt], aL, bH);
                    mma_tf32(acc[o][nt], aH, bH);
                }
            }
        }
        __syncthreads();
    }
    float* Co[3] = {q, k, v};
    const float* Bo[3] = {qb2, kb2, vb2};
    #pragma unroll
    for (int o = 0; o < 3; o++) {
        #pragma unroll
        for (int nt = 0; nt < 4; nt++) {
            int col = n0 + wn*32 + nt*8 + t*2;
            int r0  = m0 + wm*16 + g;
            float b0v = Bo[o][col], b1v = Bo[o][col + 1];
            Co[o][(size_t)r0*HD + col]       = acc[o][nt][0] + b0v;
            Co[o][(size_t)r0*HD + col + 1]   = acc[o][nt][1] + b1v;
            Co[o][(size_t)(r0+8)*HD + col]   = acc[o][nt][2] + b0v;
            Co[o][(size_t)(r0+8)*HD + col+1] = acc[o][nt][3] + b1v;
        }
    }
}

// ------- merged flash attention (no-max softmax: scores are bounded) -------
// grid (16 row-tiles of 128, 32 bh), 256 thr. Warp w owns rows w*16..w*16+15.
__global__ void __launch_bounds__(256) k_attn2(
        const float* __restrict__ Q, const float* __restrict__ Kv,
        const float* __restrict__ V, float* __restrict__ P,
        float* __restrict__ O) {
    __shared__ unsigned Ks[128*36];
    __shared__ unsigned Vs[128*40];
    int tid = threadIdx.x;
    int w = tid >> 5, lane = tid & 31, g = lane >> 2, t = lane & 3;
    int l0 = blockIdx.x * 128;
    int bh = blockIdx.y, b = bh >> 2, hh = bh & 3;
    const float* qb = Q  + (size_t)b * LL * HD + hh * DKK;
    const float* kb = Kv + (size_t)b * LL * HD + hh * DKK;
    const float* vb = V  + (size_t)b * LL * HD + hh * DKK;

    int row0 = l0 + w*16 + g;
    int row1 = row0 + 8;
    bool r0ok = row0 < LL, r1ok = row1 < LL;

    unsigned qf[4][4];
    #pragma unroll
    for (int kk = 0; kk < 4; kk++) {
        qf[kk][0] = f2tf(r0ok ? qb[(size_t)row0*HD + kk*8 + t]     : 0.f);
        qf[kk][1] = f2tf(r1ok ? qb[(size_t)row1*HD + kk*8 + t]     : 0.f);
        qf[kk][2] = f2tf(r0ok ? qb[(size_t)row0*HD + kk*8 + t + 4] : 0.f);
        qf[kk][3] = f2tf(r1ok ? qb[(size_t)row1*HD + kk*8 + t + 4] : 0.f);
    }
    const float S2 = SCALE * LOG2E;

    // ---- phase 0: per-row z = sum exp2(s*S2) (no max: bounded scores) ----
    float z0 = 0.f, z1 = 0.f;
    for (int s0 = 0; s0 < LL; s0 += 128) {
        __syncthreads();
        for (int i = tid; i < 1024; i += 256) {
            int r = i >> 3, c4 = (i & 7) * 4;
            int sr = s0 + r;
            uint4 kv = {0u,0u,0u,0u};
            if (sr < LL) kv = tf4(*(const float4*)&kb[(size_t)sr * HD + c4]);
            *(uint4*)&Ks[r*36 + c4] = kv;
        }
        __syncthreads();
        #pragma unroll
        for (int hf2 = 0; hf2 < 2; hf2++) {
            int sb = s0 + hf2*64;
            float acc[8][4] = {};
            #pragma unroll
            for (int kk = 0; kk < 4; kk++) {
                #pragma unroll
                for (int ni = 0; ni < 8; ni++) {
                    unsigned b2[2];
                    b2[0] = Ks[(hf2*64 + ni*8 + g)*36 + kk*8 + t];
                    b2[1] = Ks[(hf2*64 + ni*8 + g)*36 + kk*8 + t + 4];
                    mma_tf32(acc[ni], qf[kk], b2);
                }
            }
            #pragma unroll
            for (int ni = 0; ni < 8; ni++) {
                if (sb + ni*8 < LL) {
                    z0 += ex2(acc[ni][0]*S2) + ex2(acc[ni][1]*S2);
                    z1 += ex2(acc[ni][2]*S2) + ex2(acc[ni][3]*S2);
                }
            }
        }
    }
    z0 += __shfl_xor_sync(0xffffffffu, z0, 1);
    z0 += __shfl_xor_sync(0xffffffffu, z0, 2);
    z1 += __shfl_xor_sync(0xffffffffu, z1, 1);
    z1 += __shfl_xor_sync(0xffffffffu, z1, 2);
    float inv0 = 1.f / z0, inv1 = 1.f / z1;

    // ---- phase 1: recompute S, write P, accumulate O = P@V ---------------
    float* Pb = P + (size_t)bh * LL * LL;
    float acc2[4][4] = {};
    int srcA = (lane & 0x1C) | (t >> 1);
    bool odd = (t & 1);
    for (int s0 = 0; s0 < LL; s0 += 128) {
        __syncthreads();
        for (int i = tid; i < 1024; i += 256) {
            int r = i >> 3, c4 = (i & 7) * 4;
            int sr = s0 + r;
            uint4 kv = {0u,0u,0u,0u}, vv = {0u,0u,0u,0u};
            if (sr < LL) {
                kv = tf4(*(const float4*)&kb[(size_t)sr * HD + c4]);
                vv = tf4(*(const float4*)&vb[(size_t)sr * HD + c4]);
            }
            *(uint4*)&Ks[r*36 + c4] = kv;
            *(uint4*)&Vs[r*40 + c4] = vv;
        }
        __syncthreads();
        #pragma unroll
        for (int hf2 = 0; hf2 < 2; hf2++) {
            int sb = s0 + hf2*64;
            float acc[8][4] = {};
            #pragma unroll
            for (int kk = 0; kk < 4; kk++) {
                #pragma unroll
                for (int ni = 0; ni < 8; ni++) {
                    unsigned b2[2];
                    b2[0] = Ks[(hf2*64 + ni*8 + g)*36 + kk*8 + t];
                    b2[1] = Ks[(hf2*64 + ni*8 + g)*36 + kk*8 + t + 4];
                    mma_tf32(acc[ni], qf[kk], b2);
                }
            }
            #pragma unroll
            for (int ni = 0; ni < 8; ni++) {
                bool cok = (sb + ni*8) < LL;
                float p0 = cok ? ex2(acc[ni][0]*S2) * inv0 : 0.f;
                float p1 = cok ? ex2(acc[ni][1]*S2) * inv0 : 0.f;
                float p2 = cok ? ex2(acc[ni][2]*S2) * inv1 : 0.f;
                float p3 = cok ? ex2(acc[ni][3]*S2) * inv1 : 0.f;
                if (cok) {
                    size_t cidx = (size_t)(sb + ni*8 + t*2);
                    if (r0ok) *(float2*)&Pb[(size_t)row0*LL + cidx] = make_float2(p0, p1);
                    if (r1ok) *(float2*)&Pb[(size_t)row1*LL + cidx] = make_float2(p2, p3);
                }
                acc[ni][0] = __uint_as_float(f2tf(p0));
                acc[ni][1] = __uint_as_float(f2tf(p1));
                acc[ni][2] = __uint_as_float(f2tf(p2));
                acc[ni][3] = __uint_as_float(f2tf(p3));
            }
            #pragma unroll
            for (int kk = 0; kk < 8; kk++) {
                float x0 = __shfl_sync(0xffffffffu, acc[kk][0], srcA);
                float x1 = __shfl_sync(0xffffffffu, acc[kk][1], srcA);
                float y0 = __shfl_sync(0xffffffffu, acc[kk][2], srcA);
                float y1 = __shfl_sync(0xffffffffu, acc[kk][3], srcA);
                float x0b = __shfl_sync(0xffffffffu, acc[kk][0], srcA + 2);
                float x1b = __shfl_sync(0xffffffffu, acc[kk][1], srcA + 2);
                float y0b = __shfl_sync(0xffffffffu, acc[kk][2], srcA + 2);
                float y1b = __shfl_sync(0xffffffffu, acc[kk][3], srcA + 2);
                unsigned a[4];
                a[0] = __float_as_uint(odd ? x1  : x0);
                a[1] = __float_as_uint(odd ? y1  : y0);
                a[2] = __float_as_uint(odd ? x1b : x0b);
                a[3] = __float_as_uint(odd ? y1b : y0b);
                #pragma unroll
                for (int ni = 0; ni < 4; ni++) {
                    unsigned b2[2];
                    b2[0] = Vs[(hf2*64 + kk*8 + t)*40 + ni*8 + g];
                    b2[1] = Vs[(hf2*64 + kk*8 + t + 4)*40 + ni*8 + g];
                    mma_tf32(acc2[ni], a, b2);
                }
            }
        }
    }
    float* ob = O + (size_t)b * LL * HD + hh * DKK;
    #pragma unroll
    for (int ni = 0; ni < 4; ni++) {
        int c0 = ni*8 + t*2;
        if (r0ok) *(float2*)&ob[(size_t)row0*HD + c0] = make_float2(acc2[ni][0], acc2[ni][1]);
        if (r1ok) *(float2*)&ob[(size_t)row1*HD + c0] = make_float2(acc2[ni][2], acc2[ni][3]);
    }
}

// ---------------- h = LayerNorm(h + add) * g + b (row of 256, float4) ------
__global__ void k_ln(float* __restrict__ h, const float* __restrict__ add,
                     const float* __restrict__ g, const float* __restrict__ bta) {
    int row  = blockIdx.x * 8 + (threadIdx.x >> 5);
    int lane = threadIdx.x & 31;
    float* hp = h + (size_t)row * DD;
    const float* ap = add + (size_t)row * DD;
    float4 v[2]; float s = 0.f;
    #pragma unroll
    for (int i = 0; i < 2; i++) {
        int d = lane*4 + i*128;
        float4 a = *(const float4*)&hp[d];
        float4 c = *(const float4*)&ap[d];
        v[i] = make_float4(a.x + c.x, a.y + c.y, a.z + c.z, a.w + c.w);
        s += v[i].x + v[i].y + v[i].z + v[i].w;
    }
    #pragma unroll
    for (int o = 16; o > 0; o >>= 1) s += __shfl_xor_sync(0xffffffffu, s, o);
    float mean = s * (1.f / DD);
    float var = 0.f;
    #pragma unroll
    for (int i = 0; i < 2; i++) {
        float dx = v[i].x - mean, dy = v[i].y - mean;
        float dz = v[i].z - mean, dw = v[i].w - mean;
        var = fmaf(dx, dx, var); var = fmaf(dy, dy, var);
        var = fmaf(dz, dz, var); var = fmaf(dw, dw, var);
    }
    #pragma unroll
    for (int o = 16; o > 0; o >>= 1) var += __shfl_xor_sync(0xffffffffu, var, o);
    var *= (1.f / DD);
    float r = rsqrtf(var + EPSV);
    #pragma unroll
    for (int i = 0; i < 2; i++) {
        int d = lane*4 + i*128;
        float4 gg = *(const float4*)&g[d];
        float4 bb = *(const float4*)&bta[d];
        float4 o4;
        o4.x = (v[i].x - mean) * r * gg.x + bb.x;
        o4.y = (v[i].y - mean) * r * gg.y + bb.y;
        o4.z = (v[i].z - mean) * r * gg.z + bb.z;
        o4.w = (v[i].w - mean) * r * gg.w + bb.w;
        *(float4*)&hp[d] = o4;
    }
}

// ---------------- final head: out = A(relu'd) @ o2w(256x2) + o2b -----------
__global__ void k_out2(const float* __restrict__ A, const float* __restrict__ w,
                       const float* __restrict__ b, float* __restrict__ out) {
    int row  = blockIdx.x * 8 + (threadIdx.x >> 5);
    int lane = threadIdx.x & 31;
    const float* ap = A + (size_t)row * DD;
    float s0 = 0.f, s1 = 0.f;
    #pragma unroll
    for (int i = 0; i < 8; i++) {
        int d = lane + 32*i;
        float a = ap[d];
        s0 = fmaf(a, w[d*2],     s0);
        s1 = fmaf(a, w[d*2 + 1], s1);
    }
    #pragma unroll
    for (int o = 16; o > 0; o >>= 1) {
        s0 += __shfl_xor_sync(0xffffffffu, s0, o);
        s1 += __shfl_xor_sync(0xffffffffu, s1, o);
    }
    if (lane == 0) {
        out[(size_t)row*2]     = s0 + b[0];
        out[(size_t)row*2 + 1] = s1 + b[1];
    }
}

// ---------------------------------------------------------------------------
extern "C" void kernel_launch(void* const* d_in, const int* in_sizes, int n_in,
                              void* d_out, int out_size) {
    const float* x    = (const float*)d_in[0];
    const float* in_w = (const float*)d_in[1];
    const float* in_b = (const float*)d_in[2];
    const float* qw   = (const float*)d_in[3];
    const float* qb   = (const float*)d_in[4];
    const float* kw   = (const float*)d_in[5];
    const float* kb   = (const float*)d_in[6];
    const float* vw   = (const float*)d_in[7];
    const float* vb   = (const float*)d_in[8];
    const float* ow   = (const float*)d_in[9];
    const float* ob   = (const float*)d_in[10];
    const float* f1w  = (const float*)d_in[11];
    const float* f1b  = (const float*)d_in[12];
    const float* f2w  = (const float*)d_in[13];
    const float* f2b  = (const float*)d_in[14];
    const float* n1g  = (const float*)d_in[15];
    const float* n1b  = (const float*)d_in[16];
    const float* n2g  = (const float*)d_in[17];
    const float* n2b  = (const float*)d_in[18];
    const float* o1w  = (const float*)d_in[19];
    const float* o1b  = (const float*)d_in[20];
    const float* o2w  = (const float*)d_in[21];
    const float* o2b  = (const float*)d_in[22];

    float* out  = (float*)d_out;
    float* attn = out + (size_t)BB * LL * 2;   // attns region: (NL,B,H,L,L)

    float *h, *q, *k, *v, *o, *t1, *ff;
    cudaGetSymbolAddress((void**)&h,  g_h);
    cudaGetSymbolAddress((void**)&q,  g_q);
    cudaGetSymbolAddress((void**)&k,  g_k);
    cudaGetSymbolAddress((void**)&v,  g_v);
    cudaGetSymbolAddress((void**)&o,  g_o);
    cudaGetSymbolAddress((void**)&t1, g_t1);
    cudaGetSymbolAddress((void**)&ff, g_ff);

    // input projection
    k_input<<<(BL*DD)/256, 256>>>(x, in_w, in_b, h);

    const int RT = (LL + 127) / 128;   // 16 row tiles

    for (int i = 0; i < NLL; i++) {
        const float* qwi = qw + (size_t)i * DD * HD;
        const float* qbi = qb + (size_t)i * HD;
        const float* kwi = kw + (size_t)i * DD * HD;
        const float* kbi = kb + (size_t)i * HD;
        const float* vwi = vw + (size_t)i * DD * HD;
        const float* vbi = vb + (size_t)i * HD;
        const float* owi = ow + (size_t)i * HD * DD;
        const float* obi = ob + (size_t)i * DD;
        const float* f1wi = f1w + (size_t)i * DD * FCC;
        const float* f1bi = f1b + (size_t)i * FCC;
        const float* f2wi = f2w + (size_t)i * FCC * DD;
        const float* f2bi = f2b + (size_t)i * DD;

        // fused Q,K,V projection
        k_qkv<<<dim3(HD/64, BL/64), 256>>>(
            h, qwi, qbi, kwi, kbi, vwi, vbi, q, k, v);

        // merged flash attention (stats + P + O)
        float* Si = attn + (size_t)i * BHH * LL * LL;
        k_attn2<<<dim3(RT, BHH), 256>>>(q, k, v, Si, o);

        // output projection + residual LN
        k_gemm_mma<false><<<dim3(DD/64, BL/128), 256>>>(o, owi, obi, t1, BL, DD, HD);
        k_ln<<<BL/8, 256>>>(h, t1, n1g + (size_t)i*DD, n1b + (size_t)i*DD);

        // FFN + residual LN
        k_gemm_mma<true ><<<dim3(FCC/64, BL/128), 256>>>(h, f1wi, f1bi, ff, BL, FCC, DD);
        k_gemm_mma<false><<<dim3(DD/64, BL/128), 256>>>(ff, f2wi, f2bi, t1, BL, DD, FCC);
        k_ln<<<BL/8, 256>>>(h, t1, n2g + (size_t)i*DD, n2b + (size_t)i*DD);
    }

    // final MLP head
    k_gemm_mma<true><<<dim3(DD/64, BL/128), 256>>>(h, o1w, o1b, t1, BL, DD, DD);
    k_out2<<<BL/8, 256>>>(t1, o2w, o2b, out);
}

// round 10
// speedup vs baseline: 4.6383x; 1.1088x over previous
#include <cuda_runtime.h>
#include <math.h>

#define BB   8
#define LL   2016
#define HH   4
#define DKK  32
#define DD   256
#define FCC  64
#define NLL  3
#define BL   (BB*LL)      // 16128
#define HD   (HH*DKK)     // 128
#define BHH  (BB*HH)      // 32
#define SCALE 0.0625f     // 1/sqrt(256)
#define EPSV  1e-5f
#define LOG2E 1.4426950408889634f

// ---------------- scratch (device globals: no allocation allowed) ----------
__device__ float g_h [BL*DD];
__device__ float g_q [BL*HD];
__device__ float g_k [BL*HD];
__device__ float g_v [BL*HD];
__device__ float g_o [BL*HD];
__device__ float g_t1[BL*DD];
__device__ float g_ff[BL*FCC];

// ---------------- tf32 helpers --------------------------------------------
__device__ __forceinline__ unsigned f2tf(float f) {
    unsigned u;
    asm("cvt.rna.tf32.f32 %0, %1;" : "=r"(u) : "f"(f));
    return u;
}

__device__ __forceinline__ float ex2(float x) {
    float r;
    asm("ex2.approx.f32 %0, %1;" : "=f"(r) : "f"(x));
    return r;
}

__device__ __forceinline__ void mma_tf32(float* d, const unsigned* a, const unsigned* b) {
    asm("mma.sync.aligned.m16n8k8.row.col.f32.tf32.tf32.f32 "
        "{%0,%1,%2,%3},{%4,%5,%6,%7},{%8,%9},{%0,%1,%2,%3};"
        : "+f"(d[0]), "+f"(d[1]), "+f"(d[2]), "+f"(d[3])
        : "r"(a[0]), "r"(a[1]), "r"(a[2]), "r"(a[3]),
          "r"(b[0]), "r"(b[1]));
}

__device__ __forceinline__ void split4(float4 f, uint4& hi, uint4& lo) {
    hi.x = f2tf(f.x); hi.y = f2tf(f.y); hi.z = f2tf(f.z); hi.w = f2tf(f.w);
    lo.x = f2tf(f.x - __uint_as_float(hi.x));
    lo.y = f2tf(f.y - __uint_as_float(hi.y));
    lo.z = f2tf(f.z - __uint_as_float(hi.z));
    lo.w = f2tf(f.w - __uint_as_float(hi.w));
}

__device__ __forceinline__ uint4 tf4(float4 f) {
    uint4 u;
    u.x = f2tf(f.x); u.y = f2tf(f.y); u.z = f2tf(f.z); u.w = f2tf(f.w);
    return u;
}

// ---------------- input projection: h = x @ in_w + in_b (K=2) -------------
__global__ void k_input(const float* __restrict__ x, const float* __restrict__ w,
                        const float* __restrict__ b, float* __restrict__ h) {
    int idx = blockIdx.x * 256 + threadIdx.x;
    int d = idx & (DD - 1);
    int r = idx >> 8;
    h[idx] = fmaf(x[2*r], w[d], fmaf(x[2*r+1], w[DD + d], b[d]));
}

// ------- 2-term split-tf32 GEMM, register-prefetch double-buffered ---------
// block tile 128x64, 8 warps 4x2, warp tile 32x32. M%128==0, N%64==0, K%32==0
template<bool RELU>
__global__ void __launch_bounds__(256) k_gemm_mma(
        const float* __restrict__ A, const float* __restrict__ W,
        const float* __restrict__ bias, float* __restrict__ C,
        int M, int N, int K) {
    __shared__ unsigned AsH[128*36], AsL[128*36];
    __shared__ unsigned WsH[32*72];
    int tid = threadIdx.x;
    int w = tid >> 5, lane = tid & 31, g = lane >> 2, t = lane & 3;
    int wm = w >> 1, wn = w & 1;
    int m0 = blockIdx.y * 128, n0 = blockIdx.x * 64;
    float acc[2][4][4] = {};
    float4 pA[4], pW[2];
    #pragma unroll
    for (int j = 0; j < 4; j++) {
        int i = tid + j*256; int r = i >> 3, c4 = (i & 7)*4;
        pA[j] = *(const float4*)&A[(size_t)(m0 + r) * K + c4];
    }
    #pragma unroll
    for (int j = 0; j < 2; j++) {
        int i = tid + j*256; int kk = i >> 4, c4 = (i & 15)*4;
        pW[j] = *(const float4*)&W[(size_t)kk * N + n0 + c4];
    }
    for (int k0 = 0; k0 < K; k0 += 32) {
        #pragma unroll
        for (int j = 0; j < 4; j++) {
            int i = tid + j*256; int r = i >> 3, c4 = (i & 7)*4;
            uint4 hi, lo; split4(pA[j], hi, lo);
            *(uint4*)&AsH[r*36 + c4] = hi;
            *(uint4*)&AsL[r*36 + c4] = lo;
        }
        #pragma unroll
        for (int j = 0; j < 2; j++) {
            int i = tid + j*256; int kk = i >> 4, c4 = (i & 15)*4;
            *(uint4*)&WsH[kk*72 + c4] = tf4(pW[j]);
        }
        __syncthreads();
        if (k0 + 32 < K) {
            #pragma unroll
            for (int j = 0; j < 4; j++) {
                int i = tid + j*256; int r = i >> 3, c4 = (i & 7)*4;
                pA[j] = *(const float4*)&A[(size_t)(m0 + r) * K + k0 + 32 + c4];
            }
            #pragma unroll
            for (int j = 0; j < 2; j++) {
                int i = tid + j*256; int kk = i >> 4, c4 = (i & 15)*4;
                pW[j] = *(const float4*)&W[(size_t)(k0 + 32 + kk) * N + n0 + c4];
            }
        }
        #pragma unroll
        for (int kk = 0; kk < 4; kk++) {
            unsigned aH[2][4], aL[2][4];
            #pragma unroll
            for (int mi = 0; mi < 2; mi++) {
                int ar = wm*32 + mi*16;
                aH[mi][0] = AsH[(ar + g    )*36 + kk*8 + t];
                aH[mi][1] = AsH[(ar + g + 8)*36 + kk*8 + t];
                aH[mi][2] = AsH[(ar + g    )*36 + kk*8 + t + 4];
                aH[mi][3] = AsH[(ar + g + 8)*36 + kk*8 + t + 4];
                aL[mi][0] = AsL[(ar + g    )*36 + kk*8 + t];
                aL[mi][1] = AsL[(ar + g + 8)*36 + kk*8 + t];
                aL[mi][2] = AsL[(ar + g    )*36 + kk*8 + t + 4];
                aL[mi][3] = AsL[(ar + g + 8)*36 + kk*8 + t + 4];
            }
            #pragma unroll
            for (int nt = 0; nt < 4; nt++) {
                unsigned bH[2];
                int nc = wn*32 + nt*8 + g;
                bH[0] = WsH[(kk*8 + t    )*72 + nc];
                bH[1] = WsH[(kk*8 + t + 4)*72 + nc];
                #pragma unroll
                for (int mi = 0; mi < 2; mi++) {
                    mma_tf32(acc[mi][nt], aL[mi], bH);
                    mma_tf32(acc[mi][nt], aH[mi], bH);
                }
            }
        }
        __syncthreads();
    }
    #pragma unroll
    for (int mi = 0; mi < 2; mi++) {
        #pragma unroll
        for (int nt = 0; nt < 4; nt++) {
            int col = n0 + wn*32 + nt*8 + t*2;
            int r0  = m0 + wm*32 + mi*16 + g;
            float b0v = bias[col], b1v = bias[col + 1];
            float c00 = acc[mi][nt][0] + b0v, c01 = acc[mi][nt][1] + b1v;
            float c10 = acc[mi][nt][2] + b0v, c11 = acc[mi][nt][3] + b1v;
            if (RELU) {
                c00 = fmaxf(c00, 0.f); c01 = fmaxf(c01, 0.f);
                c10 = fmaxf(c10, 0.f); c11 = fmaxf(c11, 0.f);
            }
            C[(size_t)r0*N + col]     = c00; C[(size_t)r0*N + col + 1]     = c01;
            C[(size_t)(r0+8)*N + col] = c10; C[(size_t)(r0+8)*N + col + 1] = c11;
        }
    }
}

// ------- fused QKV: 2-term split, register-prefetch double-buffered --------
// block 64x64, 8 warps 4x2 (warp tile 16x32), grid (HD/64=2, BL/64)
__global__ void __launch_bounds__(256) k_qkv(
        const float* __restrict__ A,
        const float* __restrict__ qw, const float* __restrict__ qb2,
        const float* __restrict__ kw, const float* __restrict__ kb2,
        const float* __restrict__ vw, const float* __restrict__ vb2,
        float* __restrict__ q, float* __restrict__ k, float* __restrict__ v) {
    __shared__ unsigned AsH[64*36], AsL[64*36];
    __shared__ unsigned WsH[3*32*72];
    int tid = threadIdx.x;
    int w = tid >> 5, lane = tid & 31, g = lane >> 2, t = lane & 3;
    int wm = w >> 1, wn = w & 1;
    int m0 = blockIdx.y * 64, n0 = blockIdx.x * 64;
    const float* Wp[3] = {qw, kw, vw};
    float acc[3][4][4] = {};
    float4 pA[2], pW[6];
    #pragma unroll
    for (int j = 0; j < 2; j++) {
        int i = tid + j*256; int r = i >> 3, c4 = (i & 7)*4;
        pA[j] = *(const float4*)&A[(size_t)(m0 + r) * DD + c4];
    }
    #pragma unroll
    for (int j = 0; j < 6; j++) {
        int i = tid + j*256; int o = i >> 9, jj = i & 511;
        int kk = jj >> 4, c4 = (jj & 15)*4;
        pW[j] = *(const float4*)&Wp[o][(size_t)kk * HD + n0 + c4];
    }
    for (int k0 = 0; k0 < DD; k0 += 32) {
        #pragma unroll
        for (int j = 0; j < 2; j++) {
            int i = tid + j*256; int r = i >> 3, c4 = (i & 7)*4;
            uint4 hi, lo; split4(pA[j], hi, lo);
            *(uint4*)&AsH[r*36 + c4] = hi;
            *(uint4*)&AsL[r*36 + c4] = lo;
        }
        #pragma unroll
        for (int j = 0; j < 6; j++) {
            int i = tid + j*256; int o = i >> 9, jj = i & 511;
            int kk = jj >> 4, c4 = (jj & 15)*4;
            *(uint4*)&WsH[o*2304 + kk*72 + c4] = tf4(pW[j]);
        }
        __syncthreads();
        if (k0 + 32 < DD) {
            #pragma unroll
            for (int j = 0; j < 2; j++) {
                int i = tid + j*256; int r = i >> 3, c4 = (i & 7)*4;
                pA[j] = *(const float4*)&A[(size_t)(m0 + r) * DD + k0 + 32 + c4];
            }
            #pragma unroll
            for (int j = 0; j < 6; j++) {
                int i = tid + j*256; int o = i >> 9, jj = i & 511;
                int kk = jj >> 4, c4 = (jj & 15)*4;
                pW[j] = *(const float4*)&Wp[o][(size_t)(k0 + 32 + kk) * HD + n0 + c4];
            }
        }
        #pragma unroll
        for (int kk = 0; kk < 4; kk++) {
            unsigned aH[4], aL[4];
            int ar = wm*16;
            aH[0] = AsH[(ar + g    )*36 + kk*8 + t];
            aH[1] = AsH[(ar + g + 8)*36 + kk*8 + t];
            aH[2] = AsH[(ar + g    )*36 + kk*8 + t + 4];
            aH[3] = AsH[(ar + g + 8)*36 + kk*8 + t + 4];
            aL[0] = AsL[(ar + g    )*36 + kk*8 + t];
            aL[1] = AsL[(ar + g + 8)*36 + kk*8 + t];
            aL[2] = AsL[(ar + g    )*36 + kk*8 + t + 4];
            aL[3] = AsL[(ar + g + 8)*36 + kk*8 + t + 4];
            #pragma unroll
            for (int o = 0; o < 3; o++) {
                #pragma unroll
                for (int nt = 0; nt < 4; nt++) {
                    unsigned bH[2];
                    int nc = o*2304 + wn*32 + nt*8 + g;
                    bH[0] = WsH[(kk*8 + t    )*72 + nc];
                    bH[1] = WsH[(kk*8 + t + 4)*72 + nc];
                    mma_tf32(acc[o][nt], aL, bH);
                    mma_tf32(acc[o][nt], aH, bH);
                }
            }
        }
        __syncthreads();
    }
    float* Co[3] = {q, k, v};
    const float* Bo[3] = {qb2, kb2, vb2};
    #pragma unroll
    for (int o = 0; o < 3; o++) {
        #pragma unroll
        for (int nt = 0; nt < 4; nt++) {
            int col = n0 + wn*32 + nt*8 + t*2;
            int r0  = m0 + wm*16 + g;
            float b0v = Bo[o][col], b1v = Bo[o][col + 1];
            Co[o][(size_t)r0*HD + col]       = acc[o][nt][0] + b0v;
            Co[o][(size_t)r0*HD + col + 1]   = acc[o][nt][1] + b1v;
            Co[o][(size_t)(r0+8)*HD + col]   = acc[o][nt][2] + b0v;
            Co[o][(size_t)(r0+8)*HD + col+1] = acc[o][nt][3] + b1v;
        }
    }
}

// ------- merged flash attention (no-max softmax), 256 rows/CTA -------------
// grid (8 row-tiles of 256, 32 bh), 512 thr, 16 warps x 16 rows.
// Q frags in registers; P relayout via shuffles; K/V reg-prefetch dbl-buffer.
__global__ void __launch_bounds__(512) k_attn2(
        const float* __restrict__ Q, const float* __restrict__ Kv,
        const float* __restrict__ V, float* __restrict__ P,
        float* __restrict__ O) {
    __shared__ unsigned Ks[128*36];
    __shared__ unsigned Vs[128*40];
    int tid = threadIdx.x;
    int w = tid >> 5, lane = tid & 31, g = lane >> 2, t = lane & 3;
    int l0 = blockIdx.x * 256;
    int bh = blockIdx.y, b = bh >> 2, hh = bh & 3;
    const float* qb = Q  + (size_t)b * LL * HD + hh * DKK;
    const float* kb = Kv + (size_t)b * LL * HD + hh * DKK;
    const float* vb = V  + (size_t)b * LL * HD + hh * DKK;

    int row0 = l0 + w*16 + g;
    int row1 = row0 + 8;
    bool r0ok = row0 < LL, r1ok = row1 < LL;

    unsigned qf[4][4];
    #pragma unroll
    for (int kk = 0; kk < 4; kk++) {
        qf[kk][0] = f2tf(r0ok ? qb[(size_t)row0*HD + kk*8 + t]     : 0.f);
        qf[kk][1] = f2tf(r1ok ? qb[(size_t)row1*HD + kk*8 + t]     : 0.f);
        qf[kk][2] = f2tf(r0ok ? qb[(size_t)row0*HD + kk*8 + t + 4] : 0.f);
        qf[kk][3] = f2tf(r1ok ? qb[(size_t)row1*HD + kk*8 + t + 4] : 0.f);
    }
    const float S2 = SCALE * LOG2E;
    const float4 f0 = make_float4(0.f, 0.f, 0.f, 0.f);

    // ---- phase 0: per-row z = sum exp2(s*S2) (no max: bounded scores) ----
    float z0 = 0.f, z1 = 0.f;
    float4 pk[2];
    #pragma unroll
    for (int j = 0; j < 2; j++) {
        int i = tid + j*512; int r = i >> 3, c4 = (i & 7)*4;
        pk[j] = (r < LL) ? *(const float4*)&kb[(size_t)r * HD + c4] : f0;
    }
    for (int s0 = 0; s0 < LL; s0 += 128) {
        #pragma unroll
        for (int j = 0; j < 2; j++) {
            int i = tid + j*512; int r = i >> 3, c4 = (i & 7)*4;
            *(uint4*)&Ks[r*36 + c4] = tf4(pk[j]);
        }
        __syncthreads();
        if (s0 + 128 < LL) {
            #pragma unroll
            for (int j = 0; j < 2; j++) {
                int i = tid + j*512; int r = i >> 3, c4 = (i & 7)*4;
                int sr = s0 + 128 + r;
                pk[j] = (sr < LL) ? *(const float4*)&kb[(size_t)sr * HD + c4] : f0;
            }
        }
        #pragma unroll
        for (int hf2 = 0; hf2 < 2; hf2++) {
            int sb = s0 + hf2*64;
            float acc[8][4] = {};
            #pragma unroll
            for (int kk = 0; kk < 4; kk++) {
                #pragma unroll
                for (int ni = 0; ni < 8; ni++) {
                    unsigned b2[2];
                    b2[0] = Ks[(hf2*64 + ni*8 + g)*36 + kk*8 + t];
                    b2[1] = Ks[(hf2*64 + ni*8 + g)*36 + kk*8 + t + 4];
                    mma_tf32(acc[ni], qf[kk], b2);
                }
            }
            #pragma unroll
            for (int ni = 0; ni < 8; ni++) {
                if (sb + ni*8 < LL) {
                    z0 += ex2(acc[ni][0]*S2) + ex2(acc[ni][1]*S2);
                    z1 += ex2(acc[ni][2]*S2) + ex2(acc[ni][3]*S2);
                }
            }
        }
        __syncthreads();
    }
    z0 += __shfl_xor_sync(0xffffffffu, z0, 1);
    z0 += __shfl_xor_sync(0xffffffffu, z0, 2);
    z1 += __shfl_xor_sync(0xffffffffu, z1, 1);
    z1 += __shfl_xor_sync(0xffffffffu, z1, 2);
    float inv0 = 1.f / z0, inv1 = 1.f / z1;

    // ---- phase 1: recompute S, write P, accumulate O = P@V ---------------
    float* Pb = P + (size_t)bh * LL * LL;
    float acc2[4][4] = {};
    int srcA = (lane & 0x1C) | (t >> 1);
    bool odd = (t & 1);
    float4 pv[2];
    #pragma unroll
    for (int j = 0; j < 2; j++) {
        int i = tid + j*512; int r = i >> 3, c4 = (i & 7)*4;
        pk[j] = (r < LL) ? *(const float4*)&kb[(size_t)r * HD + c4] : f0;
        pv[j] = (r < LL) ? *(const float4*)&vb[(size_t)r * HD + c4] : f0;
    }
    for (int s0 = 0; s0 < LL; s0 += 128) {
        #pragma unroll
        for (int j = 0; j < 2; j++) {
            int i = tid + j*512; int r = i >> 3, c4 = (i & 7)*4;
            *(uint4*)&Ks[r*36 + c4] = tf4(pk[j]);
            *(uint4*)&Vs[r*40 + c4] = tf4(pv[j]);
        }
        __syncthreads();
        if (s0 + 128 < LL) {
            #pragma unroll
            for (int j = 0; j < 2; j++) {
                int i = tid + j*512; int r = i >> 3, c4 = (i & 7)*4;
                int sr = s0 + 128 + r;
                pk[j] = (sr < LL) ? *(const float4*)&kb[(size_t)sr * HD + c4] : f0;
                pv[j] = (sr < LL) ? *(const float4*)&vb[(size_t)sr * HD + c4] : f0;
            }
        }
        #pragma unroll
        for (int hf2 = 0; hf2 < 2; hf2++) {
            int sb = s0 + hf2*64;
            float acc[8][4] = {};
            #pragma unroll
            for (int kk = 0; kk < 4; kk++) {
                #pragma unroll
                for (int ni = 0; ni < 8; ni++) {
                    unsigned b2[2];
                    b2[0] = Ks[(hf2*64 + ni*8 + g)*36 + kk*8 + t];
                    b2[1] = Ks[(hf2*64 + ni*8 + g)*36 + kk*8 + t + 4];
                    mma_tf32(acc[ni], qf[kk], b2);
                }
            }
            #pragma unroll
            for (int ni = 0; ni < 8; ni++) {
                bool cok = (sb + ni*8) < LL;
                float p0 = cok ? ex2(acc[ni][0]*S2) * inv0 : 0.f;
                float p1 = cok ? ex2(acc[ni][1]*S2) * inv0 : 0.f;
                float p2 = cok ? ex2(acc[ni][2]*S2) * inv1 : 0.f;
                float p3 = cok ? ex2(acc[ni][3]*S2) * inv1 : 0.f;
                if (cok) {
                    size_t cidx = (size_t)(sb + ni*8 + t*2);
                    if (r0ok) *(float2*)&Pb[(size_t)row0*LL + cidx] = make_float2(p0, p1);
                    if (r1ok) *(float2*)&Pb[(size_t)row1*LL + cidx] = make_float2(p2, p3);
                }
                acc[ni][0] = __uint_as_float(f2tf(p0));
                acc[ni][1] = __uint_as_float(f2tf(p1));
                acc[ni][2] = __uint_as_float(f2tf(p2));
                acc[ni][3] = __uint_as_float(f2tf(p3));
            }
            #pragma unroll
            for (int kk = 0; kk < 8; kk++) {
                float x0 = __shfl_sync(0xffffffffu, acc[kk][0], srcA);
                float x1 = __shfl_sync(0xffffffffu, acc[kk][1], srcA);
                float y0 = __shfl_sync(0xffffffffu, acc[kk][2], srcA);
                float y1 = __shfl_sync(0xffffffffu, acc[kk][3], srcA);
                float x0b = __shfl_sync(0xffffffffu, acc[kk][0], srcA + 2);
                float x1b = __shfl_sync(0xffffffffu, acc[kk][1], srcA + 2);
                float y0b = __shfl_sync(0xffffffffu, acc[kk][2], srcA + 2);
                float y1b = __shfl_sync(0xffffffffu, acc[kk][3], srcA + 2);
                unsigned a[4];
                a[0] = __float_as_uint(odd ? x1  : x0);
                a[1] = __float_as_uint(odd ? y1  : y0);
                a[2] = __float_as_uint(odd ? x1b : x0b);
                a[3] = __float_as_uint(odd ? y1b : y0b);
                #pragma unroll
                for (int ni = 0; ni < 4; ni++) {
                    unsigned b2[2];
                    b2[0] = Vs[(hf2*64 + kk*8 + t)*40 + ni*8 + g];
                    b2[1] = Vs[(hf2*64 + kk*8 + t + 4)*40 + ni*8 + g];
                    mma_tf32(acc2[ni], a, b2);
                }
            }
        }
        __syncthreads();
    }
    float* ob = O + (size_t)b * LL * HD + hh * DKK;
    #pragma unroll
    for (int ni = 0; ni < 4; ni++) {
        int c0 = ni*8 + t*2;
        if (r0ok) *(float2*)&ob[(size_t)row0*HD + c0] = make_float2(acc2[ni][0], acc2[ni][1]);
        if (r1ok) *(float2*)&ob[(size_t)row1*HD + c0] = make_float2(acc2[ni][2], acc2[ni][3]);
    }
}

// ---------------- h = LayerNorm(h + add) * g + b (row of 256, float4) ------
__global__ void k_ln(float* __restrict__ h, const float* __restrict__ add,
                     const float* __restrict__ g, const float* __restrict__ bta) {
    int row  = blockIdx.x * 8 + (threadIdx.x >> 5);
    int lane = threadIdx.x & 31;
    float* hp = h + (size_t)row * DD;
    const float* ap = add + (size_t)row * DD;
    float4 v[2]; float s = 0.f;
    #pragma unroll
    for (int i = 0; i < 2; i++) {
        int d = lane*4 + i*128;
        float4 a = *(const float4*)&hp[d];
        float4 c = *(const float4*)&ap[d];
        v[i] = make_float4(a.x + c.x, a.y + c.y, a.z + c.z, a.w + c.w);
        s += v[i].x + v[i].y + v[i].z + v[i].w;
    }
    #pragma unroll
    for (int o = 16; o > 0; o >>= 1) s += __shfl_xor_sync(0xffffffffu, s, o);
    float mean = s * (1.f / DD);
    float var = 0.f;
    #pragma unroll
    for (int i = 0; i < 2; i++) {
        float dx = v[i].x - mean, dy = v[i].y - mean;
        float dz = v[i].z - mean, dw = v[i].w - mean;
        var = fmaf(dx, dx, var); var = fmaf(dy, dy, var);
        var = fmaf(dz, dz, var); var = fmaf(dw, dw, var);
    }
    #pragma unroll
    for (int o = 16; o > 0; o >>= 1) var += __shfl_xor_sync(0xffffffffu, var, o);
    var *= (1.f / DD);
    float r = rsqrtf(var + EPSV);
    #pragma unroll
    for (int i = 0; i < 2; i++) {
        int d = lane*4 + i*128;
        float4 gg = *(const float4*)&g[d];
        float4 bb = *(const float4*)&bta[d];
        float4 o4;
        o4.x = (v[i].x - mean) * r * gg.x + bb.x;
        o4.y = (v[i].y - mean) * r * gg.y + bb.y;
        o4.z = (v[i].z - mean) * r * gg.z + bb.z;
        o4.w = (v[i].w - mean) * r * gg.w + bb.w;
        *(float4*)&hp[d] = o4;
    }
}

// ---------------- final head: out = A(relu'd) @ o2w(256x2) + o2b -----------
__global__ void k_out2(const float* __restrict__ A, const float* __restrict__ w,
                       const float* __restrict__ b, float* __restrict__ out) {
    int row  = blockIdx.x * 8 + (threadIdx.x >> 5);
    int lane = threadIdx.x & 31;
    const float* ap = A + (size_t)row * DD;
    float s0 = 0.f, s1 = 0.f;
    #pragma unroll
    for (int i = 0; i < 8; i++) {
        int d = lane + 32*i;
        float a = ap[d];
        s0 = fmaf(a, w[d*2],     s0);
        s1 = fmaf(a, w[d*2 + 1], s1);
    }
    #pragma unroll
    for (int o = 16; o > 0; o >>= 1) {
        s0 += __shfl_xor_sync(0xffffffffu, s0, o);
        s1 += __shfl_xor_sync(0xffffffffu, s1, o);
    }
    if (lane == 0) {
        out[(size_t)row*2]     = s0 + b[0];
        out[(size_t)row*2 + 1] = s1 + b[1];
    }
}

// ---------------------------------------------------------------------------
extern "C" void kernel_launch(void* const* d_in, const int* in_sizes, int n_in,
                              void* d_out, int out_size) {
    const float* x    = (const float*)d_in[0];
    const float* in_w = (const float*)d_in[1];
    const float* in_b = (const float*)d_in[2];
    const float* qw   = (const float*)d_in[3];
    const float* qb   = (const float*)d_in[4];
    const float* kw   = (const float*)d_in[5];
    const float* kb   = (const float*)d_in[6];
    const float* vw   = (const float*)d_in[7];
    const float* vb   = (const float*)d_in[8];
    const float* ow   = (const float*)d_in[9];
    const float* ob   = (const float*)d_in[10];
    const float* f1w  = (const float*)d_in[11];
    const float* f1b  = (const float*)d_in[12];
    const float* f2w  = (const float*)d_in[13];
    const float* f2b  = (const float*)d_in[14];
    const float* n1g  = (const float*)d_in[15];
    const float* n1b  = (const float*)d_in[16];
    const float* n2g  = (const float*)d_in[17];
    const float* n2b  = (const float*)d_in[18];
    const float* o1w  = (const float*)d_in[19];
    const float* o1b  = (const float*)d_in[20];
    const float* o2w  = (const float*)d_in[21];
    const float* o2b  = (const float*)d_in[22];

    float* out  = (float*)d_out;
    float* attn = out + (size_t)BB * LL * 2;   // attns region: (NL,B,H,L,L)

    float *h, *q, *k, *v, *o, *t1, *ff;
    cudaGetSymbolAddress((void**)&h,  g_h);
    cudaGetSymbolAddress((void**)&q,  g_q);
    cudaGetSymbolAddress((void**)&k,  g_k);
    cudaGetSymbolAddress((void**)&v,  g_v);
    cudaGetSymbolAddress((void**)&o,  g_o);
    cudaGetSymbolAddress((void**)&t1, g_t1);
    cudaGetSymbolAddress((void**)&ff, g_ff);

    // input projection
    k_input<<<(BL*DD)/256, 256>>>(x, in_w, in_b, h);

    const int RT = (LL + 255) / 256;   // 8 row tiles

    for (int i = 0; i < NLL; i++) {
        const float* qwi = qw + (size_t)i * DD * HD;
        const float* qbi = qb + (size_t)i * HD;
        const float* kwi = kw + (size_t)i * DD * HD;
        const float* kbi = kb + (size_t)i * HD;
        const float* vwi = vw + (size_t)i * DD * HD;
        const float* vbi = vb + (size_t)i * HD;
        const float* owi = ow + (size_t)i * HD * DD;
        const float* obi = ob + (size_t)i * DD;
        const float* f1wi = f1w + (size_t)i * DD * FCC;
        const float* f1bi = f1b + (size_t)i * FCC;
        const float* f2wi = f2w + (size_t)i * FCC * DD;
        const float* f2bi = f2b + (size_t)i * DD;

        // fused Q,K,V projection
        k_qkv<<<dim3(HD/64, BL/64), 256>>>(
            h, qwi, qbi, kwi, kbi, vwi, vbi, q, k, v);

        // merged flash attention (stats + P + O), 256 rows/CTA
        float* Si = attn + (size_t)i * BHH * LL * LL;
        k_attn2<<<dim3(RT, BHH), 512>>>(q, k, v, Si, o);

        // output projection + residual LN
        k_gemm_mma<false><<<dim3(DD/64, BL/128), 256>>>(o, owi, obi, t1, BL, DD, HD);
        k_ln<<<BL/8, 256>>>(h, t1, n1g + (size_t)i*DD, n1b + (size_t)i*DD);

        // FFN + residual LN
        k_gemm_mma<true ><<<dim3(FCC/64, BL/128), 256>>>(h, f1wi, f1bi, ff, BL, FCC, DD);
        k_gemm_mma<false><<<dim3(DD/64, BL/128), 256>>>(ff, f2wi, f2bi, t1, BL, DD, FCC);
        k_ln<<<BL/8, 256>>>(h, t1, n2g + (size_t)i*DD, n2b + (size_t)i*DD);
    }

    // final MLP head
    k_gemm_mma<true><<<dim3(DD/64, BL/128), 256>>>(h, o1w, o1b, t1, BL, DD, DD);
    k_out2<<<BL/8, 256>>>(t1, o2w, o2b, out);
}

// round 11
// speedup vs baseline: 4.6451x; 1.0015x over previous
#include <cuda_runtime.h>
#include <math.h>

#define BB   8
#define LL   2016
#define HH   4
#define DKK  32
#define DD   256
#define FCC  64
#define NLL  3
#define BL   (BB*LL)      // 16128
#define HD   (HH*DKK)     // 128
#define BHH  (BB*HH)      // 32
#define SCALE 0.0625f     // 1/sqrt(256)
#define EPSV  1e-5f
#define LOG2E 1.4426950408889634f

// ---------------- scratch (device globals: no allocation allowed) ----------
__device__ float g_h [BL*DD];
__device__ float g_q [BL*HD];
__device__ float g_k [BL*HD];
__device__ float g_v [BL*HD];
__device__ float g_o [BL*HD];
__device__ float g_t1[BL*DD];
__device__ float g_ff[BL*FCC];

// ---------------- tf32 helpers --------------------------------------------
__device__ __forceinline__ unsigned f2tf(float f) {
    unsigned u;
    asm("cvt.rna.tf32.f32 %0, %1;" : "=r"(u) : "f"(f));
    return u;
}

__device__ __forceinline__ float ex2(float x) {
    float r;
    asm("ex2.approx.f32 %0, %1;" : "=f"(r) : "f"(x));
    return r;
}

__device__ __forceinline__ void mma_tf32(float* d, const unsigned* a, const unsigned* b) {
    asm("mma.sync.aligned.m16n8k8.row.col.f32.tf32.tf32.f32 "
        "{%0,%1,%2,%3},{%4,%5,%6,%7},{%8,%9},{%0,%1,%2,%3};"
        : "+f"(d[0]), "+f"(d[1]), "+f"(d[2]), "+f"(d[3])
        : "r"(a[0]), "r"(a[1]), "r"(a[2]), "r"(a[3]),
          "r"(b[0]), "r"(b[1]));
}

__device__ __forceinline__ void split4(float4 f, uint4& hi, uint4& lo) {
    hi.x = f2tf(f.x); hi.y = f2tf(f.y); hi.z = f2tf(f.z); hi.w = f2tf(f.w);
    lo.x = f2tf(f.x - __uint_as_float(hi.x));
    lo.y = f2tf(f.y - __uint_as_float(hi.y));
    lo.z = f2tf(f.z - __uint_as_float(hi.z));
    lo.w = f2tf(f.w - __uint_as_float(hi.w));
}

__device__ __forceinline__ uint4 tf4(float4 f) {
    uint4 u;
    u.x = f2tf(f.x); u.y = f2tf(f.y); u.z = f2tf(f.z); u.w = f2tf(f.w);
    return u;
}

// ---------------- input projection: h = x @ in_w + in_b (K=2) -------------
__global__ void k_input(const float* __restrict__ x, const float* __restrict__ w,
                        const float* __restrict__ b, float* __restrict__ h) {
    int idx = blockIdx.x * 256 + threadIdx.x;
    int d = idx & (DD - 1);
    int r = idx >> 8;
    h[idx] = fmaf(x[2*r], w[d], fmaf(x[2*r+1], w[DD + d], b[d]));
}

// ------- 2-term split-tf32 GEMM, register-prefetch double-buffered ---------
// block tile 128x64, 8 warps 4x2, warp tile 32x32. M%128==0, N%64==0, K%32==0
template<bool RELU>
__global__ void __launch_bounds__(256) k_gemm_mma(
        const float* __restrict__ A, const float* __restrict__ W,
        const float* __restrict__ bias, float* __restrict__ C,
        int M, int N, int K) {
    __shared__ unsigned AsH[128*36], AsL[128*36];
    __shared__ unsigned WsH[32*72];
    int tid = threadIdx.x;
    int w = tid >> 5, lane = tid & 31, g = lane >> 2, t = lane & 3;
    int wm = w >> 1, wn = w & 1;
    int m0 = blockIdx.y * 128, n0 = blockIdx.x * 64;
    float acc[2][4][4] = {};
    float4 pA[4], pW[2];
    #pragma unroll
    for (int j = 0; j < 4; j++) {
        int i = tid + j*256; int r = i >> 3, c4 = (i & 7)*4;
        pA[j] = *(const float4*)&A[(size_t)(m0 + r) * K + c4];
    }
    #pragma unroll
    for (int j = 0; j < 2; j++) {
        int i = tid + j*256; int kk = i >> 4, c4 = (i & 15)*4;
        pW[j] = *(const float4*)&W[(size_t)kk * N + n0 + c4];
    }
    for (int k0 = 0; k0 < K; k0 += 32) {
        #pragma unroll
        for (int j = 0; j < 4; j++) {
            int i = tid + j*256; int r = i >> 3, c4 = (i & 7)*4;
            uint4 hi, lo; split4(pA[j], hi, lo);
            *(uint4*)&AsH[r*36 + c4] = hi;
            *(uint4*)&AsL[r*36 + c4] = lo;
        }
        #pragma unroll
        for (int j = 0; j < 2; j++) {
            int i = tid + j*256; int kk = i >> 4, c4 = (i & 15)*4;
            *(uint4*)&WsH[kk*72 + c4] = tf4(pW[j]);
        }
        __syncthreads();
        if (k0 + 32 < K) {
            #pragma unroll
            for (int j = 0; j < 4; j++) {
                int i = tid + j*256; int r = i >> 3, c4 = (i & 7)*4;
                pA[j] = *(const float4*)&A[(size_t)(m0 + r) * K + k0 + 32 + c4];
            }
            #pragma unroll
            for (int j = 0; j < 2; j++) {
                int i = tid + j*256; int kk = i >> 4, c4 = (i & 15)*4;
                pW[j] = *(const float4*)&W[(size_t)(k0 + 32 + kk) * N + n0 + c4];
            }
        }
        #pragma unroll
        for (int kk = 0; kk < 4; kk++) {
            unsigned aH[2][4], aL[2][4];
            #pragma unroll
            for (int mi = 0; mi < 2; mi++) {
                int ar = wm*32 + mi*16;
                aH[mi][0] = AsH[(ar + g    )*36 + kk*8 + t];
                aH[mi][1] = AsH[(ar + g + 8)*36 + kk*8 + t];
                aH[mi][2] = AsH[(ar + g    )*36 + kk*8 + t + 4];
                aH[mi][3] = AsH[(ar + g + 8)*36 + kk*8 + t + 4];
                aL[mi][0] = AsL[(ar + g    )*36 + kk*8 + t];
                aL[mi][1] = AsL[(ar + g + 8)*36 + kk*8 + t];
                aL[mi][2] = AsL[(ar + g    )*36 + kk*8 + t + 4];
                aL[mi][3] = AsL[(ar + g + 8)*36 + kk*8 + t + 4];
            }
            #pragma unroll
            for (int nt = 0; nt < 4; nt++) {
                unsigned bH[2];
                int nc = wn*32 + nt*8 + g;
                bH[0] = WsH[(kk*8 + t    )*72 + nc];
                bH[1] = WsH[(kk*8 + t + 4)*72 + nc];
                #pragma unroll
                for (int mi = 0; mi < 2; mi++) {
                    mma_tf32(acc[mi][nt], aL[mi], bH);
                    mma_tf32(acc[mi][nt], aH[mi], bH);
                }
            }
        }
        __syncthreads();
    }
    #pragma unroll
    for (int mi = 0; mi < 2; mi++) {
        #pragma unroll
        for (int nt = 0; nt < 4; nt++) {
            int col = n0 + wn*32 + nt*8 + t*2;
            int r0  = m0 + wm*32 + mi*16 + g;
            float b0v = bias[col], b1v = bias[col + 1];
            float c00 = acc[mi][nt][0] + b0v, c01 = acc[mi][nt][1] + b1v;
            float c10 = acc[mi][nt][2] + b0v, c11 = acc[mi][nt][3] + b1v;
            if (RELU) {
                c00 = fmaxf(c00, 0.f); c01 = fmaxf(c01, 0.f);
                c10 = fmaxf(c10, 0.f); c11 = fmaxf(c11, 0.f);
            }
            C[(size_t)r0*N + col]     = c00; C[(size_t)r0*N + col + 1]     = c01;
            C[(size_t)(r0+8)*N + col] = c10; C[(size_t)(r0+8)*N + col + 1] = c11;
        }
    }
}

// ------- fused QKV: 2-term split, register-prefetch double-buffered --------
// block 64x64, 8 warps 4x2 (warp tile 16x32), grid (HD/64=2, BL/64)
__global__ void __launch_bounds__(256) k_qkv(
        const float* __restrict__ A,
        const float* __restrict__ qw, const float* __restrict__ qb2,
        const float* __restrict__ kw, const float* __restrict__ kb2,
        const float* __restrict__ vw, const float* __restrict__ vb2,
        float* __restrict__ q, float* __restrict__ k, float* __restrict__ v) {
    __shared__ unsigned AsH[64*36], AsL[64*36];
    __shared__ unsigned WsH[3*32*72];
    int tid = threadIdx.x;
    int w = tid >> 5, lane = tid & 31, g = lane >> 2, t = lane & 3;
    int wm = w >> 1, wn = w & 1;
    int m0 = blockIdx.y * 64, n0 = blockIdx.x * 64;
    const float* Wp[3] = {qw, kw, vw};
    float acc[3][4][4] = {};
    float4 pA[2], pW[6];
    #pragma unroll
    for (int j = 0; j < 2; j++) {
        int i = tid + j*256; int r = i >> 3, c4 = (i & 7)*4;
        pA[j] = *(const float4*)&A[(size_t)(m0 + r) * DD + c4];
    }
    #pragma unroll
    for (int j = 0; j < 6; j++) {
        int i = tid + j*256; int o = i >> 9, jj = i & 511;
        int kk = jj >> 4, c4 = (jj & 15)*4;
        pW[j] = *(const float4*)&Wp[o][(size_t)kk * HD + n0 + c4];
    }
    for (int k0 = 0; k0 < DD; k0 += 32) {
        #pragma unroll
        for (int j = 0; j < 2; j++) {
            int i = tid + j*256; int r = i >> 3, c4 = (i & 7)*4;
            uint4 hi, lo; split4(pA[j], hi, lo);
            *(uint4*)&AsH[r*36 + c4] = hi;
            *(uint4*)&AsL[r*36 + c4] = lo;
        }
        #pragma unroll
        for (int j = 0; j < 6; j++) {
            int i = tid + j*256; int o = i >> 9, jj = i & 511;
            int kk = jj >> 4, c4 = (jj & 15)*4;
            *(uint4*)&WsH[o*2304 + kk*72 + c4] = tf4(pW[j]);
        }
        __syncthreads();
        if (k0 + 32 < DD) {
            #pragma unroll
            for (int j = 0; j < 2; j++) {
                int i = tid + j*256; int r = i >> 3, c4 = (i & 7)*4;
                pA[j] = *(const float4*)&A[(size_t)(m0 + r) * DD + k0 + 32 + c4];
            }
            #pragma unroll
            for (int j = 0; j < 6; j++) {
                int i = tid + j*256; int o = i >> 9, jj = i & 511;
                int kk = jj >> 4, c4 = (jj & 15)*4;
                pW[j] = *(const float4*)&Wp[o][(size_t)(k0 + 32 + kk) * HD + n0 + c4];
            }
        }
        #pragma unroll
        for (int kk = 0; kk < 4; kk++) {
            unsigned aH[4], aL[4];
            int ar = wm*16;
            aH[0] = AsH[(ar + g    )*36 + kk*8 + t];
            aH[1] = AsH[(ar + g + 8)*36 + kk*8 + t];
            aH[2] = AsH[(ar + g    )*36 + kk*8 + t + 4];
            aH[3] = AsH[(ar + g + 8)*36 + kk*8 + t + 4];
            aL[0] = AsL[(ar + g    )*36 + kk*8 + t];
            aL[1] = AsL[(ar + g + 8)*36 + kk*8 + t];
            aL[2] = AsL[(ar + g    )*36 + kk*8 + t + 4];
            aL[3] = AsL[(ar + g + 8)*36 + kk*8 + t + 4];
            #pragma unroll
            for (int o = 0; o < 3; o++) {
                #pragma unroll
                for (int nt = 0; nt < 4; nt++) {
                    unsigned bH[2];
                    int nc = o*2304 + wn*32 + nt*8 + g;
                    bH[0] = WsH[(kk*8 + t    )*72 + nc];
                    bH[1] = WsH[(kk*8 + t + 4)*72 + nc];
                    mma_tf32(acc[o][nt], aL, bH);
                    mma_tf32(acc[o][nt], aH, bH);
                }
            }
        }
        __syncthreads();
    }
    float* Co[3] = {q, k, v};
    const float* Bo[3] = {qb2, kb2, vb2};
    #pragma unroll
    for (int o = 0; o < 3; o++) {
        #pragma unroll
        for (int nt = 0; nt < 4; nt++) {
            int col = n0 + wn*32 + nt*8 + t*2;
            int r0  = m0 + wm*16 + g;
            float b0v = Bo[o][col], b1v = Bo[o][col + 1];
            Co[o][(size_t)r0*HD + col]       = acc[o][nt][0] + b0v;
            Co[o][(size_t)r0*HD + col + 1]   = acc[o][nt][1] + b1v;
            Co[o][(size_t)(r0+8)*HD + col]   = acc[o][nt][2] + b0v;
            Co[o][(size_t)(r0+8)*HD + col+1] = acc[o][nt][3] + b1v;
        }
    }
}

// ------- merged flash attention (no-max softmax), 256 rows/CTA -------------
// grid (8 row-tiles of 256, 32 bh), 512 thr, 16 warps x 16 rows.
// Q frags in registers; P relayout via shuffles; K/V reg-prefetch dbl-buffer.
__global__ void __launch_bounds__(512) k_attn2(
        const float* __restrict__ Q, const float* __restrict__ Kv,
        const float* __restrict__ V, float* __restrict__ P,
        float* __restrict__ O) {
    __shared__ unsigned Ks[128*36];
    __shared__ unsigned Vs[128*40];
    int tid = threadIdx.x;
    int w = tid >> 5, lane = tid & 31, g = lane >> 2, t = lane & 3;
    int l0 = blockIdx.x * 256;
    int bh = blockIdx.y, b = bh >> 2, hh = bh & 3;
    const float* qb = Q  + (size_t)b * LL * HD + hh * DKK;
    const float* kb = Kv + (size_t)b * LL * HD + hh * DKK;
    const float* vb = V  + (size_t)b * LL * HD + hh * DKK;

    int row0 = l0 + w*16 + g;
    int row1 = row0 + 8;
    bool r0ok = row0 < LL, r1ok = row1 < LL;

    unsigned qf[4][4];
    #pragma unroll
    for (int kk = 0; kk < 4; kk++) {
        qf[kk][0] = f2tf(r0ok ? qb[(size_t)row0*HD + kk*8 + t]     : 0.f);
        qf[kk][1] = f2tf(r1ok ? qb[(size_t)row1*HD + kk*8 + t]     : 0.f);
        qf[kk][2] = f2tf(r0ok ? qb[(size_t)row0*HD + kk*8 + t + 4] : 0.f);
        qf[kk][3] = f2tf(r1ok ? qb[(size_t)row1*HD + kk*8 + t + 4] : 0.f);
    }
    const float S2 = SCALE * LOG2E;
    const float4 f0 = make_float4(0.f, 0.f, 0.f, 0.f);

    // ---- phase 0: per-row z = sum exp2(s*S2) (no max: bounded scores) ----
    float z0 = 0.f, z1 = 0.f;
    float4 pk[2];
    #pragma unroll
    for (int j = 0; j < 2; j++) {
        int i = tid + j*512; int r = i >> 3, c4 = (i & 7)*4;
        pk[j] = (r < LL) ? *(const float4*)&kb[(size_t)r * HD + c4] : f0;
    }
    for (int s0 = 0; s0 < LL; s0 += 128) {
        #pragma unroll
        for (int j = 0; j < 2; j++) {
            int i = tid + j*512; int r = i >> 3, c4 = (i & 7)*4;
            *(uint4*)&Ks[r*36 + c4] = tf4(pk[j]);
        }
        __syncthreads();
        if (s0 + 128 < LL) {
            #pragma unroll
            for (int j = 0; j < 2; j++) {
                int i = tid + j*512; int r = i >> 3, c4 = (i & 7)*4;
                int sr = s0 + 128 + r;
                pk[j] = (sr < LL) ? *(const float4*)&kb[(size_t)sr * HD + c4] : f0;
            }
        }
        #pragma unroll
        for (int hf2 = 0; hf2 < 2; hf2++) {
            int sb = s0 + hf2*64;
            float acc[8][4] = {};
            #pragma unroll
            for (int kk = 0; kk < 4; kk++) {
                #pragma unroll
                for (int ni = 0; ni < 8; ni++) {
                    unsigned b2[2];
                    b2[0] = Ks[(hf2*64 + ni*8 + g)*36 + kk*8 + t];
                    b2[1] = Ks[(hf2*64 + ni*8 + g)*36 + kk*8 + t + 4];
                    mma_tf32(acc[ni], qf[kk], b2);
                }
            }
            #pragma unroll
            for (int ni = 0; ni < 8; ni++) {
                if (sb + ni*8 < LL) {
                    z0 += ex2(acc[ni][0]*S2) + ex2(acc[ni][1]*S2);
                    z1 += ex2(acc[ni][2]*S2) + ex2(acc[ni][3]*S2);
                }
            }
        }
        __syncthreads();
    }
    z0 += __shfl_xor_sync(0xffffffffu, z0, 1);
    z0 += __shfl_xor_sync(0xffffffffu, z0, 2);
    z1 += __shfl_xor_sync(0xffffffffu, z1, 1);
    z1 += __shfl_xor_sync(0xffffffffu, z1, 2);
    float inv0 = 1.f / z0, inv1 = 1.f / z1;

    // ---- phase 1: recompute S, write P, accumulate O = P@V ---------------
    float* Pb = P + (size_t)bh * LL * LL;
    float acc2[4][4] = {};
    int srcA = (lane & 0x1C) | (t >> 1);
    bool odd = (t & 1);
    float4 pv[2];
    #pragma unroll
    for (int j = 0; j < 2; j++) {
        int i = tid + j*512; int r = i >> 3, c4 = (i & 7)*4;
        pk[j] = (r < LL) ? *(const float4*)&kb[(size_t)r * HD + c4] : f0;
        pv[j] = (r < LL) ? *(const float4*)&vb[(size_t)r * HD + c4] : f0;
    }
    for (int s0 = 0; s0 < LL; s0 += 128) {
        #pragma unroll
        for (int j = 0; j < 2; j++) {
            int i = tid + j*512; int r = i >> 3, c4 = (i & 7)*4;
            *(uint4*)&Ks[r*36 + c4] = tf4(pk[j]);
            *(uint4*)&Vs[r*40 + c4] = tf4(pv[j]);
        }
        __syncthreads();
        if (s0 + 128 < LL) {
            #pragma unroll
            for (int j = 0; j < 2; j++) {
                int i = tid + j*512; int r = i >> 3, c4 = (i & 7)*4;
                int sr = s0 + 128 + r;
                pk[j] = (sr < LL) ? *(const float4*)&kb[(size_t)sr * HD + c4] : f0;
                pv[j] = (sr < LL) ? *(const float4*)&vb[(size_t)sr * HD + c4] : f0;
            }
        }
        #pragma unroll
        for (int hf2 = 0; hf2 < 2; hf2++) {
            int sb = s0 + hf2*64;
            float acc[8][4] = {};
            #pragma unroll
            for (int kk = 0; kk < 4; kk++) {
                #pragma unroll
                for (int ni = 0; ni < 8; ni++) {
                    unsigned b2[2];
                    b2[0] = Ks[(hf2*64 + ni*8 + g)*36 + kk*8 + t];
                    b2[1] = Ks[(hf2*64 + ni*8 + g)*36 + kk*8 + t + 4];
                    mma_tf32(acc[ni], qf[kk], b2);
                }
            }
            #pragma unroll
            for (int ni = 0; ni < 8; ni++) {
                bool cok = (sb + ni*8) < LL;
                float p0 = cok ? ex2(acc[ni][0]*S2) * inv0 : 0.f;
                float p1 = cok ? ex2(acc[ni][1]*S2) * inv0 : 0.f;
                float p2 = cok ? ex2(acc[ni][2]*S2) * inv1 : 0.f;
                float p3 = cok ? ex2(acc[ni][3]*S2) * inv1 : 0.f;
                if (cok) {
                    size_t cidx = (size_t)(sb + ni*8 + t*2);
                    if (r0ok) *(float2*)&Pb[(size_t)row0*LL + cidx] = make_float2(p0, p1);
                    if (r1ok) *(float2*)&Pb[(size_t)row1*LL + cidx] = make_float2(p2, p3);
                }
                acc[ni][0] = __uint_as_float(f2tf(p0));
                acc[ni][1] = __uint_as_float(f2tf(p1));
                acc[ni][2] = __uint_as_float(f2tf(p2));
                acc[ni][3] = __uint_as_float(f2tf(p3));
            }
            #pragma unroll
            for (int kk = 0; kk < 8; kk++) {
                float x0 = __shfl_sync(0xffffffffu, acc[kk][0], srcA);
                float x1 = __shfl_sync(0xffffffffu, acc[kk][1], srcA);
                float y0 = __shfl_sync(0xffffffffu, acc[kk][2], srcA);
                float y1 = __shfl_sync(0xffffffffu, acc[kk][3], srcA);
                float x0b = __shfl_sync(0xffffffffu, acc[kk][0], srcA + 2);
                float x1b = __shfl_sync(0xffffffffu, acc[kk][1], srcA + 2);
                float y0b = __shfl_sync(0xffffffffu, acc[kk][2], srcA + 2);
                float y1b = __shfl_sync(0xffffffffu, acc[kk][3], srcA + 2);
                unsigned a[4];
                a[0] = __float_as_uint(odd ? x1  : x0);
                a[1] = __float_as_uint(odd ? y1  : y0);
                a[2] = __float_as_uint(odd ? x1b : x0b);
                a[3] = __float_as_uint(odd ? y1b : y0b);
                #pragma unroll
                for (int ni = 0; ni < 4; ni++) {
                    unsigned b2[2];
                    b2[0] = Vs[(hf2*64 + kk*8 + t)*40 + ni*8 + g];
                    b2[1] = Vs[(hf2*64 + kk*8 + t + 4)*40 + ni*8 + g];
                    mma_tf32(acc2[ni], a, b2);
                }
            }
        }
        __syncthreads();
    }
    float* ob = O + (size_t)b * LL * HD + hh * DKK;
    #pragma unroll
    for (int ni = 0; ni < 4; ni++) {
        int c0 = ni*8 + t*2;
        if (r0ok) *(float2*)&ob[(size_t)row0*HD + c0] = make_float2(acc2[ni][0], acc2[ni][1]);
        if (r1ok) *(float2*)&ob[(size_t)row1*HD + c0] = make_float2(acc2[ni][2], acc2[ni][3]);
    }
}

// ---------------- h = LayerNorm(h + add) * g + b (row of 256, float4) ------
__global__ void k_ln(float* __restrict__ h, const float* __restrict__ add,
                     const float* __restrict__ g, const float* __restrict__ bta) {
    int row  = blockIdx.x * 8 + (threadIdx.x >> 5);
    int lane = threadIdx.x & 31;
    float* hp = h + (size_t)row * DD;
    const float* ap = add + (size_t)row * DD;
    float4 v[2]; float s = 0.f;
    #pragma unroll
    for (int i = 0; i < 2; i++) {
        int d = lane*4 + i*128;
        float4 a = *(const float4*)&hp[d];
        float4 c = *(const float4*)&ap[d];
        v[i] = make_float4(a.x + c.x, a.y + c.y, a.z + c.z, a.w + c.w);
        s += v[i].x + v[i].y + v[i].z + v[i].w;
    }
    #pragma unroll
    for (int o = 16; o > 0; o >>= 1) s += __shfl_xor_sync(0xffffffffu, s, o);
    float mean = s * (1.f / DD);
    float var = 0.f;
    #pragma unroll
    for (int i = 0; i < 2; i++) {
        float dx = v[i].x - mean, dy = v[i].y - mean;
        float dz = v[i].z - mean, dw = v[i].w - mean;
        var = fmaf(dx, dx, var); var = fmaf(dy, dy, var);
        var = fmaf(dz, dz, var); var = fmaf(dw, dw, var);
    }
    #pragma unroll
    for (int o = 16; o > 0; o >>= 1) var += __shfl_xor_sync(0xffffffffu, var, o);
    var *= (1.f / DD);
    float r = rsqrtf(var + EPSV);
    #pragma unroll
    for (int i = 0; i < 2; i++) {
        int d = lane*4 + i*128;
        float4 gg = *(const float4*)&g[d];
        float4 bb = *(const float4*)&bta[d];
        float4 o4;
        o4.x = (v[i].x - mean) * r * gg.x + bb.x;
        o4.y = (v[i].y - mean) * r * gg.y + bb.y;
        o4.z = (v[i].z - mean) * r * gg.z + bb.z;
        o4.w = (v[i].w - mean) * r * gg.w + bb.w;
        *(float4*)&hp[d] = o4;
    }
}

// ---------------- final head: out = A(relu'd) @ o2w(256x2) + o2b -----------
__global__ void k_out2(const float* __restrict__ A, const float* __restrict__ w,
                       const float* __restrict__ b, float* __restrict__ out) {
    int row  = blockIdx.x * 8 + (threadIdx.x >> 5);
    int lane = threadIdx.x & 31;
    const float* ap = A + (size_t)row * DD;
    float s0 = 0.f, s1 = 0.f;
    #pragma unroll
    for (int i = 0; i < 8; i++) {
        int d = lane + 32*i;
        float a = ap[d];
        s0 = fmaf(a, w[d*2],     s0);
        s1 = fmaf(a, w[d*2 + 1], s1);
    }
    #pragma unroll
    for (int o = 16; o > 0; o >>= 1) {
        s0 += __shfl_xor_sync(0xffffffffu, s0, o);
        s1 += __shfl_xor_sync(0xffffffffu, s1, o);
    }
    if (lane == 0) {
        out[(size_t)row*2]     = s0 + b[0];
        out[(size_t)row*2 + 1] = s1 + b[1];
    }
}

// ---------------------------------------------------------------------------
extern "C" void kernel_launch(void* const* d_in, const int* in_sizes, int n_in,
                              void* d_out, int out_size) {
    const float* x    = (const float*)d_in[0];
    const float* in_w = (const float*)d_in[1];
    const float* in_b = (const float*)d_in[2];
    const float* qw   = (const float*)d_in[3];
    const float* qb   = (const float*)d_in[4];
    const float* kw   = (const float*)d_in[5];
    const float* kb   = (const float*)d_in[6];
    const float* vw   = (const float*)d_in[7];
    const float* vb   = (const float*)d_in[8];
    const float* ow   = (const float*)d_in[9];
    const float* ob   = (const float*)d_in[10];
    const float* f1w  = (const float*)d_in[11];
    const float* f1b  = (const float*)d_in[12];
    const float* f2w  = (const float*)d_in[13];
    const float* f2b  = (const float*)d_in[14];
    const float* n1g  = (const float*)d_in[15];
    const float* n1b  = (const float*)d_in[16];
    const float* n2g  = (const float*)d_in[17];
    const float* n2b  = (const float*)d_in[18];
    const float* o1w  = (const float*)d_in[19];
    const float* o1b  = (const float*)d_in[20];
    const float* o2w  = (const float*)d_in[21];
    const float* o2b  = (const float*)d_in[22];

    float* out  = (float*)d_out;
    float* attn = out + (size_t)BB * LL * 2;   // attns region: (NL,B,H,L,L)

    float *h, *q, *k, *v, *o, *t1, *ff;
    cudaGetSymbolAddress((void**)&h,  g_h);
    cudaGetSymbolAddress((void**)&q,  g_q);
    cudaGetSymbolAddress((void**)&k,  g_k);
    cudaGetSymbolAddress((void**)&v,  g_v);
    cudaGetSymbolAddress((void**)&o,  g_o);
    cudaGetSymbolAddress((void**)&t1, g_t1);
    cudaGetSymbolAddress((void**)&ff, g_ff);

    // input projection
    k_input<<<(BL*DD)/256, 256>>>(x, in_w, in_b, h);

    const int RT = (LL + 255) / 256;   // 8 row tiles

    for (int i = 0; i < NLL; i++) {
        const float* qwi = qw + (size_t)i * DD * HD;
        const float* qbi = qb + (size_t)i * HD;
        const float* kwi = kw + (size_t)i * DD * HD;
        const float* kbi = kb + (size_t)i * HD;
        const float* vwi = vw + (size_t)i * DD * HD;
        const float* vbi = vb + (size_t)i * HD;
        const float* owi = ow + (size_t)i * HD * DD;
        const float* obi = ob + (size_t)i * DD;
        const float* f1wi = f1w + (size_t)i * DD * FCC;
        const float* f1bi = f1b + (size_t)i * FCC;
        const float* f2wi = f2w + (size_t)i * FCC * DD;
        const float* f2bi = f2b + (size_t)i * DD;

        // fused Q,K,V projection
        k_qkv<<<dim3(HD/64, BL/64), 256>>>(
            h, qwi, qbi, kwi, kbi, vwi, vbi, q, k, v);

        // merged flash attention (stats + P + O), 256 rows/CTA
        float* Si = attn + (size_t)i * BHH * LL * LL;
        k_attn2<<<dim3(RT, BHH), 512>>>(q, k, v, Si, o);

        // output projection + residual LN
        k_gemm_mma<false><<<dim3(DD/64, BL/128), 256>>>(o, owi, obi, t1, BL, DD, HD);
        k_ln<<<BL/8, 256>>>(h, t1, n1g + (size_t)i*DD, n1b + (size_t)i*DD);

        // FFN + residual LN
        k_gemm_mma<true ><<<dim3(FCC/64, BL/128), 256>>>(h, f1wi, f1bi, ff, BL, FCC, DD);
        k_gemm_mma<false><<<dim3(DD/64, BL/128), 256>>>(ff, f2wi, f2bi, t1, BL, DD, FCC);
        k_ln<<<BL/8, 256>>>(h, t1, n2g + (size_t)i*DD, n2b + (size_t)i*DD);
    }

    // final MLP head
    k_gemm_mma<true><<<dim3(DD/64, BL/128), 256>>>(h, o1w, o1b, t1, BL, DD, DD);
    k_out2<<<BL/8, 256>>>(t1, o2w, o2b, out);
}